// round 2
// baseline (speedup 1.0000x reference)
#include <cuda_runtime.h>
#include <math.h>

#define NTOK 32768      // B * FH * FW = 8 * 64 * 64
#define DIM 768
#define HDIM 3072
#define NHEAD 12
#define HD 64
#define NWIN 128        // K*K*B = 16 * 8
#define WTOK 256        // (FH/K)*(FW/K) = 16*16
#define LAYERS 2
#define EPS 1e-6f

// ---------------- scratch (device globals; no allocations allowed) ----------
__device__ float g_xn[NTOK * DIM];
__device__ float g_q [NTOK * DIM];
__device__ float g_k [NTOK * DIM];
__device__ float g_v [NTOK * DIM];
__device__ float g_ao[NTOK * DIM];
__device__ float g_h [NTOK * HDIM];   // 402 MB MLP hidden

// ---------------- LayerNorm: one warp per row ------------------------------
__global__ void ln_kernel(const float* __restrict__ x, float* __restrict__ y,
                          const float* __restrict__ gamma, const float* __restrict__ beta) {
    int lane = threadIdx.x;
    long row = (long)blockIdx.x * 8 + threadIdx.y;
    const float4* xr = (const float4*)(x + row * DIM);
    float4 vals[6];
    float s = 0.f, s2 = 0.f;
#pragma unroll
    for (int i = 0; i < 6; i++) {
        float4 f = xr[i * 32 + lane];
        vals[i] = f;
        s  += f.x + f.y + f.z + f.w;
        s2 += f.x*f.x + f.y*f.y + f.z*f.z + f.w*f.w;
    }
#pragma unroll
    for (int off = 16; off; off >>= 1) {
        s  += __shfl_xor_sync(0xffffffffu, s,  off);
        s2 += __shfl_xor_sync(0xffffffffu, s2, off);
    }
    float mean = s * (1.f / DIM);
    float var  = s2 * (1.f / DIM) - mean * mean;
    float inv  = rsqrtf(var + EPS);

    float4* yr = (float4*)(y + row * DIM);
    const float4* gg = (const float4*)gamma;
    const float4* bb = (const float4*)beta;
#pragma unroll
    for (int i = 0; i < 6; i++) {
        int c = i * 32 + lane;
        float4 g = gg[c], b = bb[c], v = vals[i], o;
        o.x = (v.x - mean) * inv * g.x + b.x;
        o.y = (v.y - mean) * inv * g.y + b.y;
        o.z = (v.z - mean) * inv * g.z + b.z;
        o.w = (v.w - mean) * inv * g.w + b.w;
        yr[c] = o;
    }
}

// ---------------- GEMM: C = A[MxK] * W[KxN] + bias, epilogue variants ------
// EPI 0: +bias    1: (acc+bias)*alpha    2: +bias+res    3: quickgelu(acc+bias)
#define GBM 128
#define GBN 128
#define GBK 8

template <int EPI>
__global__ void __launch_bounds__(256)
gemm_kernel(const float* __restrict__ A, const float* __restrict__ W,
            const float* __restrict__ bias, const float* res,
            float* C, int M, int K, int N, float alpha) {
    __shared__ float As[GBK][GBM];
    __shared__ float Bs[GBK][GBN];

    int tid = threadIdx.x;
    int tx = tid & 15;   // 0..15 (col group of 8)
    int ty = tid >> 4;   // 0..15 (row group of 8)
    long row0 = (long)blockIdx.y * GBM;
    int  col0 = blockIdx.x * GBN;

    int arow = tid >> 1;          // 0..127
    int akof = (tid & 1) * 4;     // 0 or 4
    int brow = tid >> 5;          // 0..7
    int bcol = (tid & 31) * 4;    // 0..124

    const float* Ap = A + (row0 + arow) * K + akof;
    const float* Wp = W + (long)brow * N + col0 + bcol;

    float acc[8][8];
#pragma unroll
    for (int i = 0; i < 8; i++)
#pragma unroll
        for (int j = 0; j < 8; j++) acc[i][j] = 0.f;

    for (int k0 = 0; k0 < K; k0 += GBK) {
        float4 av = *(const float4*)(Ap + k0);
        float4 bv = *(const float4*)(Wp + (long)k0 * N);
        As[akof + 0][arow] = av.x;
        As[akof + 1][arow] = av.y;
        As[akof + 2][arow] = av.z;
        As[akof + 3][arow] = av.w;
        *(float4*)&Bs[brow][bcol] = bv;
        __syncthreads();
#pragma unroll
        for (int k = 0; k < GBK; k++) {
            float a[8], b[8];
            *(float4*)&a[0] = *(float4*)&As[k][ty * 8];
            *(float4*)&a[4] = *(float4*)&As[k][ty * 8 + 4];
            *(float4*)&b[0] = *(float4*)&Bs[k][tx * 8];
            *(float4*)&b[4] = *(float4*)&Bs[k][tx * 8 + 4];
#pragma unroll
            for (int i = 0; i < 8; i++)
#pragma unroll
                for (int j = 0; j < 8; j++) acc[i][j] += a[i] * b[j];
        }
        __syncthreads();
    }

    float bv[8];
#pragma unroll
    for (int j = 0; j < 8; j++) bv[j] = bias[col0 + tx * 8 + j];

#pragma unroll
    for (int i = 0; i < 8; i++) {
        long base = (row0 + ty * 8 + i) * N + col0 + tx * 8;
#pragma unroll
        for (int j = 0; j < 8; j++) {
            float v = acc[i][j] + bv[j];
            if (EPI == 1) v *= alpha;
            if (EPI == 2) v += res[base + j];
            if (EPI == 3) v = v / (1.f + __expf(-1.702f * v));  // x*sigmoid(1.702x)
            C[base + j] = v;
        }
    }
}

// ---------------- window attention ------------------------------------------
// grid (128 windows, 12 heads), 256 threads; K/V tile in smem, q/o in regs.
// Window slot s: b = s%8, i = (s/8)/4, j = (s/8)%4; token t: h=t/16, w=t%16
// global token n = b*4096 + (i*16+h)*64 + (j*16+w)
__device__ __forceinline__ long attn_row(int widx, int t) {
    int b = widx & 7;
    int ij = widx >> 3;
    int wi = ij >> 2, wj = ij & 3;
    int hh = t >> 4, ww = t & 15;
    return (long)b * 4096 + (wi * 16 + hh) * 64 + (wj * 16 + ww);
}

__global__ void __launch_bounds__(256, 1)
attn_kernel(const float* __restrict__ q, const float* __restrict__ k,
            const float* __restrict__ v, float* __restrict__ ao) {
    extern __shared__ float sm[];
    float* ks = sm;                 // [256][64]
    float* vs = sm + WTOK * HD;     // [256][64]

    int widx = blockIdx.x;
    int head = blockIdx.y;
    int tid = threadIdx.x;

    // load K and V window tiles (4 threads per row, float4)
    int lane4 = tid & 3;
    int rbase = tid >> 2;
#pragma unroll
    for (int rr = 0; rr < 4; rr++) {
        int t = rr * 64 + rbase;
        long grow = attn_row(widx, t) * DIM + head * HD;
#pragma unroll
        for (int i = 0; i < 4; i++) {
            int c = lane4 * 16 + i * 4;
            *(float4*)&ks[t * HD + c] = *(const float4*)&k[grow + c];
            *(float4*)&vs[t * HD + c] = *(const float4*)&v[grow + c];
        }
    }
    __syncthreads();

    // one query row per thread
    long qrow = attn_row(widx, tid) * DIM + head * HD;
    float qr[HD];
#pragma unroll
    for (int d = 0; d < HD; d += 4) {
        float4 f = *(const float4*)&q[qrow + d];
        qr[d] = f.x; qr[d + 1] = f.y; qr[d + 2] = f.z; qr[d + 3] = f.w;
    }

    // pass 1: row max
    float m = -1e30f;
    for (int key = 0; key < WTOK; key++) {
        float s = 0.f;
#pragma unroll
        for (int d = 0; d < HD; d += 4) {
            float4 kk = *(float4*)&ks[key * HD + d];
            s += qr[d] * kk.x + qr[d + 1] * kk.y + qr[d + 2] * kk.z + qr[d + 3] * kk.w;
        }
        m = fmaxf(m, s);
    }

    // pass 2: softmax weights (recomputed scores) + AV accumulation
    float l = 0.f;
    float o[HD];
#pragma unroll
    for (int d = 0; d < HD; d++) o[d] = 0.f;

    for (int key = 0; key < WTOK; key++) {
        float s = 0.f;
#pragma unroll
        for (int d = 0; d < HD; d += 4) {
            float4 kk = *(float4*)&ks[key * HD + d];
            s += qr[d] * kk.x + qr[d + 1] * kk.y + qr[d + 2] * kk.z + qr[d + 3] * kk.w;
        }
        float p = __expf(s - m);
        l += p;
#pragma unroll
        for (int d = 0; d < HD; d += 4) {
            float4 vv = *(float4*)&vs[key * HD + d];
            o[d]     += p * vv.x;
            o[d + 1] += p * vv.y;
            o[d + 2] += p * vv.z;
            o[d + 3] += p * vv.w;
        }
    }

    float inv = 1.f / l;
#pragma unroll
    for (int d = 0; d < HD; d += 4) {
        float4 f;
        f.x = o[d] * inv; f.y = o[d + 1] * inv;
        f.z = o[d + 2] * inv; f.w = o[d + 3] * inv;
        *(float4*)&ao[qrow + d] = f;
    }
}

// ---------------- host ------------------------------------------------------
extern "C" void kernel_launch(void* const* d_in, const int* in_sizes, int n_in,
                              void* d_out, int out_size) {
    const float* x    = (const float*)d_in[0];
    const float* ln1s = (const float*)d_in[1];
    const float* ln1b = (const float*)d_in[2];
    const float* Wq   = (const float*)d_in[3];
    const float* bq   = (const float*)d_in[4];
    const float* Wk   = (const float*)d_in[5];
    const float* bk   = (const float*)d_in[6];
    const float* Wv   = (const float*)d_in[7];
    const float* bv   = (const float*)d_in[8];
    const float* Wo   = (const float*)d_in[9];
    const float* bo   = (const float*)d_in[10];
    const float* ln2s = (const float*)d_in[11];
    const float* ln2b = (const float*)d_in[12];
    const float* W1   = (const float*)d_in[13];
    const float* b1   = (const float*)d_in[14];
    const float* W2   = (const float*)d_in[15];
    const float* b2   = (const float*)d_in[16];
    float* out = (float*)d_out;

    float *xn, *qb, *kb, *vb, *aob, *hb;
    cudaGetSymbolAddress((void**)&xn,  g_xn);
    cudaGetSymbolAddress((void**)&qb,  g_q);
    cudaGetSymbolAddress((void**)&kb,  g_k);
    cudaGetSymbolAddress((void**)&vb,  g_v);
    cudaGetSymbolAddress((void**)&aob, g_ao);
    cudaGetSymbolAddress((void**)&hb,  g_h);

    int attn_smem = 2 * WTOK * HD * (int)sizeof(float);  // 128 KB
    cudaFuncSetAttribute(attn_kernel, cudaFuncAttributeMaxDynamicSharedMemorySize, attn_smem);

    // residual stream lives in d_out; window permutation is identity end-to-end
    cudaMemcpyAsync(out, x, (size_t)NTOK * DIM * sizeof(float),
                    cudaMemcpyDeviceToDevice, 0);

    dim3 lnGrid(NTOK / 8), lnBlk(32, 8);
    dim3 gD(DIM / GBN,  NTOK / GBM);   // 6 x 256
    dim3 gH(HDIM / GBN, NTOK / GBM);   // 24 x 256

    for (int l = 0; l < LAYERS; l++) {
        const float* Wq_l = Wq + (long)l * DIM * DIM;
        const float* Wk_l = Wk + (long)l * DIM * DIM;
        const float* Wv_l = Wv + (long)l * DIM * DIM;
        const float* Wo_l = Wo + (long)l * DIM * DIM;
        const float* W1_l = W1 + (long)l * DIM * HDIM;
        const float* W2_l = W2 + (long)l * HDIM * DIM;

        ln_kernel<<<lnGrid, lnBlk>>>(out, xn, ln1s + l * DIM, ln1b + l * DIM);

        gemm_kernel<1><<<gD, 256>>>(xn, Wq_l, bq + l * DIM, nullptr, qb,
                                    NTOK, DIM, DIM, 0.125f);
        gemm_kernel<0><<<gD, 256>>>(xn, Wk_l, bk + l * DIM, nullptr, kb,
                                    NTOK, DIM, DIM, 1.f);
        gemm_kernel<0><<<gD, 256>>>(xn, Wv_l, bv + l * DIM, nullptr, vb,
                                    NTOK, DIM, DIM, 1.f);

        attn_kernel<<<dim3(NWIN, NHEAD), 256, attn_smem>>>(qb, kb, vb, aob);

        gemm_kernel<2><<<gD, 256>>>(aob, Wo_l, bo + l * DIM, out, out,
                                    NTOK, DIM, DIM, 1.f);

        ln_kernel<<<lnGrid, lnBlk>>>(out, xn, ln2s + l * DIM, ln2b + l * DIM);

        gemm_kernel<3><<<gH, 256>>>(xn, W1_l, b1 + l * HDIM, nullptr, hb,
                                    NTOK, DIM, HDIM, 1.f);
        gemm_kernel<2><<<gD, 256>>>(hb, W2_l, b2 + l * DIM, out, out,
                                    NTOK, HDIM, DIM, 1.f);
    }
}

// round 4
// speedup vs baseline: 3.0701x; 3.0701x over previous
#include <cuda_runtime.h>
#include <math.h>
#include <stdint.h>

#define NTOK 32768
#define DIM 768
#define HDIM 3072
#define NHEAD 12
#define HD 64
#define NWIN 128
#define WTOK 256
#define LAYERS 2
#define EPS 1e-6f

__device__ float g_xn[NTOK * DIM];
__device__ float g_q [NTOK * DIM];
__device__ float g_k [NTOK * DIM];
__device__ float g_v [NTOK * DIM];
__device__ float g_ao[NTOK * DIM];
__device__ float g_h [NTOK * HDIM];
#define LDD (LAYERS * DIM * DIM)
#define LDH (LAYERS * DIM * HDIM)
__device__ float g_wt[4 * LDD + 2 * LDH];

// ---------------- helpers ---------------------------------------------------
__device__ __forceinline__ uint32_t s2u(const void* p) {
    uint32_t a;
    asm("{ .reg .u64 t; cvta.to.shared.u64 t, %1; cvt.u32.u64 %0, t; }" : "=r"(a) : "l"(p));
    return a;
}
__device__ __forceinline__ float rtf32(float v) {   // RNE round to tf32
    uint32_t u = __float_as_uint(v);
    u = (u + 0xFFFu + ((u >> 13) & 1u)) & 0xFFFFE000u;
    return __uint_as_float(u);
}
__device__ __forceinline__ float fast_exp2(float x) {
    x = fminf(fmaxf(x, -120.f), 120.f);
    float t = x + 12582912.0f;
    float r = t - 12582912.0f;
    float f = x - r;
    int   e = (int)r;
    float p = 1.0f + f * (0.69314718f + f * (0.24022651f + f * (0.05550411f
                  + f * (0.00961813f + f * 0.00133336f))));
    return __int_as_float((e + 127) << 23) * p;
}
__device__ __forceinline__ float fast_rcp(float d) {
    float r = __int_as_float(0x7EF127EA - __float_as_int(d));
    r = r * (2.0f - d * r);
    r = r * (2.0f - d * r);
    r = r * (2.0f - d * r);
    return r;
}
__device__ __forceinline__ void cp16(uint32_t s, const void* g) {
    asm volatile("cp.async.cg.shared.global [%0], [%1], 16;" :: "r"(s), "l"(g));
}
__device__ __forceinline__ void mma8(float* c, const float* a, const float* b) {
    asm volatile(
        "mma.sync.aligned.m16n8k8.row.col.f32.tf32.tf32.f32 "
        "{%0,%1,%2,%3}, {%4,%5,%6,%7}, {%8,%9}, {%0,%1,%2,%3};"
        : "+f"(c[0]), "+f"(c[1]), "+f"(c[2]), "+f"(c[3])
        : "r"(__float_as_uint(a[0])), "r"(__float_as_uint(a[1])),
          "r"(__float_as_uint(a[2])), "r"(__float_as_uint(a[3])),
          "r"(__float_as_uint(b[0])), "r"(__float_as_uint(b[1])));
}

// ---------------- weight rounding copy ---------------------------------------
__global__ void wround(const float* __restrict__ src, float* __restrict__ dst) {
    long i = ((long)blockIdx.x * 256 + threadIdx.x) * 4;
    float4 f = *(const float4*)(src + i);
    f.x = rtf32(f.x); f.y = rtf32(f.y); f.z = rtf32(f.z); f.w = rtf32(f.w);
    *(float4*)(dst + i) = f;
}

// ---------------- LayerNorm (emits tf32-rounded) ------------------------------
__global__ void ln_kernel(const float* __restrict__ x, float* __restrict__ y,
                          const float* __restrict__ gamma, const float* __restrict__ beta) {
    int lane = threadIdx.x;
    long row = (long)blockIdx.x * 8 + threadIdx.y;
    const float4* xr = (const float4*)(x + row * DIM);
    float4 vals[6];
    float s = 0.f, s2 = 0.f;
#pragma unroll
    for (int i = 0; i < 6; i++) {
        float4 f = xr[i * 32 + lane];
        vals[i] = f;
        s  += f.x + f.y + f.z + f.w;
        s2 += f.x*f.x + f.y*f.y + f.z*f.z + f.w*f.w;
    }
#pragma unroll
    for (int off = 16; off; off >>= 1) {
        s  += __shfl_xor_sync(0xffffffffu, s,  off);
        s2 += __shfl_xor_sync(0xffffffffu, s2, off);
    }
    float mean = s * (1.f / DIM);
    float var  = s2 * (1.f / DIM) - mean * mean;
    float inv  = rsqrtf(var + EPS);
    float4* yr = (float4*)(y + row * DIM);
    const float4* gg = (const float4*)gamma;
    const float4* bb = (const float4*)beta;
#pragma unroll
    for (int i = 0; i < 6; i++) {
        int c = i * 32 + lane;
        float4 g = gg[c], b = bb[c], v = vals[i], o;
        o.x = rtf32((v.x - mean) * inv * g.x + b.x);
        o.y = rtf32((v.y - mean) * inv * g.y + b.y);
        o.z = rtf32((v.z - mean) * inv * g.z + b.z);
        o.w = rtf32((v.w - mean) * inv * g.w + b.w);
        yr[c] = o;
    }
}

// ---------------- mma.sync tf32 GEMM -----------------------------------------
// C[M,N] = A[M,K] @ W[K,N] + bias ; EPI 0:+bias 1:*alpha 2:+res 3:quickgelu
#define TBM 128
#define TBN 128
#define TBK 32
#define ASTR 36                     // A smem stride (floats)
#define BSTR 136                    // B smem stride (floats)
#define ASTG (128 * ASTR)           // 4608 floats
#define BSTG (32 * BSTR)            // 4352 floats
#define STGF (ASTG + BSTG)          // 8960 floats
#define GEMM_SMEM (2 * STGF * 4)    // 71680 bytes

template <int EPI>
__global__ void __launch_bounds__(256, 2)
tc_gemm(const float* __restrict__ A, const float* __restrict__ W,
        const float* __restrict__ bias, const float* __restrict__ res,
        float* __restrict__ C, int K, int N, float alpha) {
    extern __shared__ float sm[];
    int tid = threadIdx.x;
    int lane = tid & 31, wid = tid >> 5;
    int g = lane >> 2, t = lane & 3;
    int wm = wid & 1, wn = wid >> 1;
    long row0 = (long)blockIdx.y * TBM;
    int  col0 = blockIdx.x * TBN;
    int m0 = wm * 64, n0 = wn * 32;

    float acc[4][4][4];
#pragma unroll
    for (int i = 0; i < 4; i++)
#pragma unroll
        for (int j = 0; j < 4; j++)
#pragma unroll
            for (int r = 0; r < 4; r++) acc[i][j][r] = 0.f;

    uint32_t sbase = s2u(sm);
    int iters = K / TBK;

    auto produce = [&](int stage, int k0) {
        uint32_t ab = sbase + stage * STGF * 4;
        uint32_t bb = ab + ASTG * 4;
#pragma unroll
        for (int j = 0; j < 4; j++) {
            int id = tid + j * 256;
            int r = id >> 3, o = id & 7;
            cp16(ab + (r * ASTR + o * 4) * 4, A + (row0 + r) * K + k0 + o * 4);
            int br = id >> 5, bo = id & 31;
            cp16(bb + (br * BSTR + bo * 4) * 4, W + (long)(k0 + br) * N + col0 + bo * 4);
        }
        asm volatile("cp.async.commit_group;" ::: "memory");
    };

    produce(0, 0);
    for (int i = 0; i < iters; i++) {
        if (i + 1 < iters) {
            produce((i + 1) & 1, (i + 1) * TBK);
            asm volatile("cp.async.wait_group 1;" ::: "memory");
        } else {
            asm volatile("cp.async.wait_group 0;" ::: "memory");
        }
        __syncthreads();
        const float* as = sm + (i & 1) * STGF;
        const float* bs = as + ASTG;
#pragma unroll
        for (int kk = 0; kk < 4; kk++) {
            int k = kk * 8;
            float a[4][4], b[4][2];
#pragma unroll
            for (int mt = 0; mt < 4; mt++) {
                const float* ap = as + (m0 + mt * 16 + g) * ASTR + k + t;
                a[mt][0] = ap[0];
                a[mt][1] = ap[8 * ASTR];
                a[mt][2] = ap[4];
                a[mt][3] = ap[8 * ASTR + 4];
            }
#pragma unroll
            for (int nt = 0; nt < 4; nt++) {
                const float* bp = bs + (k + t) * BSTR + n0 + nt * 8 + g;
                b[nt][0] = bp[0];
                b[nt][1] = bp[4 * BSTR];
            }
#pragma unroll
            for (int mt = 0; mt < 4; mt++)
#pragma unroll
                for (int nt = 0; nt < 4; nt++)
                    mma8(acc[mt][nt], a[mt], b[nt]);
        }
        __syncthreads();
    }

#pragma unroll
    for (int mt = 0; mt < 4; mt++)
#pragma unroll
    for (int rh = 0; rh < 2; rh++) {
        long r = row0 + m0 + mt * 16 + rh * 8 + g;
        float* cp = C + r * (long)N + col0;
        const float* rp = res + r * (long)N + col0;
#pragma unroll
        for (int nt = 0; nt < 4; nt++) {
            int c = n0 + nt * 8 + 2 * t;
            float2 v;
            v.x = acc[mt][nt][rh * 2 + 0] + bias[col0 + c];
            v.y = acc[mt][nt][rh * 2 + 1] + bias[col0 + c + 1];
            if (EPI == 1) { v.x *= alpha; v.y *= alpha; }
            if (EPI == 2) { v.x += rp[c]; v.y += rp[c + 1]; }
            if (EPI == 3) {
                v.x = rtf32(v.x * fast_rcp(1.f + fast_exp2(-2.45547238f * v.x)));
                v.y = rtf32(v.y * fast_rcp(1.f + fast_exp2(-2.45547238f * v.y)));
            }
            *(float2*)(cp + c) = v;
        }
    }
}

// ---------------- window attention (single pass, shift = 0) ------------------
__device__ __forceinline__ long attn_row(int widx, int t) {
    int b = widx & 7;
    int ij = widx >> 3;
    int wi = ij >> 2, wj = ij & 3;
    int hh = t >> 4, ww = t & 15;
    return (long)b * 4096 + (wi * 16 + hh) * 64 + (wj * 16 + ww);
}

__global__ void __launch_bounds__(256, 1)
attn_kernel(const float* __restrict__ q, const float* __restrict__ k,
            const float* __restrict__ v, float* __restrict__ ao) {
    extern __shared__ float smv[];
    float* ks = smv;
    float* vs = smv + WTOK * HD;
    int widx = blockIdx.x, head = blockIdx.y, tid = threadIdx.x;
    int lane4 = tid & 3, rbase = tid >> 2;
#pragma unroll
    for (int rr = 0; rr < 4; rr++) {
        int t = rr * 64 + rbase;
        long grow = attn_row(widx, t) * DIM + head * HD;
#pragma unroll
        for (int i = 0; i < 4; i++) {
            int c = lane4 * 16 + i * 4;
            *(float4*)&ks[t * HD + c] = *(const float4*)&k[grow + c];
            *(float4*)&vs[t * HD + c] = *(const float4*)&v[grow + c];
        }
    }
    __syncthreads();

    long qrow = attn_row(widx, tid) * DIM + head * HD;
    float qr[HD];
#pragma unroll
    for (int d = 0; d < HD; d += 4) {
        float4 f = *(const float4*)&q[qrow + d];
        qr[d] = f.x; qr[d+1] = f.y; qr[d+2] = f.z; qr[d+3] = f.w;
    }
    float l = 0.f, o[HD];
#pragma unroll
    for (int d = 0; d < HD; d++) o[d] = 0.f;
    for (int key = 0; key < WTOK; key++) {
        float s = 0.f;
#pragma unroll
        for (int d = 0; d < HD; d += 4) {
            float4 kk = *(float4*)&ks[key * HD + d];
            s += qr[d]*kk.x + qr[d+1]*kk.y + qr[d+2]*kk.z + qr[d+3]*kk.w;
        }
        float p = __expf(s);       // scores tiny; softmax shift-invariant
        l += p;
#pragma unroll
        for (int d = 0; d < HD; d += 4) {
            float4 vv = *(float4*)&vs[key * HD + d];
            o[d] += p*vv.x; o[d+1] += p*vv.y; o[d+2] += p*vv.z; o[d+3] += p*vv.w;
        }
    }
    float inv = 1.f / l;
#pragma unroll
    for (int d = 0; d < HD; d += 4) {
        float4 f;
        f.x = rtf32(o[d] * inv);   f.y = rtf32(o[d+1] * inv);
        f.z = rtf32(o[d+2] * inv); f.w = rtf32(o[d+3] * inv);
        *(float4*)&ao[qrow + d] = f;
    }
}

// ---------------- host --------------------------------------------------------
extern "C" void kernel_launch(void* const* d_in, const int* in_sizes, int n_in,
                              void* d_out, int out_size) {
    const float* x    = (const float*)d_in[0];
    const float* ln1s = (const float*)d_in[1];
    const float* ln1b = (const float*)d_in[2];
    const float* Wq   = (const float*)d_in[3];
    const float* bq   = (const float*)d_in[4];
    const float* Wk   = (const float*)d_in[5];
    const float* bk   = (const float*)d_in[6];
    const float* Wv   = (const float*)d_in[7];
    const float* bv   = (const float*)d_in[8];
    const float* Wo   = (const float*)d_in[9];
    const float* bo   = (const float*)d_in[10];
    const float* ln2s = (const float*)d_in[11];
    const float* ln2b = (const float*)d_in[12];
    const float* W1   = (const float*)d_in[13];
    const float* b1   = (const float*)d_in[14];
    const float* W2   = (const float*)d_in[15];
    const float* b2   = (const float*)d_in[16];
    float* out = (float*)d_out;

    float *xn, *qb, *kb, *vb, *aob, *hb, *wt;
    cudaGetSymbolAddress((void**)&xn,  g_xn);
    cudaGetSymbolAddress((void**)&qb,  g_q);
    cudaGetSymbolAddress((void**)&kb,  g_k);
    cudaGetSymbolAddress((void**)&vb,  g_v);
    cudaGetSymbolAddress((void**)&aob, g_ao);
    cudaGetSymbolAddress((void**)&hb,  g_h);
    cudaGetSymbolAddress((void**)&wt,  g_wt);

    float* WqT = wt;
    float* WkT = wt + (long)LDD;
    float* WvT = wt + 2L * LDD;
    float* WoT = wt + 3L * LDD;
    float* W1T = wt + 4L * LDD;
    float* W2T = wt + 4L * LDD + (long)LDH;

    int attn_smem = 2 * WTOK * HD * (int)sizeof(float);
    cudaFuncSetAttribute(attn_kernel, cudaFuncAttributeMaxDynamicSharedMemorySize, attn_smem);
    cudaFuncSetAttribute(tc_gemm<0>, cudaFuncAttributeMaxDynamicSharedMemorySize, GEMM_SMEM);
    cudaFuncSetAttribute(tc_gemm<1>, cudaFuncAttributeMaxDynamicSharedMemorySize, GEMM_SMEM);
    cudaFuncSetAttribute(tc_gemm<2>, cudaFuncAttributeMaxDynamicSharedMemorySize, GEMM_SMEM);
    cudaFuncSetAttribute(tc_gemm<3>, cudaFuncAttributeMaxDynamicSharedMemorySize, GEMM_SMEM);

    cudaMemcpyAsync(out, x, (size_t)NTOK * DIM * sizeof(float), cudaMemcpyDeviceToDevice, 0);

    wround<<<LDD / 1024, 256>>>(Wq, WqT);
    wround<<<LDD / 1024, 256>>>(Wk, WkT);
    wround<<<LDD / 1024, 256>>>(Wv, WvT);
    wround<<<LDD / 1024, 256>>>(Wo, WoT);
    wround<<<LDH / 1024, 256>>>(W1, W1T);
    wround<<<LDH / 1024, 256>>>(W2, W2T);

    dim3 lnGrid(NTOK / 8), lnBlk(32, 8);
    dim3 gD(DIM / TBN,  NTOK / TBM);   // 6 x 256
    dim3 gH(HDIM / TBN, NTOK / TBM);   // 24 x 256

    for (int l = 0; l < LAYERS; l++) {
        long oDD = (long)l * DIM * DIM;
        long oDH = (long)l * DIM * HDIM;

        ln_kernel<<<lnGrid, lnBlk>>>(out, xn, ln1s + l*DIM, ln1b + l*DIM);

        tc_gemm<1><<<gD, 256, GEMM_SMEM>>>(xn, WqT + oDD, bq + l*DIM, out, qb, DIM, DIM, 0.125f);
        tc_gemm<0><<<gD, 256, GEMM_SMEM>>>(xn, WkT + oDD, bk + l*DIM, out, kb, DIM, DIM, 1.f);
        tc_gemm<0><<<gD, 256, GEMM_SMEM>>>(xn, WvT + oDD, bv + l*DIM, out, vb, DIM, DIM, 1.f);

        attn_kernel<<<dim3(NWIN, NHEAD), 256, attn_smem>>>(qb, kb, vb, aob);

        tc_gemm<2><<<gD, 256, GEMM_SMEM>>>(aob, WoT + oDD, bo + l*DIM, out, out, DIM, DIM, 1.f);

        ln_kernel<<<lnGrid, lnBlk>>>(out, xn, ln2s + l*DIM, ln2b + l*DIM);

        tc_gemm<3><<<gH, 256, GEMM_SMEM>>>(xn, W1T + oDH, b1 + l*HDIM, out, hb, DIM, HDIM, 1.f);
        tc_gemm<2><<<gD, 256, GEMM_SMEM>>>(hb, W2T + oDH, b2 + l*DIM, out, out, HDIM, DIM, 1.f);
    }
}

// round 6
// speedup vs baseline: 3.1615x; 1.0297x over previous
#include <cuda_runtime.h>
#include <math.h>
#include <stdint.h>

#define NTOK 32768
#define DIM 768
#define QKVN 2304
#define HDIM 3072
#define NHEAD 12
#define HD 64
#define NWIN 128
#define WTOK 256
#define LAYERS 2
#define EPS 1e-6f

__device__ float g_xn  [NTOK * DIM];
__device__ float g_qkv [(size_t)NTOK * QKVN];
__device__ float g_ao  [NTOK * DIM];
__device__ float g_h   [(size_t)NTOK * HDIM];
__device__ float g_qkvT[LAYERS * 3 * DIM * DIM];
__device__ float g_woT [LAYERS * DIM * DIM];
__device__ float g_w1T [LAYERS * DIM * HDIM];
__device__ float g_w2T [LAYERS * DIM * HDIM];
__device__ float g_qkvBias[LAYERS * QKVN];     // dedicated: no aliasing

// ---------------- helpers ---------------------------------------------------
__device__ __forceinline__ uint32_t s2u(const void* p) {
    uint32_t a;
    asm("{ .reg .u64 t; cvta.to.shared.u64 t, %1; cvt.u32.u64 %0, t; }" : "=r"(a) : "l"(p));
    return a;
}
__device__ __forceinline__ float rtf32(float v) {
    uint32_t u = __float_as_uint(v);
    u = (u + 0xFFFu + ((u >> 13) & 1u)) & 0xFFFFE000u;
    return __uint_as_float(u);
}
__device__ __forceinline__ float fast_exp2(float x) {
    x = fminf(fmaxf(x, -120.f), 120.f);
    float t = x + 12582912.0f;
    float r = t - 12582912.0f;
    float f = x - r;
    int   e = (int)r;
    float p = 1.0f + f * (0.69314718f + f * (0.24022651f + f * (0.05550411f
                  + f * (0.00961813f + f * 0.00133336f))));
    return __int_as_float((e + 127) << 23) * p;
}
__device__ __forceinline__ float fast_rcp(float d) {
    float r = __int_as_float(0x7EF127EA - __float_as_int(d));
    r = r * (2.0f - d * r);
    r = r * (2.0f - d * r);
    r = r * (2.0f - d * r);
    return r;
}
__device__ __forceinline__ void cp16(uint32_t s, const void* g) {
    asm volatile("cp.async.cg.shared.global [%0], [%1], 16;" :: "r"(s), "l"(g));
}
__device__ __forceinline__ void mma8(float* c, const float* a, const float* b) {
    asm volatile(
        "mma.sync.aligned.m16n8k8.row.col.f32.tf32.tf32.f32 "
        "{%0,%1,%2,%3}, {%4,%5,%6,%7}, {%8,%9}, {%0,%1,%2,%3};"
        : "+f"(c[0]), "+f"(c[1]), "+f"(c[2]), "+f"(c[3])
        : "r"(__float_as_uint(a[0])), "r"(__float_as_uint(a[1])),
          "r"(__float_as_uint(a[2])), "r"(__float_as_uint(a[3])),
          "r"(__float_as_uint(b[0])), "r"(__float_as_uint(b[1])));
}

// ---------------- weight transposes [K,N] -> [N,K], tf32-rounded -------------
__global__ void transpose_a(const float* __restrict__ Wq, const float* __restrict__ Wk,
                            const float* __restrict__ Wv, const float* __restrict__ Wo,
                            float* __restrict__ qkvT, float* __restrict__ woT) {
    __shared__ float tb[32][33];
    int w = blockIdx.z >> 1, l = blockIdx.z & 1;
    const float* src = (w == 0 ? Wq : w == 1 ? Wk : w == 2 ? Wv : Wo) + (long)l * DIM * DIM;
    float* dst = (w < 3) ? qkvT + (long)l * 3 * DIM * DIM + (long)w * DIM * DIM
                         : woT + (long)l * DIM * DIM;
    int nb = blockIdx.x * 32, kb = blockIdx.y * 32;
    int x = threadIdx.x, y = threadIdx.y;
#pragma unroll
    for (int r = 0; r < 32; r += 8)
        tb[y + r][x] = src[(long)(kb + y + r) * DIM + nb + x];
    __syncthreads();
#pragma unroll
    for (int r = 0; r < 32; r += 8)
        dst[(long)(nb + y + r) * DIM + kb + x] = rtf32(tb[x][y + r]);
}
__global__ void transpose_b(const float* __restrict__ W1, const float* __restrict__ W2,
                            float* __restrict__ d1, float* __restrict__ d2) {
    __shared__ float tb[32][33];
    int w = blockIdx.z >> 1, l = blockIdx.z & 1;
    const float* src; float* dst; int K, N;
    if (w == 0) { src = W1 + (long)l * DIM * HDIM; dst = d1 + (long)l * DIM * HDIM; K = DIM;  N = HDIM; }
    else        { src = W2 + (long)l * DIM * HDIM; dst = d2 + (long)l * DIM * HDIM; K = HDIM; N = DIM; }
    if (blockIdx.x * 32 >= (unsigned)N || blockIdx.y * 32 >= (unsigned)K) return;
    int nb = blockIdx.x * 32, kb = blockIdx.y * 32;
    int x = threadIdx.x, y = threadIdx.y;
#pragma unroll
    for (int r = 0; r < 32; r += 8)
        tb[y + r][x] = src[(long)(kb + y + r) * N + nb + x];
    __syncthreads();
#pragma unroll
    for (int r = 0; r < 32; r += 8)
        dst[(long)(nb + y + r) * K + kb + x] = rtf32(tb[x][y + r]);
}

// ---------------- LayerNorm (emits tf32-rounded) ------------------------------
__global__ void ln_kernel(const float* __restrict__ x, float* __restrict__ y,
                          const float* __restrict__ gamma, const float* __restrict__ beta) {
    int lane = threadIdx.x;
    long row = (long)blockIdx.x * 8 + threadIdx.y;
    const float4* xr = (const float4*)(x + row * DIM);
    float4 vals[6];
    float s = 0.f, s2 = 0.f;
#pragma unroll
    for (int i = 0; i < 6; i++) {
        float4 f = xr[i * 32 + lane];
        vals[i] = f;
        s  += f.x + f.y + f.z + f.w;
        s2 += f.x*f.x + f.y*f.y + f.z*f.z + f.w*f.w;
    }
#pragma unroll
    for (int off = 16; off; off >>= 1) {
        s  += __shfl_xor_sync(0xffffffffu, s,  off);
        s2 += __shfl_xor_sync(0xffffffffu, s2, off);
    }
    float mean = s * (1.f / DIM);
    float var  = s2 * (1.f / DIM) - mean * mean;
    float inv  = rsqrtf(var + EPS);
    float4* yr = (float4*)(y + row * DIM);
    const float4* gg = (const float4*)gamma;
    const float4* bb = (const float4*)beta;
#pragma unroll
    for (int i = 0; i < 6; i++) {
        int c = i * 32 + lane;
        float4 g = gg[c], b = bb[c], v = vals[i], o;
        o.x = rtf32((v.x - mean) * inv * g.x + b.x);
        o.y = rtf32((v.y - mean) * inv * g.y + b.y);
        o.z = rtf32((v.z - mean) * inv * g.z + b.z);
        o.w = rtf32((v.w - mean) * inv * g.w + b.w);
        yr[c] = o;
    }
}

// ---------------- mma.sync tf32 GEMM: C = A[M,K] @ Wt[N,K]^T + bias ----------
// 128x128x32 CTA tile, 4 warps of 64x64.  EPI 0:+bias 2:+bias+res 3:gelu 4:qkv-scale
#define TBM 128
#define TBN 128
#define TBK 32
#define SSTR 36
#define TSTG (128 * SSTR)
#define STGF (2 * TSTG)
#define GEMM_SMEM (2 * STGF * 4)

template <int EPI>
__global__ void __launch_bounds__(128, 2)
tc_gemm(const float* __restrict__ A, const float* __restrict__ Wt,
        const float* __restrict__ bias, const float* __restrict__ res,
        float* __restrict__ C, int K, int N, float alpha) {
    extern __shared__ float sm[];
    int tid = threadIdx.x;
    int lane = tid & 31, wid = tid >> 5;
    int g = lane >> 2, t = lane & 3;
    int m0 = (wid & 1) * 64, n0 = (wid >> 1) * 64;
    long row0 = (long)blockIdx.y * TBM;
    int  col0 = blockIdx.x * TBN;

    float acc[4][8][4];
#pragma unroll
    for (int i = 0; i < 4; i++)
#pragma unroll
        for (int j = 0; j < 8; j++)
#pragma unroll
            for (int r = 0; r < 4; r++) acc[i][j][r] = 0.f;

    uint32_t sbase = s2u(sm);
    int iters = K / TBK;

    auto produce = [&](int stage, int k0) {
        uint32_t ab = sbase + stage * STGF * 4;
        uint32_t bb = ab + TSTG * 4;
#pragma unroll
        for (int j = 0; j < 8; j++) {
            int id = tid + j * 128;
            int r = id >> 3, o = id & 7;
            cp16(ab + (r * SSTR + o * 4) * 4, A  + (row0 + r) * (long)K + k0 + o * 4);
            cp16(bb + (r * SSTR + o * 4) * 4, Wt + (col0 + r) * (long)K + k0 + o * 4);
        }
        asm volatile("cp.async.commit_group;" ::: "memory");
    };

    produce(0, 0);
    for (int i = 0; i < iters; i++) {
        if (i + 1 < iters) {
            produce((i + 1) & 1, (i + 1) * TBK);
            asm volatile("cp.async.wait_group 1;" ::: "memory");
        } else {
            asm volatile("cp.async.wait_group 0;" ::: "memory");
        }
        __syncthreads();
        const float* as = sm + (i & 1) * STGF;
        const float* bs = as + TSTG;
#pragma unroll
        for (int kk = 0; kk < 4; kk++) {
            int k = kk * 8;
            float a[4][4], b[8][2];
#pragma unroll
            for (int mt = 0; mt < 4; mt++) {
                const float* ap = as + (m0 + mt * 16 + g) * SSTR + k + t;
                a[mt][0] = ap[0];
                a[mt][1] = ap[8 * SSTR];
                a[mt][2] = ap[4];
                a[mt][3] = ap[8 * SSTR + 4];
            }
#pragma unroll
            for (int nt = 0; nt < 8; nt++) {
                const float* bp = bs + (n0 + nt * 8 + g) * SSTR + k + t;
                b[nt][0] = bp[0];
                b[nt][1] = bp[4];
            }
#pragma unroll
            for (int mt = 0; mt < 4; mt++)
#pragma unroll
                for (int nt = 0; nt < 8; nt++)
                    mma8(acc[mt][nt], a[mt], b[nt]);
        }
        __syncthreads();
    }

    float sc = (EPI == 4) ? ((col0 < 768) ? alpha : 1.f) : alpha;
#pragma unroll
    for (int mt = 0; mt < 4; mt++)
#pragma unroll
    for (int rh = 0; rh < 2; rh++) {
        long r = row0 + m0 + mt * 16 + rh * 8 + g;
        float* cp = C + r * (long)N + col0;
        const float* rp = res + r * (long)N + col0;
#pragma unroll
        for (int nt = 0; nt < 8; nt++) {
            int c = n0 + nt * 8 + 2 * t;
            float2 v;
            v.x = acc[mt][nt][rh * 2 + 0] + bias[col0 + c];
            v.y = acc[mt][nt][rh * 2 + 1] + bias[col0 + c + 1];
            if (EPI == 4) { v.x *= sc; v.y *= sc; }
            if (EPI == 2) { v.x += rp[c]; v.y += rp[c + 1]; }
            if (EPI == 3) {
                v.x = rtf32(v.x * fast_rcp(1.f + fast_exp2(-2.45547238f * v.x)));
                v.y = rtf32(v.y * fast_rcp(1.f + fast_exp2(-2.45547238f * v.y)));
            }
            *(float2*)(cp + c) = v;
        }
    }
}

// ---------------- window attention (single pass, FFMA-only exp) --------------
__device__ __forceinline__ long attn_row(int widx, int t) {
    int b = widx & 7;
    int ij = widx >> 3;
    int wi = ij >> 2, wj = ij & 3;
    int hh = t >> 4, ww = t & 15;
    return (long)b * 4096 + (wi * 16 + hh) * 64 + (wj * 16 + ww);
}

__global__ void __launch_bounds__(256, 1)
attn_kernel(const float* __restrict__ qkv, float* __restrict__ ao) {
    extern __shared__ float smv[];
    float* ks = smv;
    float* vs = smv + WTOK * HD;
    int widx = blockIdx.x, head = blockIdx.y, tid = threadIdx.x;
    int lane4 = tid & 3, rbase = tid >> 2;
#pragma unroll
    for (int rr = 0; rr < 4; rr++) {
        int t = rr * 64 + rbase;
        long gk = attn_row(widx, t) * QKVN + 768 + head * HD;
#pragma unroll
        for (int i = 0; i < 4; i++) {
            int c = lane4 * 16 + i * 4;
            *(float4*)&ks[t * HD + c] = *(const float4*)&qkv[gk + c];
            *(float4*)&vs[t * HD + c] = *(const float4*)&qkv[gk + 768 + c];
        }
    }
    __syncthreads();

    long nrow = attn_row(widx, tid);
    const float* qp = qkv + nrow * QKVN + head * HD;
    float qr[HD];
#pragma unroll
    for (int d = 0; d < HD; d += 4) {
        float4 f = *(const float4*)&qp[d];
        qr[d] = f.x; qr[d+1] = f.y; qr[d+2] = f.z; qr[d+3] = f.w;
    }
    float l = 0.f, o[HD];
#pragma unroll
    for (int d = 0; d < HD; d++) o[d] = 0.f;
    for (int key = 0; key < WTOK; key++) {
        float s = 0.f;
#pragma unroll
        for (int d = 0; d < HD; d += 4) {
            float4 kk = *(float4*)&ks[key * HD + d];
            s += qr[d]*kk.x + qr[d+1]*kk.y + qr[d+2]*kk.z + qr[d+3]*kk.w;
        }
        float p = fast_exp2(1.4426950409f * s);   // scores tiny; shift-invariant
        l += p;
#pragma unroll
        for (int d = 0; d < HD; d += 4) {
            float4 vv = *(float4*)&vs[key * HD + d];
            o[d] += p*vv.x; o[d+1] += p*vv.y; o[d+2] += p*vv.z; o[d+3] += p*vv.w;
        }
    }
    float inv = 1.f / l;
    float* aop = ao + nrow * DIM + head * HD;
#pragma unroll
    for (int d = 0; d < HD; d += 4) {
        float4 f;
        f.x = rtf32(o[d] * inv);   f.y = rtf32(o[d+1] * inv);
        f.z = rtf32(o[d+2] * inv); f.w = rtf32(o[d+3] * inv);
        *(float4*)&aop[d] = f;
    }
}

// ---------------- host --------------------------------------------------------
extern "C" void kernel_launch(void* const* d_in, const int* in_sizes, int n_in,
                              void* d_out, int out_size) {
    const float* x    = (const float*)d_in[0];
    const float* ln1s = (const float*)d_in[1];
    const float* ln1b = (const float*)d_in[2];
    const float* Wq   = (const float*)d_in[3];
    const float* bq   = (const float*)d_in[4];
    const float* Wk   = (const float*)d_in[5];
    const float* bk   = (const float*)d_in[6];
    const float* Wv   = (const float*)d_in[7];
    const float* bv   = (const float*)d_in[8];
    const float* Wo   = (const float*)d_in[9];
    const float* bo   = (const float*)d_in[10];
    const float* ln2s = (const float*)d_in[11];
    const float* ln2b = (const float*)d_in[12];
    const float* W1   = (const float*)d_in[13];
    const float* b1   = (const float*)d_in[14];
    const float* W2   = (const float*)d_in[15];
    const float* b2   = (const float*)d_in[16];
    float* out = (float*)d_out;

    float *xn, *qkvb, *aob, *hb, *qkvT, *woT, *w1T, *w2T, *qb3;
    cudaGetSymbolAddress((void**)&xn,   g_xn);
    cudaGetSymbolAddress((void**)&qkvb, g_qkv);
    cudaGetSymbolAddress((void**)&aob,  g_ao);
    cudaGetSymbolAddress((void**)&hb,   g_h);
    cudaGetSymbolAddress((void**)&qkvT, g_qkvT);
    cudaGetSymbolAddress((void**)&woT,  g_woT);
    cudaGetSymbolAddress((void**)&w1T,  g_w1T);
    cudaGetSymbolAddress((void**)&w2T,  g_w2T);
    cudaGetSymbolAddress((void**)&qb3,  g_qkvBias);

    int attn_smem = 2 * WTOK * HD * (int)sizeof(float);
    cudaFuncSetAttribute(attn_kernel, cudaFuncAttributeMaxDynamicSharedMemorySize, attn_smem);
    cudaFuncSetAttribute(tc_gemm<0>, cudaFuncAttributeMaxDynamicSharedMemorySize, GEMM_SMEM);
    cudaFuncSetAttribute(tc_gemm<2>, cudaFuncAttributeMaxDynamicSharedMemorySize, GEMM_SMEM);
    cudaFuncSetAttribute(tc_gemm<3>, cudaFuncAttributeMaxDynamicSharedMemorySize, GEMM_SMEM);
    cudaFuncSetAttribute(tc_gemm<4>, cudaFuncAttributeMaxDynamicSharedMemorySize, GEMM_SMEM);

    cudaMemcpyAsync(out, x, (size_t)NTOK * DIM * sizeof(float), cudaMemcpyDeviceToDevice, 0);

    // pack qkv bias into its own global (read-only thereafter; no aliasing)
    for (int l = 0; l < LAYERS; l++) {
        cudaMemcpyAsync(qb3 + l * QKVN,        bq + l * DIM, DIM * sizeof(float), cudaMemcpyDeviceToDevice, 0);
        cudaMemcpyAsync(qb3 + l * QKVN + 768,  bk + l * DIM, DIM * sizeof(float), cudaMemcpyDeviceToDevice, 0);
        cudaMemcpyAsync(qb3 + l * QKVN + 1536, bv + l * DIM, DIM * sizeof(float), cudaMemcpyDeviceToDevice, 0);
    }

    // setup transposes (2 launches)
    transpose_a<<<dim3(24, 24, 8), dim3(32, 8)>>>(Wq, Wk, Wv, Wo, qkvT, woT);
    transpose_b<<<dim3(96, 96, 4), dim3(32, 8)>>>(W1, W2, w1T, w2T);

    dim3 lnGrid(NTOK / 8), lnBlk(32, 8);
    dim3 gQKV(QKVN / TBN, NTOK / TBM);  // 18 x 256
    dim3 gD(DIM / TBN,    NTOK / TBM);  // 6 x 256
    dim3 gH(HDIM / TBN,   NTOK / TBM);  // 24 x 256

    for (int l = 0; l < LAYERS; l++) {
        long oDD = (long)l * DIM * DIM;
        long oDH = (long)l * DIM * HDIM;

        ln_kernel<<<lnGrid, lnBlk>>>(out, xn, ln1s + l*DIM, ln1b + l*DIM);

        tc_gemm<4><<<gQKV, 128, GEMM_SMEM>>>(xn, qkvT + 3*oDD, qb3 + l*QKVN, out,
                                             qkvb, DIM, QKVN, 0.125f);

        attn_kernel<<<dim3(NWIN, NHEAD), 256, attn_smem>>>(qkvb, aob);

        tc_gemm<2><<<gD, 128, GEMM_SMEM>>>(aob, woT + oDD, bo + l*DIM, out, out,
                                           DIM, DIM, 1.f);

        ln_kernel<<<lnGrid, lnBlk>>>(out, xn, ln2s + l*DIM, ln2b + l*DIM);

        tc_gemm<3><<<gH, 128, GEMM_SMEM>>>(xn, w1T + oDH, b1 + l*HDIM, out, hb,
                                           DIM, HDIM, 1.f);
        tc_gemm<2><<<gD, 128, GEMM_SMEM>>>(hb, w2T + oDH, b2 + l*DIM, out, out,
                                           HDIM, DIM, 1.f);
    }
}

// round 7
// speedup vs baseline: 6.8432x; 2.1646x over previous
#include <cuda_runtime.h>
#include <cuda_fp16.h>
#include <math.h>
#include <stdint.h>

#define NTOK 32768
#define DIM 768
#define QKVN 2304
#define HDIM 3072
#define NHEAD 12
#define HD 64
#define NWIN 128
#define WTOK 256
#define LAYERS 2
#define EPS 1e-6f
#define LOG2E 1.4426950409f

__device__ __half g_xn  [NTOK * DIM];
__device__ __half g_qkv [(size_t)NTOK * QKVN];
__device__ __half g_ao  [NTOK * DIM];
__device__ __half g_h   [(size_t)NTOK * HDIM];
__device__ __half g_qkvT[LAYERS * 3 * DIM * DIM];
__device__ __half g_woT [LAYERS * DIM * DIM];
__device__ __half g_w1T [LAYERS * DIM * HDIM];
__device__ __half g_w2T [LAYERS * DIM * HDIM];
__device__ float  g_qkvBias[LAYERS * QKVN];

// ---------------- helpers ---------------------------------------------------
__device__ __forceinline__ uint32_t s2u(const void* p) {
    uint32_t a;
    asm("{ .reg .u64 t; cvta.to.shared.u64 t, %1; cvt.u32.u64 %0, t; }" : "=r"(a) : "l"(p));
    return a;
}
__device__ __forceinline__ float fast_exp2(float x) {
    x = fminf(fmaxf(x, -120.f), 120.f);
    float t = x + 12582912.0f;
    float r = t - 12582912.0f;
    float f = x - r;
    int   e = (int)r;
    float p = 1.0f + f * (0.69314718f + f * (0.24022651f + f * (0.05550411f
                  + f * (0.00961813f + f * 0.00133336f))));
    return __int_as_float((e + 127) << 23) * p;
}
__device__ __forceinline__ float fast_rcp(float d) {
    float r = __int_as_float(0x7EF127EA - __float_as_int(d));
    r = r * (2.0f - d * r);
    r = r * (2.0f - d * r);
    r = r * (2.0f - d * r);
    return r;
}
__device__ __forceinline__ void cp16(uint32_t s, const void* g) {
    asm volatile("cp.async.cg.shared.global [%0], [%1], 16;" :: "r"(s), "l"(g));
}
// fp16 MMA, fp32 accum: D += A(16x16) * B(16x8)
__device__ __forceinline__ void mma16(float* c, const uint32_t* a, const uint32_t* b) {
    asm volatile(
        "mma.sync.aligned.m16n8k16.row.col.f32.f16.f16.f32 "
        "{%0,%1,%2,%3}, {%4,%5,%6,%7}, {%8,%9}, {%0,%1,%2,%3};"
        : "+f"(c[0]), "+f"(c[1]), "+f"(c[2]), "+f"(c[3])
        : "r"(a[0]), "r"(a[1]), "r"(a[2]), "r"(a[3]), "r"(b[0]), "r"(b[1]));
}
__device__ __forceinline__ uint32_t h2u(float x, float y) {
    __half2 h = __floats2half2_rn(x, y);
    return *(uint32_t*)&h;
}

// ---------------- weight transposes [K,N] -> [N,K] half ----------------------
__global__ void transpose_a(const float* __restrict__ Wq, const float* __restrict__ Wk,
                            const float* __restrict__ Wv, const float* __restrict__ Wo,
                            __half* __restrict__ qkvT, __half* __restrict__ woT) {
    __shared__ float tb[32][33];
    int w = blockIdx.z >> 1, l = blockIdx.z & 1;
    const float* src = (w == 0 ? Wq : w == 1 ? Wk : w == 2 ? Wv : Wo) + (long)l * DIM * DIM;
    __half* dst = (w < 3) ? qkvT + (long)l * 3 * DIM * DIM + (long)w * DIM * DIM
                          : woT + (long)l * DIM * DIM;
    int nb = blockIdx.x * 32, kb = blockIdx.y * 32;
    int x = threadIdx.x, y = threadIdx.y;
#pragma unroll
    for (int r = 0; r < 32; r += 8)
        tb[y + r][x] = src[(long)(kb + y + r) * DIM + nb + x];
    __syncthreads();
#pragma unroll
    for (int r = 0; r < 32; r += 8)
        dst[(long)(nb + y + r) * DIM + kb + x] = __float2half_rn(tb[x][y + r]);
}
__global__ void transpose_b(const float* __restrict__ W1, const float* __restrict__ W2,
                            __half* __restrict__ d1, __half* __restrict__ d2) {
    __shared__ float tb[32][33];
    int w = blockIdx.z >> 1, l = blockIdx.z & 1;
    const float* src; __half* dst; int K, N;
    if (w == 0) { src = W1 + (long)l * DIM * HDIM; dst = d1 + (long)l * DIM * HDIM; K = DIM;  N = HDIM; }
    else        { src = W2 + (long)l * DIM * HDIM; dst = d2 + (long)l * DIM * HDIM; K = HDIM; N = DIM; }
    if (blockIdx.x * 32 >= (unsigned)N || blockIdx.y * 32 >= (unsigned)K) return;
    int nb = blockIdx.x * 32, kb = blockIdx.y * 32;
    int x = threadIdx.x, y = threadIdx.y;
#pragma unroll
    for (int r = 0; r < 32; r += 8)
        tb[y + r][x] = src[(long)(kb + y + r) * N + nb + x];
    __syncthreads();
#pragma unroll
    for (int r = 0; r < 32; r += 8)
        dst[(long)(nb + y + r) * K + kb + x] = __float2half_rn(tb[x][y + r]);
}

// ---------------- LayerNorm: fp32 in, half out --------------------------------
__global__ void ln_kernel(const float* __restrict__ x, __half* __restrict__ y,
                          const float* __restrict__ gamma, const float* __restrict__ beta) {
    int lane = threadIdx.x;
    long row = (long)blockIdx.x * 8 + threadIdx.y;
    const float4* xr = (const float4*)(x + row * DIM);
    float4 vals[6];
    float s = 0.f, s2 = 0.f;
#pragma unroll
    for (int i = 0; i < 6; i++) {
        float4 f = xr[i * 32 + lane];
        vals[i] = f;
        s  += f.x + f.y + f.z + f.w;
        s2 += f.x*f.x + f.y*f.y + f.z*f.z + f.w*f.w;
    }
#pragma unroll
    for (int off = 16; off; off >>= 1) {
        s  += __shfl_xor_sync(0xffffffffu, s,  off);
        s2 += __shfl_xor_sync(0xffffffffu, s2, off);
    }
    float mean = s * (1.f / DIM);
    float var  = s2 * (1.f / DIM) - mean * mean;
    float inv  = rsqrtf(var + EPS);
    uint2* yr = (uint2*)(y + row * DIM);
    const float4* gg = (const float4*)gamma;
    const float4* bb = (const float4*)beta;
#pragma unroll
    for (int i = 0; i < 6; i++) {
        int c = i * 32 + lane;
        float4 g = gg[c], b = bb[c], v = vals[i];
        uint2 u;
        u.x = h2u((v.x - mean) * inv * g.x + b.x, (v.y - mean) * inv * g.y + b.y);
        u.y = h2u((v.z - mean) * inv * g.z + b.z, (v.w - mean) * inv * g.w + b.w);
        yr[c] = u;
    }
}

// ---------------- fp16 mma GEMM: C = A[M,K] @ Wt[N,K]^T + bias ---------------
// EPI 2:+bias+res (float out)  3:gelu (half out)  4:qkv-scale (half out)
#define TBM 128
#define TBN 128
#define TBK 64
#define SH 72                       // smem row stride (halfs): 144B, 16B aligned
#define TSTG (128 * SH)             // halfs per operand stage
#define STGH (2 * TSTG)
#define GEMM_SMEM (2 * STGH * 2)    // 73728 B

template <int EPI, typename CT>
__global__ void __launch_bounds__(128, 2)
tc_gemm(const __half* __restrict__ A, const __half* __restrict__ Wt,
        const float* __restrict__ bias, const float* __restrict__ res,
        CT* __restrict__ C, int K, int N, float alpha) {
    extern __shared__ __half smh[];
    int tid = threadIdx.x;
    int lane = tid & 31, wid = tid >> 5;
    int g = lane >> 2, t = lane & 3;
    int m0 = (wid & 1) * 64, n0 = (wid >> 1) * 64;
    long row0 = (long)blockIdx.y * TBM;
    int  col0 = blockIdx.x * TBN;

    float acc[4][8][4];
#pragma unroll
    for (int i = 0; i < 4; i++)
#pragma unroll
        for (int j = 0; j < 8; j++)
#pragma unroll
            for (int r = 0; r < 4; r++) acc[i][j][r] = 0.f;

    uint32_t sbase = s2u(smh);
    int iters = K / TBK;

    auto produce = [&](int stage, int k0) {
        uint32_t ab = sbase + stage * STGH * 2;
        uint32_t bb = ab + TSTG * 2;
#pragma unroll
        for (int j = 0; j < 8; j++) {
            int id = tid + j * 128;
            int r = id >> 3, o = id & 7;
            cp16(ab + r * 144 + o * 16, A  + (row0 + r) * (long)K + k0 + o * 8);
            cp16(bb + r * 144 + o * 16, Wt + (col0 + r) * (long)K + k0 + o * 8);
        }
        asm volatile("cp.async.commit_group;" ::: "memory");
    };

    produce(0, 0);
    for (int i = 0; i < iters; i++) {
        if (i + 1 < iters) {
            produce((i + 1) & 1, (i + 1) * TBK);
            asm volatile("cp.async.wait_group 1;" ::: "memory");
        } else {
            asm volatile("cp.async.wait_group 0;" ::: "memory");
        }
        __syncthreads();
        const __half* as = smh + (i & 1) * STGH;
        const __half* bs = as + TSTG;
#pragma unroll
        for (int kk = 0; kk < 4; kk++) {
            int k2 = kk * 16;
            uint32_t a[4][4], b[8][2];
#pragma unroll
            for (int mt = 0; mt < 4; mt++) {
                const __half* ap = as + (m0 + mt * 16 + g) * SH + k2 + 2 * t;
                a[mt][0] = *(const uint32_t*)(ap);
                a[mt][1] = *(const uint32_t*)(ap + 8 * SH);
                a[mt][2] = *(const uint32_t*)(ap + 8);
                a[mt][3] = *(const uint32_t*)(ap + 8 * SH + 8);
            }
#pragma unroll
            for (int nt = 0; nt < 8; nt++) {
                const __half* bp = bs + (n0 + nt * 8 + g) * SH + k2 + 2 * t;
                b[nt][0] = *(const uint32_t*)(bp);
                b[nt][1] = *(const uint32_t*)(bp + 8);
            }
#pragma unroll
            for (int mt = 0; mt < 4; mt++)
#pragma unroll
                for (int nt = 0; nt < 8; nt++)
                    mma16(acc[mt][nt], a[mt], b[nt]);
        }
        __syncthreads();
    }

    float sc = (EPI == 4) ? ((col0 < 768) ? alpha : 1.f) : alpha;
#pragma unroll
    for (int mt = 0; mt < 4; mt++)
#pragma unroll
    for (int rh = 0; rh < 2; rh++) {
        long r = row0 + m0 + mt * 16 + rh * 8 + g;
        CT* cp = C + r * (long)N + col0;
        const float* rp = res + r * (long)N + col0;
#pragma unroll
        for (int nt = 0; nt < 8; nt++) {
            int c = n0 + nt * 8 + 2 * t;
            float vx = acc[mt][nt][rh * 2 + 0] + bias[col0 + c];
            float vy = acc[mt][nt][rh * 2 + 1] + bias[col0 + c + 1];
            if (EPI == 4) { vx *= sc; vy *= sc; }
            if (EPI == 2) { vx += rp[c]; vy += rp[c + 1]; }
            if (EPI == 3) {
                vx = vx * fast_rcp(1.f + fast_exp2(-2.45547238f * vx));
                vy = vy * fast_rcp(1.f + fast_exp2(-2.45547238f * vy));
            }
            if (sizeof(CT) == 2) {
                *(uint32_t*)(cp + c) = h2u(vx, vy);
            } else {
                float2 v; v.x = vx; v.y = vy;
                *(float2*)((float*)cp + c) = v;
            }
        }
    }
}

// ---------------- tensor-core window attention --------------------------------
// CTA = (window, head); 8 warps, 32 query rows each; S=QK^T and O=PV via mma16.
#define KSH 72    // K smem row stride (halfs) = 144B
#define VSH 264   // V^T smem row stride (halfs) = 528B
#define ATT_SMEM ((WTOK * KSH + HD * VSH) * 2)

__device__ __forceinline__ long attn_row(int widx, int t) {
    int b = widx & 7;
    int ij = widx >> 3;
    int wi = ij >> 2, wj = ij & 3;
    int hh = t >> 4, ww = t & 15;
    return (long)b * 4096 + (wi * 16 + hh) * 64 + (wj * 16 + ww);
}

__global__ void __launch_bounds__(256, 1)
attn_kernel(const __half* __restrict__ qkv, __half* __restrict__ ao) {
    extern __shared__ __half smh[];
    __half* ks  = smh;                 // [256][KSH] keys, d-contiguous
    __half* vsT = smh + WTOK * KSH;    // [64][VSH]  V transposed, key-contiguous
    int widx = blockIdx.x, head = blockIdx.y, tid = threadIdx.x;
    int lane = tid & 31, warp = tid >> 5;
    int g = lane >> 2, t = lane & 3;

    // stage K rows + V rows (coalesced gmem), V scattered into transpose
    {
        int key = tid;
        long tok = attn_row(widx, key);
        const uint4* kp4 = (const uint4*)(qkv + tok * QKVN + 768 + head * HD);
        uint4* kd = (uint4*)(ks + key * KSH);
#pragma unroll
        for (int o = 0; o < 8; o++) kd[o] = kp4[o];
        const uint4* vp4 = kp4 + 96;   // +768 halfs = 96 uint4
#pragma unroll
        for (int o = 0; o < 8; o++) {
            uint4 u = vp4[o];
            const __half* hh = (const __half*)&u;
#pragma unroll
            for (int d2 = 0; d2 < 8; d2++)
                vsT[(o * 8 + d2) * VSH + key] = hh[d2];
        }
    }
    __syncthreads();

    // Q fragments for this warp's 32 rows (2 m-tiles of 16)
    uint32_t qa[2][4][4];
    long tok0[2], tok1[2];
#pragma unroll
    for (int mt2 = 0; mt2 < 2; mt2++) {
        int r0 = warp * 32 + mt2 * 16 + g;
        tok0[mt2] = attn_row(widx, r0);
        tok1[mt2] = attn_row(widx, r0 + 8);
        const __half* q0 = qkv + tok0[mt2] * QKVN + head * HD;
        const __half* q1 = qkv + tok1[mt2] * QKVN + head * HD;
#pragma unroll
        for (int kk = 0; kk < 4; kk++) {
            qa[mt2][kk][0] = *(const uint32_t*)(q0 + kk * 16 + 2 * t);
            qa[mt2][kk][1] = *(const uint32_t*)(q1 + kk * 16 + 2 * t);
            qa[mt2][kk][2] = *(const uint32_t*)(q0 + kk * 16 + 2 * t + 8);
            qa[mt2][kk][3] = *(const uint32_t*)(q1 + kk * 16 + 2 * t + 8);
        }
    }

    float oacc[2][8][4];
#pragma unroll
    for (int i = 0; i < 2; i++)
#pragma unroll
        for (int j = 0; j < 8; j++)
#pragma unroll
            for (int r = 0; r < 4; r++) oacc[i][j][r] = 0.f;
    float lsum[2][2] = {{0.f, 0.f}, {0.f, 0.f}};
    uint32_t pfrag[2][2][2];

    for (int j = 0; j < 32; j++) {
        uint32_t kb[4][2];
#pragma unroll
        for (int kk = 0; kk < 4; kk++) {
            const __half* bp = ks + (j * 8 + g) * KSH + kk * 16 + 2 * t;
            kb[kk][0] = *(const uint32_t*)(bp);
            kb[kk][1] = *(const uint32_t*)(bp + 8);
        }
#pragma unroll
        for (int mt2 = 0; mt2 < 2; mt2++) {
            float s[4] = {0.f, 0.f, 0.f, 0.f};
#pragma unroll
            for (int kk = 0; kk < 4; kk++) mma16(s, qa[mt2][kk], kb[kk]);
            float e0 = fast_exp2(LOG2E * s[0]);
            float e1 = fast_exp2(LOG2E * s[1]);
            float e2 = fast_exp2(LOG2E * s[2]);
            float e3 = fast_exp2(LOG2E * s[3]);
            lsum[mt2][0] += e0 + e1;
            lsum[mt2][1] += e2 + e3;
            pfrag[mt2][j & 1][0] = h2u(e0, e1);
            pfrag[mt2][j & 1][1] = h2u(e2, e3);
        }
        if (j & 1) {
            int k0 = (j >> 1) * 16;
            uint32_t vb[8][2];
#pragma unroll
            for (int dt = 0; dt < 8; dt++) {
                const __half* bp = vsT + (dt * 8 + g) * VSH + k0 + 2 * t;
                vb[dt][0] = *(const uint32_t*)(bp);
                vb[dt][1] = *(const uint32_t*)(bp + 8);
            }
#pragma unroll
            for (int mt2 = 0; mt2 < 2; mt2++) {
                uint32_t pa[4] = {pfrag[mt2][0][0], pfrag[mt2][0][1],
                                  pfrag[mt2][1][0], pfrag[mt2][1][1]};
#pragma unroll
                for (int dt = 0; dt < 8; dt++) mma16(oacc[mt2][dt], pa, vb[dt]);
            }
        }
    }

    // reduce row sums across the 4 quad lanes
#pragma unroll
    for (int mt2 = 0; mt2 < 2; mt2++)
#pragma unroll
        for (int rr = 0; rr < 2; rr++) {
            float l = lsum[mt2][rr];
            l += __shfl_xor_sync(0xffffffffu, l, 1);
            l += __shfl_xor_sync(0xffffffffu, l, 2);
            lsum[mt2][rr] = l;
        }

#pragma unroll
    for (int mt2 = 0; mt2 < 2; mt2++) {
        float i0 = fast_rcp(lsum[mt2][0]);
        float i1 = fast_rcp(lsum[mt2][1]);
        __half* o0 = ao + tok0[mt2] * DIM + head * HD;
        __half* o1 = ao + tok1[mt2] * DIM + head * HD;
#pragma unroll
        for (int dt = 0; dt < 8; dt++) {
            int c = dt * 8 + 2 * t;
            *(uint32_t*)(o0 + c) = h2u(oacc[mt2][dt][0] * i0, oacc[mt2][dt][1] * i0);
            *(uint32_t*)(o1 + c) = h2u(oacc[mt2][dt][2] * i1, oacc[mt2][dt][3] * i1);
        }
    }
}

// ---------------- host --------------------------------------------------------
extern "C" void kernel_launch(void* const* d_in, const int* in_sizes, int n_in,
                              void* d_out, int out_size) {
    const float* x    = (const float*)d_in[0];
    const float* ln1s = (const float*)d_in[1];
    const float* ln1b = (const float*)d_in[2];
    const float* Wq   = (const float*)d_in[3];
    const float* bq   = (const float*)d_in[4];
    const float* Wk   = (const float*)d_in[5];
    const float* bk   = (const float*)d_in[6];
    const float* Wv   = (const float*)d_in[7];
    const float* bv   = (const float*)d_in[8];
    const float* Wo   = (const float*)d_in[9];
    const float* bo   = (const float*)d_in[10];
    const float* ln2s = (const float*)d_in[11];
    const float* ln2b = (const float*)d_in[12];
    const float* W1   = (const float*)d_in[13];
    const float* b1   = (const float*)d_in[14];
    const float* W2   = (const float*)d_in[15];
    const float* b2   = (const float*)d_in[16];
    float* out = (float*)d_out;

    __half *xn, *qkvb, *aob, *hb, *qkvT, *woT, *w1T, *w2T;
    float* qb3;
    cudaGetSymbolAddress((void**)&xn,   g_xn);
    cudaGetSymbolAddress((void**)&qkvb, g_qkv);
    cudaGetSymbolAddress((void**)&aob,  g_ao);
    cudaGetSymbolAddress((void**)&hb,   g_h);
    cudaGetSymbolAddress((void**)&qkvT, g_qkvT);
    cudaGetSymbolAddress((void**)&woT,  g_woT);
    cudaGetSymbolAddress((void**)&w1T,  g_w1T);
    cudaGetSymbolAddress((void**)&w2T,  g_w2T);
    cudaGetSymbolAddress((void**)&qb3,  g_qkvBias);

    cudaFuncSetAttribute(attn_kernel, cudaFuncAttributeMaxDynamicSharedMemorySize, ATT_SMEM);
    cudaFuncSetAttribute((const void*)tc_gemm<2, float>,  cudaFuncAttributeMaxDynamicSharedMemorySize, GEMM_SMEM);
    cudaFuncSetAttribute((const void*)tc_gemm<3, __half>, cudaFuncAttributeMaxDynamicSharedMemorySize, GEMM_SMEM);
    cudaFuncSetAttribute((const void*)tc_gemm<4, __half>, cudaFuncAttributeMaxDynamicSharedMemorySize, GEMM_SMEM);

    cudaMemcpyAsync(out, x, (size_t)NTOK * DIM * sizeof(float), cudaMemcpyDeviceToDevice, 0);

    for (int l = 0; l < LAYERS; l++) {
        cudaMemcpyAsync(qb3 + l * QKVN,        bq + l * DIM, DIM * sizeof(float), cudaMemcpyDeviceToDevice, 0);
        cudaMemcpyAsync(qb3 + l * QKVN + 768,  bk + l * DIM, DIM * sizeof(float), cudaMemcpyDeviceToDevice, 0);
        cudaMemcpyAsync(qb3 + l * QKVN + 1536, bv + l * DIM, DIM * sizeof(float), cudaMemcpyDeviceToDevice, 0);
    }

    transpose_a<<<dim3(24, 24, 8), dim3(32, 8)>>>(Wq, Wk, Wv, Wo, qkvT, woT);
    transpose_b<<<dim3(96, 96, 4), dim3(32, 8)>>>(W1, W2, w1T, w2T);

    dim3 lnGrid(NTOK / 8), lnBlk(32, 8);
    dim3 gQKV(QKVN / TBN, NTOK / TBM);
    dim3 gD(DIM / TBN,    NTOK / TBM);
    dim3 gH(HDIM / TBN,   NTOK / TBM);

    for (int l = 0; l < LAYERS; l++) {
        long oDD = (long)l * DIM * DIM;
        long oDH = (long)l * DIM * HDIM;

        ln_kernel<<<lnGrid, lnBlk>>>(out, xn, ln1s + l*DIM, ln1b + l*DIM);

        tc_gemm<4, __half><<<gQKV, 128, GEMM_SMEM>>>(xn, qkvT + 3*oDD, qb3 + l*QKVN,
                                                     out, qkvb, DIM, QKVN, 0.125f);

        attn_kernel<<<dim3(NWIN, NHEAD), 256, ATT_SMEM>>>(qkvb, aob);

        tc_gemm<2, float><<<gD, 128, GEMM_SMEM>>>(aob, woT + oDD, bo + l*DIM,
                                                  out, out, DIM, DIM, 1.f);

        ln_kernel<<<lnGrid, lnBlk>>>(out, xn, ln2s + l*DIM, ln2b + l*DIM);

        tc_gemm<3, __half><<<gH, 128, GEMM_SMEM>>>(xn, w1T + oDH, b1 + l*HDIM,
                                                   out, hb, DIM, HDIM, 1.f);
        tc_gemm<2, float><<<gD, 128, GEMM_SMEM>>>(hb, w2T + oDH, b2 + l*DIM,
                                                  out, out, HDIM, DIM, 1.f);
    }
}

// round 8
// speedup vs baseline: 7.0131x; 1.0248x over previous
#include <cuda_runtime.h>
#include <cuda_fp16.h>
#include <math.h>
#include <stdint.h>

#define NTOK 32768
#define DIM 768
#define QKVN 2304
#define HDIM 3072
#define NHEAD 12
#define HD 64
#define NWIN 128
#define WTOK 256
#define LAYERS 2
#define EPS 1e-6f
#define LOG2E 1.4426950409f

__device__ __half g_xn  [NTOK * DIM];
__device__ __half g_qkv [(size_t)NTOK * QKVN];
__device__ __half g_ao  [NTOK * DIM];
__device__ __half g_h   [(size_t)NTOK * HDIM];
__device__ __half g_qkvT[LAYERS * 3 * DIM * DIM];
__device__ __half g_woT [LAYERS * DIM * DIM];
__device__ __half g_w1T [LAYERS * DIM * HDIM];
__device__ __half g_w2T [LAYERS * DIM * HDIM];
__device__ float  g_qkvBias[LAYERS * QKVN];

// ---------------- helpers ---------------------------------------------------
__device__ __forceinline__ uint32_t s2u(const void* p) {
    uint32_t a;
    asm("{ .reg .u64 t; cvta.to.shared.u64 t, %1; cvt.u32.u64 %0, t; }" : "=r"(a) : "l"(p));
    return a;
}
__device__ __forceinline__ float fast_exp2(float x) {
    x = fminf(fmaxf(x, -120.f), 120.f);
    float t = x + 12582912.0f;
    float r = t - 12582912.0f;
    float f = x - r;
    int   e = (int)r;
    float p = 1.0f + f * (0.69314718f + f * (0.24022651f + f * (0.05550411f
                  + f * (0.00961813f + f * 0.00133336f))));
    return __int_as_float((e + 127) << 23) * p;
}
__device__ __forceinline__ float fast_rcp(float d) {
    float r = __int_as_float(0x7EF127EA - __float_as_int(d));
    r = r * (2.0f - d * r);
    r = r * (2.0f - d * r);
    r = r * (2.0f - d * r);
    return r;
}
__device__ __forceinline__ void cp16(uint32_t s, const void* g) {
    asm volatile("cp.async.cg.shared.global [%0], [%1], 16;" :: "r"(s), "l"(g));
}
__device__ __forceinline__ void mma16(float* c, const uint32_t* a, const uint32_t* b) {
    asm volatile(
        "mma.sync.aligned.m16n8k16.row.col.f32.f16.f16.f32 "
        "{%0,%1,%2,%3}, {%4,%5,%6,%7}, {%8,%9}, {%0,%1,%2,%3};"
        : "+f"(c[0]), "+f"(c[1]), "+f"(c[2]), "+f"(c[3])
        : "r"(a[0]), "r"(a[1]), "r"(a[2]), "r"(a[3]), "r"(b[0]), "r"(b[1]));
}
__device__ __forceinline__ void ldsm4(uint32_t* r, uint32_t addr) {
    asm volatile("ldmatrix.sync.aligned.m8n8.x4.shared.b16 {%0,%1,%2,%3}, [%4];"
                 : "=r"(r[0]), "=r"(r[1]), "=r"(r[2]), "=r"(r[3]) : "r"(addr));
}
__device__ __forceinline__ uint32_t h2u(float x, float y) {
    __half2 h = __floats2half2_rn(x, y);
    return *(uint32_t*)&h;
}

// ---------------- weight transposes [K,N] -> [N,K] half ----------------------
__global__ void transpose_a(const float* __restrict__ Wq, const float* __restrict__ Wk,
                            const float* __restrict__ Wv, const float* __restrict__ Wo,
                            __half* __restrict__ qkvT, __half* __restrict__ woT) {
    __shared__ float tb[32][33];
    int w = blockIdx.z >> 1, l = blockIdx.z & 1;
    const float* src = (w == 0 ? Wq : w == 1 ? Wk : w == 2 ? Wv : Wo) + (long)l * DIM * DIM;
    __half* dst = (w < 3) ? qkvT + (long)l * 3 * DIM * DIM + (long)w * DIM * DIM
                          : woT + (long)l * DIM * DIM;
    int nb = blockIdx.x * 32, kb = blockIdx.y * 32;
    int x = threadIdx.x, y = threadIdx.y;
#pragma unroll
    for (int r = 0; r < 32; r += 8)
        tb[y + r][x] = src[(long)(kb + y + r) * DIM + nb + x];
    __syncthreads();
#pragma unroll
    for (int r = 0; r < 32; r += 8)
        dst[(long)(nb + y + r) * DIM + kb + x] = __float2half_rn(tb[x][y + r]);
}
__global__ void transpose_b(const float* __restrict__ W1, const float* __restrict__ W2,
                            __half* __restrict__ d1, __half* __restrict__ d2) {
    __shared__ float tb[32][33];
    int w = blockIdx.z >> 1, l = blockIdx.z & 1;
    const float* src; __half* dst; int K, N;
    if (w == 0) { src = W1 + (long)l * DIM * HDIM; dst = d1 + (long)l * DIM * HDIM; K = DIM;  N = HDIM; }
    else        { src = W2 + (long)l * DIM * HDIM; dst = d2 + (long)l * DIM * HDIM; K = HDIM; N = DIM; }
    if (blockIdx.x * 32 >= (unsigned)N || blockIdx.y * 32 >= (unsigned)K) return;
    int nb = blockIdx.x * 32, kb = blockIdx.y * 32;
    int x = threadIdx.x, y = threadIdx.y;
#pragma unroll
    for (int r = 0; r < 32; r += 8)
        tb[y + r][x] = src[(long)(kb + y + r) * N + nb + x];
    __syncthreads();
#pragma unroll
    for (int r = 0; r < 32; r += 8)
        dst[(long)(nb + y + r) * K + kb + x] = __float2half_rn(tb[x][y + r]);
}

// ---------------- LayerNorm: fp32 in, half out --------------------------------
__global__ void ln_kernel(const float* __restrict__ x, __half* __restrict__ y,
                          const float* __restrict__ gamma, const float* __restrict__ beta) {
    int lane = threadIdx.x;
    long row = (long)blockIdx.x * 8 + threadIdx.y;
    const float4* xr = (const float4*)(x + row * DIM);
    float4 vals[6];
    float s = 0.f, s2 = 0.f;
#pragma unroll
    for (int i = 0; i < 6; i++) {
        float4 f = xr[i * 32 + lane];
        vals[i] = f;
        s  += f.x + f.y + f.z + f.w;
        s2 += f.x*f.x + f.y*f.y + f.z*f.z + f.w*f.w;
    }
#pragma unroll
    for (int off = 16; off; off >>= 1) {
        s  += __shfl_xor_sync(0xffffffffu, s,  off);
        s2 += __shfl_xor_sync(0xffffffffu, s2, off);
    }
    float mean = s * (1.f / DIM);
    float var  = s2 * (1.f / DIM) - mean * mean;
    float inv  = rsqrtf(var + EPS);
    uint2* yr = (uint2*)(y + row * DIM);
    const float4* gg = (const float4*)gamma;
    const float4* bb = (const float4*)beta;
#pragma unroll
    for (int i = 0; i < 6; i++) {
        int c = i * 32 + lane;
        float4 g = gg[c], b = bb[c], v = vals[i];
        uint2 u;
        u.x = h2u((v.x - mean) * inv * g.x + b.x, (v.y - mean) * inv * g.y + b.y);
        u.y = h2u((v.z - mean) * inv * g.z + b.z, (v.w - mean) * inv * g.w + b.w);
        yr[c] = u;
    }
}

// ---------------- fp16 mma GEMM with ldmatrix fragments ----------------------
#define TBM 128
#define TBN 128
#define TBK 64
#define SH 72
#define TSTG (128 * SH)
#define STGH (2 * TSTG)
#define GEMM_SMEM (2 * STGH * 2)

template <int EPI, typename CT>
__global__ void __launch_bounds__(128, 2)
tc_gemm(const __half* __restrict__ A, const __half* __restrict__ Wt,
        const float* __restrict__ bias, const float* __restrict__ res,
        CT* __restrict__ C, int K, int N, float alpha) {
    extern __shared__ __half smh[];
    int tid = threadIdx.x;
    int lane = tid & 31, wid = tid >> 5;
    int g = lane >> 2, t = lane & 3;
    int m0 = (wid & 1) * 64, n0 = (wid >> 1) * 64;
    long row0 = (long)blockIdx.y * TBM;
    int  col0 = blockIdx.x * TBN;

    float acc[4][8][4];
#pragma unroll
    for (int i = 0; i < 4; i++)
#pragma unroll
        for (int j = 0; j < 8; j++)
#pragma unroll
            for (int r = 0; r < 4; r++) acc[i][j][r] = 0.f;

    uint32_t sbase = s2u(smh);
    int iters = K / TBK;

    // per-thread ldmatrix base offsets (halfs)
    int aoff = (m0 + (lane & 15)) * SH + ((lane >> 4) << 3);
    int boff = (n0 + (lane & 7) + ((lane >> 4) << 3)) * SH + (((lane >> 3) & 1) << 3);

    auto produce = [&](int stage, int k0) {
        uint32_t ab = sbase + stage * STGH * 2;
        uint32_t bb = ab + TSTG * 2;
#pragma unroll
        for (int j = 0; j < 8; j++) {
            int id = tid + j * 128;
            int r = id >> 3, o = id & 7;
            cp16(ab + r * 144 + o * 16, A  + (row0 + r) * (long)K + k0 + o * 8);
            cp16(bb + r * 144 + o * 16, Wt + (col0 + r) * (long)K + k0 + o * 8);
        }
        asm volatile("cp.async.commit_group;" ::: "memory");
    };

    produce(0, 0);
    for (int i = 0; i < iters; i++) {
        if (i + 1 < iters) {
            produce((i + 1) & 1, (i + 1) * TBK);
            asm volatile("cp.async.wait_group 1;" ::: "memory");
        } else {
            asm volatile("cp.async.wait_group 0;" ::: "memory");
        }
        __syncthreads();
        uint32_t ab = sbase + (i & 1) * STGH * 2;
        uint32_t bb = ab + TSTG * 2;
#pragma unroll
        for (int kk = 0; kk < 4; kk++) {
            int k2 = kk * 16;
            uint32_t a[4][4], b[4][4];
#pragma unroll
            for (int mt = 0; mt < 4; mt++)
                ldsm4(a[mt], ab + (aoff + mt * 16 * SH + k2) * 2);
#pragma unroll
            for (int np = 0; np < 4; np++)
                ldsm4(b[np], bb + (boff + np * 16 * SH + k2) * 2);
#pragma unroll
            for (int mt = 0; mt < 4; mt++)
#pragma unroll
                for (int nt = 0; nt < 8; nt++)
                    mma16(acc[mt][nt], a[mt], &b[nt >> 1][(nt & 1) * 2]);
        }
        __syncthreads();
    }

    float sc = (EPI == 4) ? ((col0 < 768) ? alpha : 1.f) : alpha;
#pragma unroll
    for (int mt = 0; mt < 4; mt++)
#pragma unroll
    for (int rh = 0; rh < 2; rh++) {
        long r = row0 + m0 + mt * 16 + rh * 8 + g;
        CT* cp = C + r * (long)N + col0;
        const float* rp = res + r * (long)N + col0;
#pragma unroll
        for (int nt = 0; nt < 8; nt++) {
            int c = n0 + nt * 8 + 2 * t;
            float vx = acc[mt][nt][rh * 2 + 0] + bias[col0 + c];
            float vy = acc[mt][nt][rh * 2 + 1] + bias[col0 + c + 1];
            if (EPI == 4) { vx *= sc; vy *= sc; }
            if (EPI == 2) { vx += rp[c]; vy += rp[c + 1]; }
            if (EPI == 3) {
                vx = vx * fast_rcp(1.f + fast_exp2(-2.45547238f * vx));
                vy = vy * fast_rcp(1.f + fast_exp2(-2.45547238f * vy));
            }
            if (sizeof(CT) == 2) {
                *(uint32_t*)(cp + c) = h2u(vx, vy);
            } else {
                float2 v; v.x = vx; v.y = vy;
                *(float2*)((float*)cp + c) = v;
            }
        }
    }
}

// ---------------- tensor-core window attention (ldmatrix fragments) -----------
#define KSH 72
#define VSH 264
#define ATT_SMEM ((WTOK * KSH + HD * VSH) * 2)

__device__ __forceinline__ long attn_row(int widx, int t) {
    int b = widx & 7;
    int ij = widx >> 3;
    int wi = ij >> 2, wj = ij & 3;
    int hh = t >> 4, ww = t & 15;
    return (long)b * 4096 + (wi * 16 + hh) * 64 + (wj * 16 + ww);
}

__global__ void __launch_bounds__(256, 1)
attn_kernel(const __half* __restrict__ qkv, __half* __restrict__ ao) {
    extern __shared__ __half smh[];
    __half* ks  = smh;                 // [256][KSH]
    __half* vsT = smh + WTOK * KSH;    // [64][VSH]
    int widx = blockIdx.x, head = blockIdx.y, tid = threadIdx.x;
    int lane = tid & 31, warp = tid >> 5;
    int g = lane >> 2, t = lane & 3;

    {
        int key = tid;
        long tok = attn_row(widx, key);
        const uint4* kp4 = (const uint4*)(qkv + tok * QKVN + 768 + head * HD);
        uint4* kd = (uint4*)(ks + key * KSH);
#pragma unroll
        for (int o = 0; o < 8; o++) kd[o] = kp4[o];
        const uint4* vp4 = kp4 + 96;
#pragma unroll
        for (int o = 0; o < 8; o++) {
            uint4 u = vp4[o];
            const __half* hh = (const __half*)&u;
#pragma unroll
            for (int d2 = 0; d2 < 8; d2++)
                vsT[(o * 8 + d2) * VSH + key] = hh[d2];
        }
    }
    __syncthreads();

    uint32_t ksb = s2u(ks), vsb = s2u(vsT);
    // K as B-operand: 4 k-blocks per ldmatrix (rows = 8 keys)
    int koff = (lane & 7) * KSH + (lane >> 3) * 8;
    // V^T as B-operand: 2 d-tiles per ldmatrix
    int voff = ((lane & 7) + ((lane >> 4) << 3)) * VSH + (((lane >> 3) & 1) << 3);

    uint32_t qa[2][4][4];
    long tok0[2], tok1[2];
#pragma unroll
    for (int mt2 = 0; mt2 < 2; mt2++) {
        int r0 = warp * 32 + mt2 * 16 + g;
        tok0[mt2] = attn_row(widx, r0);
        tok1[mt2] = attn_row(widx, r0 + 8);
        const __half* q0 = qkv + tok0[mt2] * QKVN + head * HD;
        const __half* q1 = qkv + tok1[mt2] * QKVN + head * HD;
#pragma unroll
        for (int kk = 0; kk < 4; kk++) {
            qa[mt2][kk][0] = *(const uint32_t*)(q0 + kk * 16 + 2 * t);
            qa[mt2][kk][1] = *(const uint32_t*)(q1 + kk * 16 + 2 * t);
            qa[mt2][kk][2] = *(const uint32_t*)(q0 + kk * 16 + 2 * t + 8);
            qa[mt2][kk][3] = *(const uint32_t*)(q1 + kk * 16 + 2 * t + 8);
        }
    }

    float oacc[2][8][4];
#pragma unroll
    for (int i = 0; i < 2; i++)
#pragma unroll
        for (int j = 0; j < 8; j++)
#pragma unroll
            for (int r = 0; r < 4; r++) oacc[i][j][r] = 0.f;
    float lsum[2][2] = {{0.f, 0.f}, {0.f, 0.f}};
    uint32_t pfrag[2][2][2];

    for (int j = 0; j < 32; j++) {
        uint32_t kb[2][4];
        ldsm4(kb[0], ksb + (j * 8 * KSH + koff) * 2);           // k 0..31
        ldsm4(kb[1], ksb + (j * 8 * KSH + koff + 32) * 2);      // k 32..63
#pragma unroll
        for (int mt2 = 0; mt2 < 2; mt2++) {
            float s[4] = {0.f, 0.f, 0.f, 0.f};
#pragma unroll
            for (int kk = 0; kk < 4; kk++)
                mma16(s, qa[mt2][kk], &kb[kk >> 1][(kk & 1) * 2]);
            float e0 = fast_exp2(LOG2E * s[0]);
            float e1 = fast_exp2(LOG2E * s[1]);
            float e2 = fast_exp2(LOG2E * s[2]);
            float e3 = fast_exp2(LOG2E * s[3]);
            lsum[mt2][0] += e0 + e1;
            lsum[mt2][1] += e2 + e3;
            pfrag[mt2][j & 1][0] = h2u(e0, e1);
            pfrag[mt2][j & 1][1] = h2u(e2, e3);
        }
        if (j & 1) {
            int k0 = (j >> 1) * 16;
            uint32_t vb[4][4];
#pragma unroll
            for (int dp = 0; dp < 4; dp++)
                ldsm4(vb[dp], vsb + (dp * 16 * VSH + voff + k0) * 2);
#pragma unroll
            for (int mt2 = 0; mt2 < 2; mt2++) {
                uint32_t pa[4] = {pfrag[mt2][0][0], pfrag[mt2][0][1],
                                  pfrag[mt2][1][0], pfrag[mt2][1][1]};
#pragma unroll
                for (int dt = 0; dt < 8; dt++)
                    mma16(oacc[mt2][dt], pa, &vb[dt >> 1][(dt & 1) * 2]);
            }
        }
    }

#pragma unroll
    for (int mt2 = 0; mt2 < 2; mt2++)
#pragma unroll
        for (int rr = 0; rr < 2; rr++) {
            float l = lsum[mt2][rr];
            l += __shfl_xor_sync(0xffffffffu, l, 1);
            l += __shfl_xor_sync(0xffffffffu, l, 2);
            lsum[mt2][rr] = l;
        }

#pragma unroll
    for (int mt2 = 0; mt2 < 2; mt2++) {
        float i0 = fast_rcp(lsum[mt2][0]);
        float i1 = fast_rcp(lsum[mt2][1]);
        __half* o0 = ao + tok0[mt2] * DIM + head * HD;
        __half* o1 = ao + tok1[mt2] * DIM + head * HD;
#pragma unroll
        for (int dt = 0; dt < 8; dt++) {
            int c = dt * 8 + 2 * t;
            *(uint32_t*)(o0 + c) = h2u(oacc[mt2][dt][0] * i0, oacc[mt2][dt][1] * i0);
            *(uint32_t*)(o1 + c) = h2u(oacc[mt2][dt][2] * i1, oacc[mt2][dt][3] * i1);
        }
    }
}

// ---------------- host --------------------------------------------------------
extern "C" void kernel_launch(void* const* d_in, const int* in_sizes, int n_in,
                              void* d_out, int out_size) {
    const float* x    = (const float*)d_in[0];
    const float* ln1s = (const float*)d_in[1];
    const float* ln1b = (const float*)d_in[2];
    const float* Wq   = (const float*)d_in[3];
    const float* bq   = (const float*)d_in[4];
    const float* Wk   = (const float*)d_in[5];
    const float* bk   = (const float*)d_in[6];
    const float* Wv   = (const float*)d_in[7];
    const float* bv   = (const float*)d_in[8];
    const float* Wo   = (const float*)d_in[9];
    const float* bo   = (const float*)d_in[10];
    const float* ln2s = (const float*)d_in[11];
    const float* ln2b = (const float*)d_in[12];
    const float* W1   = (const float*)d_in[13];
    const float* b1   = (const float*)d_in[14];
    const float* W2   = (const float*)d_in[15];
    const float* b2   = (const float*)d_in[16];
    float* out = (float*)d_out;

    __half *xn, *qkvb, *aob, *hb, *qkvT, *woT, *w1T, *w2T;
    float* qb3;
    cudaGetSymbolAddress((void**)&xn,   g_xn);
    cudaGetSymbolAddress((void**)&qkvb, g_qkv);
    cudaGetSymbolAddress((void**)&aob,  g_ao);
    cudaGetSymbolAddress((void**)&hb,   g_h);
    cudaGetSymbolAddress((void**)&qkvT, g_qkvT);
    cudaGetSymbolAddress((void**)&woT,  g_woT);
    cudaGetSymbolAddress((void**)&w1T,  g_w1T);
    cudaGetSymbolAddress((void**)&w2T,  g_w2T);
    cudaGetSymbolAddress((void**)&qb3,  g_qkvBias);

    cudaFuncSetAttribute(attn_kernel, cudaFuncAttributeMaxDynamicSharedMemorySize, ATT_SMEM);
    cudaFuncSetAttribute((const void*)tc_gemm<2, float>,  cudaFuncAttributeMaxDynamicSharedMemorySize, GEMM_SMEM);
    cudaFuncSetAttribute((const void*)tc_gemm<3, __half>, cudaFuncAttributeMaxDynamicSharedMemorySize, GEMM_SMEM);
    cudaFuncSetAttribute((const void*)tc_gemm<4, __half>, cudaFuncAttributeMaxDynamicSharedMemorySize, GEMM_SMEM);

    cudaMemcpyAsync(out, x, (size_t)NTOK * DIM * sizeof(float), cudaMemcpyDeviceToDevice, 0);

    for (int l = 0; l < LAYERS; l++) {
        cudaMemcpyAsync(qb3 + l * QKVN,        bq + l * DIM, DIM * sizeof(float), cudaMemcpyDeviceToDevice, 0);
        cudaMemcpyAsync(qb3 + l * QKVN + 768,  bk + l * DIM, DIM * sizeof(float), cudaMemcpyDeviceToDevice, 0);
        cudaMemcpyAsync(qb3 + l * QKVN + 1536, bv + l * DIM, DIM * sizeof(float), cudaMemcpyDeviceToDevice, 0);
    }

    transpose_a<<<dim3(24, 24, 8), dim3(32, 8)>>>(Wq, Wk, Wv, Wo, qkvT, woT);
    transpose_b<<<dim3(96, 96, 4), dim3(32, 8)>>>(W1, W2, w1T, w2T);

    dim3 lnGrid(NTOK / 8), lnBlk(32, 8);
    dim3 gQKV(QKVN / TBN, NTOK / TBM);
    dim3 gD(DIM / TBN,    NTOK / TBM);
    dim3 gH(HDIM / TBN,   NTOK / TBM);

    for (int l = 0; l < LAYERS; l++) {
        long oDD = (long)l * DIM * DIM;
        long oDH = (long)l * DIM * HDIM;

        ln_kernel<<<lnGrid, lnBlk>>>(out, xn, ln1s + l*DIM, ln1b + l*DIM);

        tc_gemm<4, __half><<<gQKV, 128, GEMM_SMEM>>>(xn, qkvT + 3*oDD, qb3 + l*QKVN,
                                                     out, qkvb, DIM, QKVN, 0.125f);

        attn_kernel<<<dim3(NWIN, NHEAD), 256, ATT_SMEM>>>(qkvb, aob);

        tc_gemm<2, float><<<gD, 128, GEMM_SMEM>>>(aob, woT + oDD, bo + l*DIM,
                                                  out, out, DIM, DIM, 1.f);

        ln_kernel<<<lnGrid, lnBlk>>>(out, xn, ln2s + l*DIM, ln2b + l*DIM);

        tc_gemm<3, __half><<<gH, 128, GEMM_SMEM>>>(xn, w1T + oDH, b1 + l*HDIM,
                                                   out, hb, DIM, HDIM, 1.f);
        tc_gemm<2, float><<<gD, 128, GEMM_SMEM>>>(hb, w2T + oDH, b2 + l*DIM,
                                                  out, out, HDIM, DIM, 1.f);
    }
}

// round 10
// speedup vs baseline: 7.0936x; 1.0115x over previous
#include <cuda_runtime.h>
#include <cuda_fp16.h>
#include <math.h>
#include <stdint.h>

#define NTOK 32768
#define DIM 768
#define QKVN 2304
#define HDIM 3072
#define NHEAD 12
#define HD 64
#define NWIN 128
#define WTOK 256
#define LAYERS 2
#define EPS 1e-6f
#define LOG2E 1.4426950409f

__device__ __half g_xn  [NTOK * DIM];
__device__ __half g_qkv [(size_t)NTOK * QKVN];
__device__ __half g_ao  [NTOK * DIM];
__device__ __half g_h   [(size_t)NTOK * HDIM];
__device__ __half g_qkvT[LAYERS * 3 * DIM * DIM];
__device__ __half g_woT [LAYERS * DIM * DIM];
__device__ __half g_w1T [LAYERS * DIM * HDIM];
__device__ __half g_w2T [LAYERS * DIM * HDIM];
__device__ float  g_qkvBias[LAYERS * QKVN];

// ---------------- helpers ---------------------------------------------------
__device__ __forceinline__ uint32_t s2u(const void* p) {
    uint32_t a;
    asm("{ .reg .u64 t; cvta.to.shared.u64 t, %1; cvt.u32.u64 %0, t; }" : "=r"(a) : "l"(p));
    return a;
}
__device__ __forceinline__ float fast_exp2(float x) {
    x = fminf(fmaxf(x, -120.f), 120.f);
    float t = x + 12582912.0f;
    float r = t - 12582912.0f;
    float f = x - r;
    int   e = (int)r;
    float p = 1.0f + f * (0.69314718f + f * (0.24022651f + f * (0.05550411f
                  + f * (0.00961813f + f * 0.00133336f))));
    return __int_as_float((e + 127) << 23) * p;
}
__device__ __forceinline__ float fast_rcp(float d) {
    float r = __int_as_float(0x7EF127EA - __float_as_int(d));
    r = r * (2.0f - d * r);
    r = r * (2.0f - d * r);
    r = r * (2.0f - d * r);
    return r;
}
__device__ __forceinline__ void cp16(uint32_t s, const void* g) {
    asm volatile("cp.async.cg.shared.global [%0], [%1], 16;" :: "r"(s), "l"(g));
}
__device__ __forceinline__ void mma16(float* c, const uint32_t* a, const uint32_t* b) {
    asm volatile(
        "mma.sync.aligned.m16n8k16.row.col.f32.f16.f16.f32 "
        "{%0,%1,%2,%3}, {%4,%5,%6,%7}, {%8,%9}, {%0,%1,%2,%3};"
        : "+f"(c[0]), "+f"(c[1]), "+f"(c[2]), "+f"(c[3])
        : "r"(a[0]), "r"(a[1]), "r"(a[2]), "r"(a[3]), "r"(b[0]), "r"(b[1]));
}
__device__ __forceinline__ void ldsm4(uint32_t* r, uint32_t addr) {
    asm volatile("ldmatrix.sync.aligned.m8n8.x4.shared.b16 {%0,%1,%2,%3}, [%4];"
                 : "=r"(r[0]), "=r"(r[1]), "=r"(r[2]), "=r"(r[3]) : "r"(addr));
}
__device__ __forceinline__ uint32_t h2u(float x, float y) {
    __half2 h = __floats2half2_rn(x, y);
    return *(uint32_t*)&h;
}

// ---------------- weight transposes [K,N] -> [N,K] half ----------------------
__global__ void transpose_a(const float* __restrict__ Wq, const float* __restrict__ Wk,
                            const float* __restrict__ Wv, const float* __restrict__ Wo,
                            __half* __restrict__ qkvT, __half* __restrict__ woT) {
    __shared__ float tb[32][33];
    int w = blockIdx.z >> 1, l = blockIdx.z & 1;
    const float* src = (w == 0 ? Wq : w == 1 ? Wk : w == 2 ? Wv : Wo) + (long)l * DIM * DIM;
    __half* dst = (w < 3) ? qkvT + (long)l * 3 * DIM * DIM + (long)w * DIM * DIM
                          : woT + (long)l * DIM * DIM;
    int nb = blockIdx.x * 32, kb = blockIdx.y * 32;
    int x = threadIdx.x, y = threadIdx.y;
#pragma unroll
    for (int r = 0; r < 32; r += 8)
        tb[y + r][x] = src[(long)(kb + y + r) * DIM + nb + x];
    __syncthreads();
#pragma unroll
    for (int r = 0; r < 32; r += 8)
        dst[(long)(nb + y + r) * DIM + kb + x] = __float2half_rn(tb[x][y + r]);
}
__global__ void transpose_b(const float* __restrict__ W1, const float* __restrict__ W2,
                            __half* __restrict__ d1, __half* __restrict__ d2) {
    __shared__ float tb[32][33];
    int w = blockIdx.z >> 1, l = blockIdx.z & 1;
    const float* src; __half* dst; int K, N;
    if (w == 0) { src = W1 + (long)l * DIM * HDIM; dst = d1 + (long)l * DIM * HDIM; K = DIM;  N = HDIM; }
    else        { src = W2 + (long)l * DIM * HDIM; dst = d2 + (long)l * DIM * HDIM; K = HDIM; N = DIM; }
    if (blockIdx.x * 32 >= (unsigned)N || blockIdx.y * 32 >= (unsigned)K) return;
    int nb = blockIdx.x * 32, kb = blockIdx.y * 32;
    int x = threadIdx.x, y = threadIdx.y;
#pragma unroll
    for (int r = 0; r < 32; r += 8)
        tb[y + r][x] = src[(long)(kb + y + r) * N + nb + x];
    __syncthreads();
#pragma unroll
    for (int r = 0; r < 32; r += 8)
        dst[(long)(nb + y + r) * K + kb + x] = __float2half_rn(tb[x][y + r]);
}

// ---------------- LayerNorm: fp32 in, half out --------------------------------
__global__ void ln_kernel(const float* __restrict__ x, __half* __restrict__ y,
                          const float* __restrict__ gamma, const float* __restrict__ beta) {
    int lane = threadIdx.x;
    long row = (long)blockIdx.x * 8 + threadIdx.y;
    const float4* xr = (const float4*)(x + row * DIM);
    float4 vals[6];
    float s = 0.f, s2 = 0.f;
#pragma unroll
    for (int i = 0; i < 6; i++) {
        float4 f = xr[i * 32 + lane];
        vals[i] = f;
        s  += f.x + f.y + f.z + f.w;
        s2 += f.x*f.x + f.y*f.y + f.z*f.z + f.w*f.w;
    }
#pragma unroll
    for (int off = 16; off; off >>= 1) {
        s  += __shfl_xor_sync(0xffffffffu, s,  off);
        s2 += __shfl_xor_sync(0xffffffffu, s2, off);
    }
    float mean = s * (1.f / DIM);
    float var  = s2 * (1.f / DIM) - mean * mean;
    float inv  = rsqrtf(var + EPS);
    uint2* yr = (uint2*)(y + row * DIM);
    const float4* gg = (const float4*)gamma;
    const float4* bb = (const float4*)beta;
#pragma unroll
    for (int i = 0; i < 6; i++) {
        int c = i * 32 + lane;
        float4 g = gg[c], b = bb[c], v = vals[i];
        uint2 u;
        u.x = h2u((v.x - mean) * inv * g.x + b.x, (v.y - mean) * inv * g.y + b.y);
        u.y = h2u((v.z - mean) * inv * g.z + b.z, (v.w - mean) * inv * g.w + b.w);
        yr[c] = u;
    }
}

// ---------------- fp16 mma GEMM: 3-stage, single sync per k-iter --------------
#define TBM 128
#define TBN 128
#define TBK 64
#define SH 72
#define TSTG (128 * SH)
#define STGH (2 * TSTG)
#define NSTG 3
#define GEMM_SMEM (NSTG * STGH * 2)   // 110592 B; 2 CTAs = 221 KB/SM

template <int EPI, typename CT>
__global__ void __launch_bounds__(128, 2)
tc_gemm(const __half* __restrict__ A, const __half* __restrict__ Wt,
        const float* __restrict__ bias, const float* __restrict__ res,
        CT* __restrict__ C, int K, int N, float alpha) {
    extern __shared__ __half smh[];
    int tid = threadIdx.x;
    int lane = tid & 31, wid = tid >> 5;
    int g = lane >> 2, t = lane & 3;
    int m0 = (wid & 1) * 64, n0 = (wid >> 1) * 64;
    long row0 = (long)blockIdx.y * TBM;
    int  col0 = blockIdx.x * TBN;

    float acc[4][8][4];
#pragma unroll
    for (int i = 0; i < 4; i++)
#pragma unroll
        for (int j = 0; j < 8; j++)
#pragma unroll
            for (int r = 0; r < 4; r++) acc[i][j][r] = 0.f;

    uint32_t sbase = s2u(smh);
    int iters = K / TBK;

    int aoff = (m0 + (lane & 15)) * SH + ((lane >> 4) << 3);
    int boff = (n0 + (lane & 7) + ((lane >> 4) << 3)) * SH + (((lane >> 3) & 1) << 3);

    auto produce = [&](int stage, int k0) {
        uint32_t ab = sbase + stage * STGH * 2;
        uint32_t bb = ab + TSTG * 2;
#pragma unroll
        for (int j = 0; j < 8; j++) {
            int id = tid + j * 128;
            int r = id >> 3, o = id & 7;
            cp16(ab + r * 144 + o * 16, A  + (row0 + r) * (long)K + k0 + o * 8);
            cp16(bb + r * 144 + o * 16, Wt + (col0 + r) * (long)K + k0 + o * 8);
        }
        asm volatile("cp.async.commit_group;" ::: "memory");
    };

    produce(0, 0);
    produce(1, TBK);
    int cs = 0;                 // compute stage buffer
    int ps = 2;                 // next produce buffer
    for (int i = 0; i < iters; i++) {
        if (i < iters - 1) {
            asm volatile("cp.async.wait_group 1;" ::: "memory");   // group i landed
        } else {
            asm volatile("cp.async.wait_group 0;" ::: "memory");
        }
        __syncthreads();        // visibility of group i to ALL threads; all done with i-1
        if (i + 2 < iters) {
            produce(ps, (i + 2) * TBK);   // writes buffer (i-1)%3: everyone finished it
            if (++ps == NSTG) ps = 0;
        }
        uint32_t ab = sbase + cs * STGH * 2;
        uint32_t bb = ab + TSTG * 2;
        if (++cs == NSTG) cs = 0;
#pragma unroll
        for (int kk = 0; kk < 4; kk++) {
            int k2 = kk * 16;
            uint32_t a[4][4], b[4][4];
#pragma unroll
            for (int mt = 0; mt < 4; mt++)
                ldsm4(a[mt], ab + (aoff + mt * 16 * SH + k2) * 2);
#pragma unroll
            for (int np = 0; np < 4; np++)
                ldsm4(b[np], bb + (boff + np * 16 * SH + k2) * 2);
#pragma unroll
            for (int mt = 0; mt < 4; mt++)
#pragma unroll
                for (int nt = 0; nt < 8; nt++)
                    mma16(acc[mt][nt], a[mt], &b[nt >> 1][(nt & 1) * 2]);
        }
    }

    float sc = (EPI == 4) ? ((col0 < 768) ? alpha : 1.f) : alpha;
#pragma unroll
    for (int mt = 0; mt < 4; mt++)
#pragma unroll
    for (int rh = 0; rh < 2; rh++) {
        long r = row0 + m0 + mt * 16 + rh * 8 + g;
        CT* cp = C + r * (long)N + col0;
        const float* rp = res + r * (long)N + col0;
#pragma unroll
        for (int nt = 0; nt < 8; nt++) {
            int c = n0 + nt * 8 + 2 * t;
            float vx = acc[mt][nt][rh * 2 + 0] + bias[col0 + c];
            float vy = acc[mt][nt][rh * 2 + 1] + bias[col0 + c + 1];
            if (EPI == 4) { vx *= sc; vy *= sc; }
            if (EPI == 2) { vx += rp[c]; vy += rp[c + 1]; }
            if (EPI == 3) {
                vx = vx * fast_rcp(1.f + fast_exp2(-2.45547238f * vx));
                vy = vy * fast_rcp(1.f + fast_exp2(-2.45547238f * vy));
            }
            if (sizeof(CT) == 2) {
                *(uint32_t*)(cp + c) = h2u(vx, vy);
            } else {
                float2 v; v.x = vx; v.y = vy;
                *(float2*)((float*)cp + c) = v;
            }
        }
    }
}

// ---------------- tensor-core window attention (round-8 proven version) -------
#define KSH 72
#define VSH 264
#define ATT_SMEM ((WTOK * KSH + HD * VSH) * 2)

__device__ __forceinline__ long attn_row(int widx, int t) {
    int b = widx & 7;
    int ij = widx >> 3;
    int wi = ij >> 2, wj = ij & 3;
    int hh = t >> 4, ww = t & 15;
    return (long)b * 4096 + (wi * 16 + hh) * 64 + (wj * 16 + ww);
}

__global__ void __launch_bounds__(256, 1)
attn_kernel(const __half* __restrict__ qkv, __half* __restrict__ ao) {
    extern __shared__ __half smh[];
    __half* ks  = smh;                 // [256][KSH]
    __half* vsT = smh + WTOK * KSH;    // [64][VSH]
    int widx = blockIdx.x, head = blockIdx.y, tid = threadIdx.x;
    int lane = tid & 31, warp = tid >> 5;
    int g = lane >> 2, t = lane & 3;

    {
        int key = tid;
        long tok = attn_row(widx, key);
        const uint4* kp4 = (const uint4*)(qkv + tok * QKVN + 768 + head * HD);
        uint4* kd = (uint4*)(ks + key * KSH);
#pragma unroll
        for (int o = 0; o < 8; o++) kd[o] = kp4[o];
        const uint4* vp4 = kp4 + 96;
#pragma unroll
        for (int o = 0; o < 8; o++) {
            uint4 u = vp4[o];
            const __half* hh = (const __half*)&u;
#pragma unroll
            for (int d2 = 0; d2 < 8; d2++)
                vsT[(o * 8 + d2) * VSH + key] = hh[d2];
        }
    }
    __syncthreads();

    uint32_t ksb = s2u(ks), vsb = s2u(vsT);
    int koff = (lane & 7) * KSH + (lane >> 3) * 8;
    int voff = ((lane & 7) + ((lane >> 4) << 3)) * VSH + (((lane >> 3) & 1) << 3);

    uint32_t qa[2][4][4];
    long tok0[2], tok1[2];
#pragma unroll
    for (int mt2 = 0; mt2 < 2; mt2++) {
        int r0 = warp * 32 + mt2 * 16 + g;
        tok0[mt2] = attn_row(widx, r0);
        tok1[mt2] = attn_row(widx, r0 + 8);
        const __half* q0 = qkv + tok0[mt2] * QKVN + head * HD;
        const __half* q1 = qkv + tok1[mt2] * QKVN + head * HD;
#pragma unroll
        for (int kk = 0; kk < 4; kk++) {
            qa[mt2][kk][0] = *(const uint32_t*)(q0 + kk * 16 + 2 * t);
            qa[mt2][kk][1] = *(const uint32_t*)(q1 + kk * 16 + 2 * t);
            qa[mt2][kk][2] = *(const uint32_t*)(q0 + kk * 16 + 2 * t + 8);
            qa[mt2][kk][3] = *(const uint32_t*)(q1 + kk * 16 + 2 * t + 8);
        }
    }

    float oacc[2][8][4];
#pragma unroll
    for (int i = 0; i < 2; i++)
#pragma unroll
        for (int j = 0; j < 8; j++)
#pragma unroll
            for (int r = 0; r < 4; r++) oacc[i][j][r] = 0.f;
    float lsum[2][2] = {{0.f, 0.f}, {0.f, 0.f}};
    uint32_t pfrag[2][2][2];

    for (int j = 0; j < 32; j++) {
        uint32_t kb[2][4];
        ldsm4(kb[0], ksb + (j * 8 * KSH + koff) * 2);
        ldsm4(kb[1], ksb + (j * 8 * KSH + koff + 32) * 2);
#pragma unroll
        for (int mt2 = 0; mt2 < 2; mt2++) {
            float s[4] = {0.f, 0.f, 0.f, 0.f};
#pragma unroll
            for (int kk = 0; kk < 4; kk++)
                mma16(s, qa[mt2][kk], &kb[kk >> 1][(kk & 1) * 2]);
            float e0 = fast_exp2(LOG2E * s[0]);
            float e1 = fast_exp2(LOG2E * s[1]);
            float e2 = fast_exp2(LOG2E * s[2]);
            float e3 = fast_exp2(LOG2E * s[3]);
            lsum[mt2][0] += e0 + e1;
            lsum[mt2][1] += e2 + e3;
            pfrag[mt2][j & 1][0] = h2u(e0, e1);
            pfrag[mt2][j & 1][1] = h2u(e2, e3);
        }
        if (j & 1) {
            int k0 = (j >> 1) * 16;
            uint32_t vb[4][4];
#pragma unroll
            for (int dp = 0; dp < 4; dp++)
                ldsm4(vb[dp], vsb + (dp * 16 * VSH + voff + k0) * 2);
#pragma unroll
            for (int mt2 = 0; mt2 < 2; mt2++) {
                uint32_t pa[4] = {pfrag[mt2][0][0], pfrag[mt2][0][1],
                                  pfrag[mt2][1][0], pfrag[mt2][1][1]};
#pragma unroll
                for (int dt = 0; dt < 8; dt++)
                    mma16(oacc[mt2][dt], pa, &vb[dt >> 1][(dt & 1) * 2]);
            }
        }
    }

#pragma unroll
    for (int mt2 = 0; mt2 < 2; mt2++)
#pragma unroll
        for (int rr = 0; rr < 2; rr++) {
            float l = lsum[mt2][rr];
            l += __shfl_xor_sync(0xffffffffu, l, 1);
            l += __shfl_xor_sync(0xffffffffu, l, 2);
            lsum[mt2][rr] = l;
        }

#pragma unroll
    for (int mt2 = 0; mt2 < 2; mt2++) {
        float i0 = fast_rcp(lsum[mt2][0]);
        float i1 = fast_rcp(lsum[mt2][1]);
        __half* o0 = ao + tok0[mt2] * DIM + head * HD;
        __half* o1 = ao + tok1[mt2] * DIM + head * HD;
#pragma unroll
        for (int dt = 0; dt < 8; dt++) {
            int c = dt * 8 + 2 * t;
            *(uint32_t*)(o0 + c) = h2u(oacc[mt2][dt][0] * i0, oacc[mt2][dt][1] * i0);
            *(uint32_t*)(o1 + c) = h2u(oacc[mt2][dt][2] * i1, oacc[mt2][dt][3] * i1);
        }
    }
}

// ---------------- host --------------------------------------------------------
extern "C" void kernel_launch(void* const* d_in, const int* in_sizes, int n_in,
                              void* d_out, int out_size) {
    const float* x    = (const float*)d_in[0];
    const float* ln1s = (const float*)d_in[1];
    const float* ln1b = (const float*)d_in[2];
    const float* Wq   = (const float*)d_in[3];
    const float* bq   = (const float*)d_in[4];
    const float* Wk   = (const float*)d_in[5];
    const float* bk   = (const float*)d_in[6];
    const float* Wv   = (const float*)d_in[7];
    const float* bv   = (const float*)d_in[8];
    const float* Wo   = (const float*)d_in[9];
    const float* bo   = (const float*)d_in[10];
    const float* ln2s = (const float*)d_in[11];
    const float* ln2b = (const float*)d_in[12];
    const float* W1   = (const float*)d_in[13];
    const float* b1   = (const float*)d_in[14];
    const float* W2   = (const float*)d_in[15];
    const float* b2   = (const float*)d_in[16];
    float* out = (float*)d_out;

    __half *xn, *qkvb, *aob, *hb, *qkvT, *woT, *w1T, *w2T;
    float* qb3;
    cudaGetSymbolAddress((void**)&xn,   g_xn);
    cudaGetSymbolAddress((void**)&qkvb, g_qkv);
    cudaGetSymbolAddress((void**)&aob,  g_ao);
    cudaGetSymbolAddress((void**)&hb,   g_h);
    cudaGetSymbolAddress((void**)&qkvT, g_qkvT);
    cudaGetSymbolAddress((void**)&woT,  g_woT);
    cudaGetSymbolAddress((void**)&w1T,  g_w1T);
    cudaGetSymbolAddress((void**)&w2T,  g_w2T);
    cudaGetSymbolAddress((void**)&qb3,  g_qkvBias);

    cudaFuncSetAttribute(attn_kernel, cudaFuncAttributeMaxDynamicSharedMemorySize, ATT_SMEM);
    cudaFuncSetAttribute((const void*)tc_gemm<2, float>,  cudaFuncAttributeMaxDynamicSharedMemorySize, GEMM_SMEM);
    cudaFuncSetAttribute((const void*)tc_gemm<3, __half>, cudaFuncAttributeMaxDynamicSharedMemorySize, GEMM_SMEM);
    cudaFuncSetAttribute((const void*)tc_gemm<4, __half>, cudaFuncAttributeMaxDynamicSharedMemorySize, GEMM_SMEM);

    cudaMemcpyAsync(out, x, (size_t)NTOK * DIM * sizeof(float), cudaMemcpyDeviceToDevice, 0);

    for (int l = 0; l < LAYERS; l++) {
        cudaMemcpyAsync(qb3 + l * QKVN,        bq + l * DIM, DIM * sizeof(float), cudaMemcpyDeviceToDevice, 0);
        cudaMemcpyAsync(qb3 + l * QKVN + 768,  bk + l * DIM, DIM * sizeof(float), cudaMemcpyDeviceToDevice, 0);
        cudaMemcpyAsync(qb3 + l * QKVN + 1536, bv + l * DIM, DIM * sizeof(float), cudaMemcpyDeviceToDevice, 0);
    }

    transpose_a<<<dim3(24, 24, 8), dim3(32, 8)>>>(Wq, Wk, Wv, Wo, qkvT, woT);
    transpose_b<<<dim3(96, 96, 4), dim3(32, 8)>>>(W1, W2, w1T, w2T);

    dim3 lnGrid(NTOK / 8), lnBlk(32, 8);
    dim3 gQKV(QKVN / TBN, NTOK / TBM);
    dim3 gD(DIM / TBN,    NTOK / TBM);
    dim3 gH(HDIM / TBN,   NTOK / TBM);

    for (int l = 0; l < LAYERS; l++) {
        long oDD = (long)l * DIM * DIM;
        long oDH = (long)l * DIM * HDIM;

        ln_kernel<<<lnGrid, lnBlk>>>(out, xn, ln1s + l*DIM, ln1b + l*DIM);

        tc_gemm<4, __half><<<gQKV, 128, GEMM_SMEM>>>(xn, qkvT + 3*oDD, qb3 + l*QKVN,
                                                     out, qkvb, DIM, QKVN, 0.125f);

        attn_kernel<<<dim3(NWIN, NHEAD), 256, ATT_SMEM>>>(qkvb, aob);

        tc_gemm<2, float><<<gD, 128, GEMM_SMEM>>>(aob, woT + oDD, bo + l*DIM,
                                                  out, out, DIM, DIM, 1.f);

        ln_kernel<<<lnGrid, lnBlk>>>(out, xn, ln2s + l*DIM, ln2b + l*DIM);

        tc_gemm<3, __half><<<gH, 128, GEMM_SMEM>>>(xn, w1T + oDH, b1 + l*HDIM,
                                                   out, hb, DIM, HDIM, 1.f);
        tc_gemm<2, float><<<gD, 128, GEMM_SMEM>>>(hb, w2T + oDH, b2 + l*DIM,
                                                  out, out, HDIM, DIM, 1.f);
    }
}

// round 11
// speedup vs baseline: 7.2488x; 1.0219x over previous
#include <cuda_runtime.h>
#include <cuda_fp16.h>
#include <math.h>
#include <stdint.h>

#define NTOK 32768
#define DIM 768
#define QKVN 2304
#define HDIM 3072
#define NHEAD 12
#define HD 64
#define NWIN 128
#define WTOK 256
#define LAYERS 2
#define EPS 1e-6f
#define LOG2E 1.4426950409f

__device__ __half g_xn  [NTOK * DIM];
__device__ __half g_qkv [(size_t)NTOK * QKVN];
__device__ __half g_ao  [NTOK * DIM];
__device__ __half g_h   [(size_t)NTOK * HDIM];
__device__ __half g_qkvT[LAYERS * 3 * DIM * DIM];
__device__ __half g_woT [LAYERS * DIM * DIM];
__device__ __half g_w1T [LAYERS * DIM * HDIM];
__device__ __half g_w2T [LAYERS * DIM * HDIM];
__device__ float  g_qkvBias[LAYERS * QKVN];

// ---------------- helpers ---------------------------------------------------
__device__ __forceinline__ uint32_t s2u(const void* p) {
    uint32_t a;
    asm("{ .reg .u64 t; cvta.to.shared.u64 t, %1; cvt.u32.u64 %0, t; }" : "=r"(a) : "l"(p));
    return a;
}
__device__ __forceinline__ float fast_exp2(float x) {
    x = fminf(fmaxf(x, -120.f), 120.f);
    float t = x + 12582912.0f;
    float r = t - 12582912.0f;
    float f = x - r;
    int   e = (int)r;
    float p = 1.0f + f * (0.69314718f + f * (0.24022651f + f * (0.05550411f
                  + f * (0.00961813f + f * 0.00133336f))));
    return __int_as_float((e + 127) << 23) * p;
}
__device__ __forceinline__ float fast_rcp(float d) {
    float r = __int_as_float(0x7EF127EA - __float_as_int(d));
    r = r * (2.0f - d * r);
    r = r * (2.0f - d * r);
    r = r * (2.0f - d * r);
    return r;
}
__device__ __forceinline__ void cp16(uint32_t s, const void* g) {
    asm volatile("cp.async.cg.shared.global [%0], [%1], 16;" :: "r"(s), "l"(g));
}
__device__ __forceinline__ void mma16(float* c, const uint32_t* a, const uint32_t* b) {
    asm volatile(
        "mma.sync.aligned.m16n8k16.row.col.f32.f16.f16.f32 "
        "{%0,%1,%2,%3}, {%4,%5,%6,%7}, {%8,%9}, {%0,%1,%2,%3};"
        : "+f"(c[0]), "+f"(c[1]), "+f"(c[2]), "+f"(c[3])
        : "r"(a[0]), "r"(a[1]), "r"(a[2]), "r"(a[3]), "r"(b[0]), "r"(b[1]));
}
__device__ __forceinline__ void ldsm4(uint32_t* r, uint32_t addr) {
    asm volatile("ldmatrix.sync.aligned.m8n8.x4.shared.b16 {%0,%1,%2,%3}, [%4];"
                 : "=r"(r[0]), "=r"(r[1]), "=r"(r[2]), "=r"(r[3]) : "r"(addr));
}
__device__ __forceinline__ uint32_t h2u(float x, float y) {
    __half2 h = __floats2half2_rn(x, y);
    return *(uint32_t*)&h;
}

// ---------------- weight transposes [K,N] -> [N,K] half ----------------------
__global__ void transpose_a(const float* __restrict__ Wq, const float* __restrict__ Wk,
                            const float* __restrict__ Wv, const float* __restrict__ Wo,
                            __half* __restrict__ qkvT, __half* __restrict__ woT) {
    __shared__ float tb[32][33];
    int w = blockIdx.z >> 1, l = blockIdx.z & 1;
    const float* src = (w == 0 ? Wq : w == 1 ? Wk : w == 2 ? Wv : Wo) + (long)l * DIM * DIM;
    __half* dst = (w < 3) ? qkvT + (long)l * 3 * DIM * DIM + (long)w * DIM * DIM
                          : woT + (long)l * DIM * DIM;
    int nb = blockIdx.x * 32, kb = blockIdx.y * 32;
    int x = threadIdx.x, y = threadIdx.y;
#pragma unroll
    for (int r = 0; r < 32; r += 8)
        tb[y + r][x] = src[(long)(kb + y + r) * DIM + nb + x];
    __syncthreads();
#pragma unroll
    for (int r = 0; r < 32; r += 8)
        dst[(long)(nb + y + r) * DIM + kb + x] = __float2half_rn(tb[x][y + r]);
}
__global__ void transpose_b(const float* __restrict__ W1, const float* __restrict__ W2,
                            __half* __restrict__ d1, __half* __restrict__ d2) {
    __shared__ float tb[32][33];
    int w = blockIdx.z >> 1, l = blockIdx.z & 1;
    const float* src; __half* dst; int K, N;
    if (w == 0) { src = W1 + (long)l * DIM * HDIM; dst = d1 + (long)l * DIM * HDIM; K = DIM;  N = HDIM; }
    else        { src = W2 + (long)l * DIM * HDIM; dst = d2 + (long)l * DIM * HDIM; K = HDIM; N = DIM; }
    if (blockIdx.x * 32 >= (unsigned)N || blockIdx.y * 32 >= (unsigned)K) return;
    int nb = blockIdx.x * 32, kb = blockIdx.y * 32;
    int x = threadIdx.x, y = threadIdx.y;
#pragma unroll
    for (int r = 0; r < 32; r += 8)
        tb[y + r][x] = src[(long)(kb + y + r) * N + nb + x];
    __syncthreads();
#pragma unroll
    for (int r = 0; r < 32; r += 8)
        dst[(long)(nb + y + r) * K + kb + x] = __float2half_rn(tb[x][y + r]);
}

// ---------------- LayerNorm: fp32 in, half out --------------------------------
__global__ void ln_kernel(const float* __restrict__ x, __half* __restrict__ y,
                          const float* __restrict__ gamma, const float* __restrict__ beta) {
    int lane = threadIdx.x;
    long row = (long)blockIdx.x * 8 + threadIdx.y;
    const float4* xr = (const float4*)(x + row * DIM);
    float4 vals[6];
    float s = 0.f, s2 = 0.f;
#pragma unroll
    for (int i = 0; i < 6; i++) {
        float4 f = xr[i * 32 + lane];
        vals[i] = f;
        s  += f.x + f.y + f.z + f.w;
        s2 += f.x*f.x + f.y*f.y + f.z*f.z + f.w*f.w;
    }
#pragma unroll
    for (int off = 16; off; off >>= 1) {
        s  += __shfl_xor_sync(0xffffffffu, s,  off);
        s2 += __shfl_xor_sync(0xffffffffu, s2, off);
    }
    float mean = s * (1.f / DIM);
    float var  = s2 * (1.f / DIM) - mean * mean;
    float inv  = rsqrtf(var + EPS);
    uint2* yr = (uint2*)(y + row * DIM);
    const float4* gg = (const float4*)gamma;
    const float4* bb = (const float4*)beta;
#pragma unroll
    for (int i = 0; i < 6; i++) {
        int c = i * 32 + lane;
        float4 g = gg[c], b = bb[c], v = vals[i];
        uint2 u;
        u.x = h2u((v.x - mean) * inv * g.x + b.x, (v.y - mean) * inv * g.y + b.y);
        u.y = h2u((v.z - mean) * inv * g.z + b.z, (v.w - mean) * inv * g.w + b.w);
        yr[c] = u;
    }
}

// ---------------- fp16 mma GEMM: 256 thr, 64x32 warp tile, 16 warps/SM --------
#define TBM 128
#define TBN 128
#define TBK 64
#define SH 72
#define TSTG (128 * SH)
#define STGH (2 * TSTG)
#define NSTG 3
#define GEMM_SMEM (NSTG * STGH * 2)   // 110592 B; 2 CTAs = 221 KB/SM

template <int EPI, typename CT>
__global__ void __launch_bounds__(256, 2)
tc_gemm(const __half* __restrict__ A, const __half* __restrict__ Wt,
        const float* __restrict__ bias, const float* __restrict__ res,
        CT* __restrict__ C, int K, int N, float alpha) {
    extern __shared__ __half smh[];
    int tid = threadIdx.x;
    int lane = tid & 31, wid = tid >> 5;
    int g = lane >> 2, t = lane & 3;
    int m0 = (wid & 1) * 64, n0 = (wid >> 1) * 32;   // 2x4 warps, 64x32 tiles
    long row0 = (long)blockIdx.y * TBM;
    int  col0 = blockIdx.x * TBN;

    float acc[4][4][4];
#pragma unroll
    for (int i = 0; i < 4; i++)
#pragma unroll
        for (int j = 0; j < 4; j++)
#pragma unroll
            for (int r = 0; r < 4; r++) acc[i][j][r] = 0.f;

    uint32_t sbase = s2u(smh);
    int iters = K / TBK;

    int aoff = (m0 + (lane & 15)) * SH + ((lane >> 4) << 3);
    int boff = (n0 + (lane & 7) + ((lane >> 4) << 3)) * SH + (((lane >> 3) & 1) << 3);

    auto produce = [&](int stage, int k0) {
        uint32_t ab = sbase + stage * STGH * 2;
        uint32_t bb = ab + TSTG * 2;
#pragma unroll
        for (int j = 0; j < 4; j++) {
            int id = tid + j * 256;
            int r = id >> 3, o = id & 7;
            cp16(ab + r * 144 + o * 16, A  + (row0 + r) * (long)K + k0 + o * 8);
            cp16(bb + r * 144 + o * 16, Wt + (col0 + r) * (long)K + k0 + o * 8);
        }
        asm volatile("cp.async.commit_group;" ::: "memory");
    };

    produce(0, 0);
    produce(1, TBK);
    int cs = 0, ps = 2;
    for (int i = 0; i < iters; i++) {
        if (i < iters - 1) {
            asm volatile("cp.async.wait_group 1;" ::: "memory");
        } else {
            asm volatile("cp.async.wait_group 0;" ::: "memory");
        }
        __syncthreads();
        if (i + 2 < iters) {
            produce(ps, (i + 2) * TBK);
            if (++ps == NSTG) ps = 0;
        }
        uint32_t ab = sbase + cs * STGH * 2;
        uint32_t bb = ab + TSTG * 2;
        if (++cs == NSTG) cs = 0;
#pragma unroll
        for (int kk = 0; kk < 4; kk++) {
            int k2 = kk * 16;
            uint32_t a[4][4], b[2][4];
#pragma unroll
            for (int mt = 0; mt < 4; mt++)
                ldsm4(a[mt], ab + (aoff + mt * 16 * SH + k2) * 2);
#pragma unroll
            for (int np = 0; np < 2; np++)
                ldsm4(b[np], bb + (boff + np * 16 * SH + k2) * 2);
#pragma unroll
            for (int mt = 0; mt < 4; mt++)
#pragma unroll
                for (int nt = 0; nt < 4; nt++)
                    mma16(acc[mt][nt], a[mt], &b[nt >> 1][(nt & 1) * 2]);
        }
    }

    float sc = (EPI == 4) ? ((col0 < 768) ? alpha : 1.f) : alpha;
#pragma unroll
    for (int mt = 0; mt < 4; mt++)
#pragma unroll
    for (int rh = 0; rh < 2; rh++) {
        long r = row0 + m0 + mt * 16 + rh * 8 + g;
        CT* cp = C + r * (long)N + col0;
        const float* rp = res + r * (long)N + col0;
#pragma unroll
        for (int nt = 0; nt < 4; nt++) {
            int c = n0 + nt * 8 + 2 * t;
            float vx = acc[mt][nt][rh * 2 + 0] + bias[col0 + c];
            float vy = acc[mt][nt][rh * 2 + 1] + bias[col0 + c + 1];
            if (EPI == 4) { vx *= sc; vy *= sc; }
            if (EPI == 2) { vx += rp[c]; vy += rp[c + 1]; }
            if (EPI == 3) {
                vx = vx * fast_rcp(1.f + fast_exp2(-2.45547238f * vx));
                vy = vy * fast_rcp(1.f + fast_exp2(-2.45547238f * vy));
            }
            if (sizeof(CT) == 2) {
                *(uint32_t*)(cp + c) = h2u(vx, vy);
            } else {
                float2 v; v.x = vx; v.y = vy;
                *(float2*)((float*)cp + c) = v;
            }
        }
    }
}

// ---------------- tensor-core window attention (round-8 proven version) -------
#define KSH 72
#define VSH 264
#define ATT_SMEM ((WTOK * KSH + HD * VSH) * 2)

__device__ __forceinline__ long attn_row(int widx, int t) {
    int b = widx & 7;
    int ij = widx >> 3;
    int wi = ij >> 2, wj = ij & 3;
    int hh = t >> 4, ww = t & 15;
    return (long)b * 4096 + (wi * 16 + hh) * 64 + (wj * 16 + ww);
}

__global__ void __launch_bounds__(256, 1)
attn_kernel(const __half* __restrict__ qkv, __half* __restrict__ ao) {
    extern __shared__ __half smh[];
    __half* ks  = smh;                 // [256][KSH]
    __half* vsT = smh + WTOK * KSH;    // [64][VSH]
    int widx = blockIdx.x, head = blockIdx.y, tid = threadIdx.x;
    int lane = tid & 31, warp = tid >> 5;
    int g = lane >> 2, t = lane & 3;

    {
        int key = tid;
        long tok = attn_row(widx, key);
        const uint4* kp4 = (const uint4*)(qkv + tok * QKVN + 768 + head * HD);
        uint4* kd = (uint4*)(ks + key * KSH);
#pragma unroll
        for (int o = 0; o < 8; o++) kd[o] = kp4[o];
        const uint4* vp4 = kp4 + 96;
#pragma unroll
        for (int o = 0; o < 8; o++) {
            uint4 u = vp4[o];
            const __half* hh = (const __half*)&u;
#pragma unroll
            for (int d2 = 0; d2 < 8; d2++)
                vsT[(o * 8 + d2) * VSH + key] = hh[d2];
        }
    }
    __syncthreads();

    uint32_t ksb = s2u(ks), vsb = s2u(vsT);
    int koff = (lane & 7) * KSH + (lane >> 3) * 8;
    int voff = ((lane & 7) + ((lane >> 4) << 3)) * VSH + (((lane >> 3) & 1) << 3);

    uint32_t qa[2][4][4];
    long tok0[2], tok1[2];
#pragma unroll
    for (int mt2 = 0; mt2 < 2; mt2++) {
        int r0 = warp * 32 + mt2 * 16 + g;
        tok0[mt2] = attn_row(widx, r0);
        tok1[mt2] = attn_row(widx, r0 + 8);
        const __half* q0 = qkv + tok0[mt2] * QKVN + head * HD;
        const __half* q1 = qkv + tok1[mt2] * QKVN + head * HD;
#pragma unroll
        for (int kk = 0; kk < 4; kk++) {
            qa[mt2][kk][0] = *(const uint32_t*)(q0 + kk * 16 + 2 * t);
            qa[mt2][kk][1] = *(const uint32_t*)(q1 + kk * 16 + 2 * t);
            qa[mt2][kk][2] = *(const uint32_t*)(q0 + kk * 16 + 2 * t + 8);
            qa[mt2][kk][3] = *(const uint32_t*)(q1 + kk * 16 + 2 * t + 8);
        }
    }

    float oacc[2][8][4];
#pragma unroll
    for (int i = 0; i < 2; i++)
#pragma unroll
        for (int j = 0; j < 8; j++)
#pragma unroll
            for (int r = 0; r < 4; r++) oacc[i][j][r] = 0.f;
    float lsum[2][2] = {{0.f, 0.f}, {0.f, 0.f}};
    uint32_t pfrag[2][2][2];

    for (int j = 0; j < 32; j++) {
        uint32_t kb[2][4];
        ldsm4(kb[0], ksb + (j * 8 * KSH + koff) * 2);
        ldsm4(kb[1], ksb + (j * 8 * KSH + koff + 32) * 2);
#pragma unroll
        for (int mt2 = 0; mt2 < 2; mt2++) {
            float s[4] = {0.f, 0.f, 0.f, 0.f};
#pragma unroll
            for (int kk = 0; kk < 4; kk++)
                mma16(s, qa[mt2][kk], &kb[kk >> 1][(kk & 1) * 2]);
            float e0 = fast_exp2(LOG2E * s[0]);
            float e1 = fast_exp2(LOG2E * s[1]);
            float e2 = fast_exp2(LOG2E * s[2]);
            float e3 = fast_exp2(LOG2E * s[3]);
            lsum[mt2][0] += e0 + e1;
            lsum[mt2][1] += e2 + e3;
            pfrag[mt2][j & 1][0] = h2u(e0, e1);
            pfrag[mt2][j & 1][1] = h2u(e2, e3);
        }
        if (j & 1) {
            int k0 = (j >> 1) * 16;
            uint32_t vb[4][4];
#pragma unroll
            for (int dp = 0; dp < 4; dp++)
                ldsm4(vb[dp], vsb + (dp * 16 * VSH + voff + k0) * 2);
#pragma unroll
            for (int mt2 = 0; mt2 < 2; mt2++) {
                uint32_t pa[4] = {pfrag[mt2][0][0], pfrag[mt2][0][1],
                                  pfrag[mt2][1][0], pfrag[mt2][1][1]};
#pragma unroll
                for (int dt = 0; dt < 8; dt++)
                    mma16(oacc[mt2][dt], pa, &vb[dt >> 1][(dt & 1) * 2]);
            }
        }
    }

#pragma unroll
    for (int mt2 = 0; mt2 < 2; mt2++)
#pragma unroll
        for (int rr = 0; rr < 2; rr++) {
            float l = lsum[mt2][rr];
            l += __shfl_xor_sync(0xffffffffu, l, 1);
            l += __shfl_xor_sync(0xffffffffu, l, 2);
            lsum[mt2][rr] = l;
        }

#pragma unroll
    for (int mt2 = 0; mt2 < 2; mt2++) {
        float i0 = fast_rcp(lsum[mt2][0]);
        float i1 = fast_rcp(lsum[mt2][1]);
        __half* o0 = ao + tok0[mt2] * DIM + head * HD;
        __half* o1 = ao + tok1[mt2] * DIM + head * HD;
#pragma unroll
        for (int dt = 0; dt < 8; dt++) {
            int c = dt * 8 + 2 * t;
            *(uint32_t*)(o0 + c) = h2u(oacc[mt2][dt][0] * i0, oacc[mt2][dt][1] * i0);
            *(uint32_t*)(o1 + c) = h2u(oacc[mt2][dt][2] * i1, oacc[mt2][dt][3] * i1);
        }
    }
}

// ---------------- host --------------------------------------------------------
extern "C" void kernel_launch(void* const* d_in, const int* in_sizes, int n_in,
                              void* d_out, int out_size) {
    const float* x    = (const float*)d_in[0];
    const float* ln1s = (const float*)d_in[1];
    const float* ln1b = (const float*)d_in[2];
    const float* Wq   = (const float*)d_in[3];
    const float* bq   = (const float*)d_in[4];
    const float* Wk   = (const float*)d_in[5];
    const float* bk   = (const float*)d_in[6];
    const float* Wv   = (const float*)d_in[7];
    const float* bv   = (const float*)d_in[8];
    const float* Wo   = (const float*)d_in[9];
    const float* bo   = (const float*)d_in[10];
    const float* ln2s = (const float*)d_in[11];
    const float* ln2b = (const float*)d_in[12];
    const float* W1   = (const float*)d_in[13];
    const float* b1   = (const float*)d_in[14];
    const float* W2   = (const float*)d_in[15];
    const float* b2   = (const float*)d_in[16];
    float* out = (float*)d_out;

    __half *xn, *qkvb, *aob, *hb, *qkvT, *woT, *w1T, *w2T;
    float* qb3;
    cudaGetSymbolAddress((void**)&xn,   g_xn);
    cudaGetSymbolAddress((void**)&qkvb, g_qkv);
    cudaGetSymbolAddress((void**)&aob,  g_ao);
    cudaGetSymbolAddress((void**)&hb,   g_h);
    cudaGetSymbolAddress((void**)&qkvT, g_qkvT);
    cudaGetSymbolAddress((void**)&woT,  g_woT);
    cudaGetSymbolAddress((void**)&w1T,  g_w1T);
    cudaGetSymbolAddress((void**)&w2T,  g_w2T);
    cudaGetSymbolAddress((void**)&qb3,  g_qkvBias);

    cudaFuncSetAttribute(attn_kernel, cudaFuncAttributeMaxDynamicSharedMemorySize, ATT_SMEM);
    cudaFuncSetAttribute((const void*)tc_gemm<2, float>,  cudaFuncAttributeMaxDynamicSharedMemorySize, GEMM_SMEM);
    cudaFuncSetAttribute((const void*)tc_gemm<3, __half>, cudaFuncAttributeMaxDynamicSharedMemorySize, GEMM_SMEM);
    cudaFuncSetAttribute((const void*)tc_gemm<4, __half>, cudaFuncAttributeMaxDynamicSharedMemorySize, GEMM_SMEM);

    cudaMemcpyAsync(out, x, (size_t)NTOK * DIM * sizeof(float), cudaMemcpyDeviceToDevice, 0);

    for (int l = 0; l < LAYERS; l++) {
        cudaMemcpyAsync(qb3 + l * QKVN,        bq + l * DIM, DIM * sizeof(float), cudaMemcpyDeviceToDevice, 0);
        cudaMemcpyAsync(qb3 + l * QKVN + 768,  bk + l * DIM, DIM * sizeof(float), cudaMemcpyDeviceToDevice, 0);
        cudaMemcpyAsync(qb3 + l * QKVN + 1536, bv + l * DIM, DIM * sizeof(float), cudaMemcpyDeviceToDevice, 0);
    }

    transpose_a<<<dim3(24, 24, 8), dim3(32, 8)>>>(Wq, Wk, Wv, Wo, qkvT, woT);
    transpose_b<<<dim3(96, 96, 4), dim3(32, 8)>>>(W1, W2, w1T, w2T);

    dim3 lnGrid(NTOK / 8), lnBlk(32, 8);
    dim3 gQKV(QKVN / TBN, NTOK / TBM);
    dim3 gD(DIM / TBN,    NTOK / TBM);
    dim3 gH(HDIM / TBN,   NTOK / TBM);

    for (int l = 0; l < LAYERS; l++) {
        long oDD = (long)l * DIM * DIM;
        long oDH = (long)l * DIM * HDIM;

        ln_kernel<<<lnGrid, lnBlk>>>(out, xn, ln1s + l*DIM, ln1b + l*DIM);

        tc_gemm<4, __half><<<gQKV, 256, GEMM_SMEM>>>(xn, qkvT + 3*oDD, qb3 + l*QKVN,
                                                     out, qkvb, DIM, QKVN, 0.125f);

        attn_kernel<<<dim3(NWIN, NHEAD), 256, ATT_SMEM>>>(qkvb, aob);

        tc_gemm<2, float><<<gD, 256, GEMM_SMEM>>>(aob, woT + oDD, bo + l*DIM,
                                                  out, out, DIM, DIM, 1.f);

        ln_kernel<<<lnGrid, lnBlk>>>(out, xn, ln2s + l*DIM, ln2b + l*DIM);

        tc_gemm<3, __half><<<gH, 256, GEMM_SMEM>>>(xn, w1T + oDH, b1 + l*HDIM,
                                                   out, hb, DIM, HDIM, 1.f);
        tc_gemm<2, float><<<gD, 256, GEMM_SMEM>>>(hb, w2T + oDH, b2 + l*DIM,
                                                  out, out, HDIM, DIM, 1.f);
    }
}

// round 12
// speedup vs baseline: 7.3645x; 1.0160x over previous
#include <cuda_runtime.h>
#include <cuda_fp16.h>
#include <math.h>
#include <stdint.h>

#define NTOK 32768
#define DIM 768
#define QKVN 2304
#define HDIM 3072
#define NHEAD 12
#define HD 64
#define NWIN 128
#define WTOK 256
#define LAYERS 2
#define EPS 1e-6f
#define LOG2E 1.4426950409f

__device__ __half g_xn  [NTOK * DIM];
__device__ __half g_qkv [(size_t)NTOK * QKVN];
__device__ __half g_ao  [NTOK * DIM];
__device__ __half g_h   [(size_t)NTOK * HDIM];
__device__ __half g_qkvT[LAYERS * 3 * DIM * DIM];
__device__ __half g_woT [LAYERS * DIM * DIM];
__device__ __half g_w1T [LAYERS * DIM * HDIM];
__device__ __half g_w2T [LAYERS * DIM * HDIM];
__device__ float  g_qkvBias[LAYERS * QKVN];

// ---------------- helpers ---------------------------------------------------
__device__ __forceinline__ uint32_t s2u(const void* p) {
    uint32_t a;
    asm("{ .reg .u64 t; cvta.to.shared.u64 t, %1; cvt.u32.u64 %0, t; }" : "=r"(a) : "l"(p));
    return a;
}
// degree-3 exp2, no clamp: valid for |x| < ~100 (args here bounded ~|x|<12)
__device__ __forceinline__ float fast_exp2(float x) {
    float t = x + 12582912.0f;
    float r = t - 12582912.0f;
    float f = x - r;
    int   e = (int)r;
    float p = 1.0f + f * (0.69314927f + f * (0.24022357f + f * 0.05550327f));
    return __int_as_float((e + 127) << 23) * p;
}
__device__ __forceinline__ float fast_rcp(float d) {
    float r = __int_as_float(0x7EF127EA - __float_as_int(d));
    r = r * (2.0f - d * r);
    r = r * (2.0f - d * r);
    return r;
}
__device__ __forceinline__ void cp16(uint32_t s, const void* g) {
    asm volatile("cp.async.cg.shared.global [%0], [%1], 16;" :: "r"(s), "l"(g));
}
__device__ __forceinline__ void mma16(float* c, const uint32_t* a, const uint32_t* b) {
    asm volatile(
        "mma.sync.aligned.m16n8k16.row.col.f32.f16.f16.f32 "
        "{%0,%1,%2,%3}, {%4,%5,%6,%7}, {%8,%9}, {%0,%1,%2,%3};"
        : "+f"(c[0]), "+f"(c[1]), "+f"(c[2]), "+f"(c[3])
        : "r"(a[0]), "r"(a[1]), "r"(a[2]), "r"(a[3]), "r"(b[0]), "r"(b[1]));
}
__device__ __forceinline__ void ldsm4(uint32_t* r, uint32_t addr) {
    asm volatile("ldmatrix.sync.aligned.m8n8.x4.shared.b16 {%0,%1,%2,%3}, [%4];"
                 : "=r"(r[0]), "=r"(r[1]), "=r"(r[2]), "=r"(r[3]) : "r"(addr));
}
__device__ __forceinline__ void ldsm4t(uint32_t* r, uint32_t addr) {
    asm volatile("ldmatrix.sync.aligned.m8n8.x4.trans.shared.b16 {%0,%1,%2,%3}, [%4];"
                 : "=r"(r[0]), "=r"(r[1]), "=r"(r[2]), "=r"(r[3]) : "r"(addr));
}
__device__ __forceinline__ uint32_t h2u(float x, float y) {
    __half2 h = __floats2half2_rn(x, y);
    return *(uint32_t*)&h;
}

// ---------------- weight transposes [K,N] -> [N,K] half ----------------------
__global__ void transpose_a(const float* __restrict__ Wq, const float* __restrict__ Wk,
                            const float* __restrict__ Wv, const float* __restrict__ Wo,
                            __half* __restrict__ qkvT, __half* __restrict__ woT) {
    __shared__ float tb[32][33];
    int w = blockIdx.z >> 1, l = blockIdx.z & 1;
    const float* src = (w == 0 ? Wq : w == 1 ? Wk : w == 2 ? Wv : Wo) + (long)l * DIM * DIM;
    __half* dst = (w < 3) ? qkvT + (long)l * 3 * DIM * DIM + (long)w * DIM * DIM
                          : woT + (long)l * DIM * DIM;
    int nb = blockIdx.x * 32, kb = blockIdx.y * 32;
    int x = threadIdx.x, y = threadIdx.y;
#pragma unroll
    for (int r = 0; r < 32; r += 8)
        tb[y + r][x] = src[(long)(kb + y + r) * DIM + nb + x];
    __syncthreads();
#pragma unroll
    for (int r = 0; r < 32; r += 8)
        dst[(long)(nb + y + r) * DIM + kb + x] = __float2half_rn(tb[x][y + r]);
}
__global__ void transpose_b(const float* __restrict__ W1, const float* __restrict__ W2,
                            __half* __restrict__ d1, __half* __restrict__ d2) {
    __shared__ float tb[32][33];
    int w = blockIdx.z >> 1, l = blockIdx.z & 1;
    const float* src; __half* dst; int K, N;
    if (w == 0) { src = W1 + (long)l * DIM * HDIM; dst = d1 + (long)l * DIM * HDIM; K = DIM;  N = HDIM; }
    else        { src = W2 + (long)l * DIM * HDIM; dst = d2 + (long)l * DIM * HDIM; K = HDIM; N = DIM; }
    if (blockIdx.x * 32 >= (unsigned)N || blockIdx.y * 32 >= (unsigned)K) return;
    int nb = blockIdx.x * 32, kb = blockIdx.y * 32;
    int x = threadIdx.x, y = threadIdx.y;
#pragma unroll
    for (int r = 0; r < 32; r += 8)
        tb[y + r][x] = src[(long)(kb + y + r) * N + nb + x];
    __syncthreads();
#pragma unroll
    for (int r = 0; r < 32; r += 8)
        dst[(long)(nb + y + r) * K + kb + x] = __float2half_rn(tb[x][y + r]);
}

// ---------------- LayerNorm: fp32 in, half out --------------------------------
__global__ void ln_kernel(const float* __restrict__ x, __half* __restrict__ y,
                          const float* __restrict__ gamma, const float* __restrict__ beta) {
    int lane = threadIdx.x;
    long row = (long)blockIdx.x * 8 + threadIdx.y;
    const float4* xr = (const float4*)(x + row * DIM);
    float4 vals[6];
    float s = 0.f, s2 = 0.f;
#pragma unroll
    for (int i = 0; i < 6; i++) {
        float4 f = xr[i * 32 + lane];
        vals[i] = f;
        s  += f.x + f.y + f.z + f.w;
        s2 += f.x*f.x + f.y*f.y + f.z*f.z + f.w*f.w;
    }
#pragma unroll
    for (int off = 16; off; off >>= 1) {
        s  += __shfl_xor_sync(0xffffffffu, s,  off);
        s2 += __shfl_xor_sync(0xffffffffu, s2, off);
    }
    float mean = s * (1.f / DIM);
    float var  = s2 * (1.f / DIM) - mean * mean;
    float inv  = rsqrtf(var + EPS);
    uint2* yr = (uint2*)(y + row * DIM);
    const float4* gg = (const float4*)gamma;
    const float4* bb = (const float4*)beta;
#pragma unroll
    for (int i = 0; i < 6; i++) {
        int c = i * 32 + lane;
        float4 g = gg[c], b = bb[c], v = vals[i];
        uint2 u;
        u.x = h2u((v.x - mean) * inv * g.x + b.x, (v.y - mean) * inv * g.y + b.y);
        u.y = h2u((v.z - mean) * inv * g.z + b.z, (v.w - mean) * inv * g.w + b.w);
        yr[c] = u;
    }
}

// ---------------- fp16 mma GEMM: 256 thr, 64x32 warp tile (r11 proven) --------
#define TBM 128
#define TBN 128
#define TBK 64
#define SH 72
#define TSTG (128 * SH)
#define STGH (2 * TSTG)
#define NSTG 3
#define GEMM_SMEM (NSTG * STGH * 2)

template <int EPI, typename CT>
__global__ void __launch_bounds__(256, 2)
tc_gemm(const __half* __restrict__ A, const __half* __restrict__ Wt,
        const float* __restrict__ bias, const float* __restrict__ res,
        CT* __restrict__ C, int K, int N, float alpha) {
    extern __shared__ __half smh[];
    int tid = threadIdx.x;
    int lane = tid & 31, wid = tid >> 5;
    int g = lane >> 2, t = lane & 3;
    int m0 = (wid & 1) * 64, n0 = (wid >> 1) * 32;
    long row0 = (long)blockIdx.y * TBM;
    int  col0 = blockIdx.x * TBN;

    float acc[4][4][4];
#pragma unroll
    for (int i = 0; i < 4; i++)
#pragma unroll
        for (int j = 0; j < 4; j++)
#pragma unroll
            for (int r = 0; r < 4; r++) acc[i][j][r] = 0.f;

    uint32_t sbase = s2u(smh);
    int iters = K / TBK;

    int aoff = (m0 + (lane & 15)) * SH + ((lane >> 4) << 3);
    int boff = (n0 + (lane & 7) + ((lane >> 4) << 3)) * SH + (((lane >> 3) & 1) << 3);

    auto produce = [&](int stage, int k0) {
        uint32_t ab = sbase + stage * STGH * 2;
        uint32_t bb = ab + TSTG * 2;
#pragma unroll
        for (int j = 0; j < 4; j++) {
            int id = tid + j * 256;
            int r = id >> 3, o = id & 7;
            cp16(ab + r * 144 + o * 16, A  + (row0 + r) * (long)K + k0 + o * 8);
            cp16(bb + r * 144 + o * 16, Wt + (col0 + r) * (long)K + k0 + o * 8);
        }
        asm volatile("cp.async.commit_group;" ::: "memory");
    };

    produce(0, 0);
    produce(1, TBK);
    int cs = 0, ps = 2;
    for (int i = 0; i < iters; i++) {
        if (i < iters - 1) {
            asm volatile("cp.async.wait_group 1;" ::: "memory");
        } else {
            asm volatile("cp.async.wait_group 0;" ::: "memory");
        }
        __syncthreads();
        if (i + 2 < iters) {
            produce(ps, (i + 2) * TBK);
            if (++ps == NSTG) ps = 0;
        }
        uint32_t ab = sbase + cs * STGH * 2;
        uint32_t bb = ab + TSTG * 2;
        if (++cs == NSTG) cs = 0;
#pragma unroll
        for (int kk = 0; kk < 4; kk++) {
            int k2 = kk * 16;
            uint32_t a[4][4], b[2][4];
#pragma unroll
            for (int mt = 0; mt < 4; mt++)
                ldsm4(a[mt], ab + (aoff + mt * 16 * SH + k2) * 2);
#pragma unroll
            for (int np = 0; np < 2; np++)
                ldsm4(b[np], bb + (boff + np * 16 * SH + k2) * 2);
#pragma unroll
            for (int mt = 0; mt < 4; mt++)
#pragma unroll
                for (int nt = 0; nt < 4; nt++)
                    mma16(acc[mt][nt], a[mt], &b[nt >> 1][(nt & 1) * 2]);
        }
    }

    float sc = (EPI == 4) ? ((col0 < 768) ? alpha : 1.f) : alpha;
#pragma unroll
    for (int mt = 0; mt < 4; mt++)
#pragma unroll
    for (int rh = 0; rh < 2; rh++) {
        long r = row0 + m0 + mt * 16 + rh * 8 + g;
        CT* cp = C + r * (long)N + col0;
        const float* rp = res + r * (long)N + col0;
#pragma unroll
        for (int nt = 0; nt < 4; nt++) {
            int c = n0 + nt * 8 + 2 * t;
            float vx = acc[mt][nt][rh * 2 + 0] + bias[col0 + c];
            float vy = acc[mt][nt][rh * 2 + 1] + bias[col0 + c + 1];
            if (EPI == 4) { vx *= sc; vy *= sc; }
            if (EPI == 2) { vx += rp[c]; vy += rp[c + 1]; }
            if (EPI == 3) {
                vx = vx * fast_rcp(1.f + fast_exp2(-2.45547238f * vx));
                vy = vy * fast_rcp(1.f + fast_exp2(-2.45547238f * vy));
            }
            if (sizeof(CT) == 2) {
                *(uint32_t*)(cp + c) = h2u(vx, vy);
            } else {
                float2 v; v.x = vx; v.y = vy;
                *(float2*)((float*)cp + c) = v;
            }
        }
    }
}

// ---------------- tensor-core window attention (ldmatrix.trans V) -------------
#define KSH 72
#define ATT_SMEM (2 * WTOK * KSH * 2)   // K rows + V rows, both [256][72] half

__device__ __forceinline__ long attn_row(int widx, int t) {
    int b = widx & 7;
    int ij = widx >> 3;
    int wi = ij >> 2, wj = ij & 3;
    int hh = t >> 4, ww = t & 15;
    return (long)b * 4096 + (wi * 16 + hh) * 64 + (wj * 16 + ww);
}

__global__ void __launch_bounds__(256, 1)
attn_kernel(const __half* __restrict__ qkv, __half* __restrict__ ao) {
    extern __shared__ __half smh[];
    __half* ks = smh;                 // [256][KSH] keys (d-contiguous)
    __half* vs = smh + WTOK * KSH;    // [256][KSH] values (d-contiguous)
    int widx = blockIdx.x, head = blockIdx.y, tid = threadIdx.x;
    int lane = tid & 31, warp = tid >> 5;
    int g = lane >> 2, t = lane & 3;

    {
        int key = tid;
        long tok = attn_row(widx, key);
        const uint4* kp4 = (const uint4*)(qkv + tok * QKVN + 768 + head * HD);
        uint4* kd = (uint4*)(ks + key * KSH);
        uint4* vd = (uint4*)(vs + key * KSH);
#pragma unroll
        for (int o = 0; o < 8; o++) kd[o] = kp4[o];
#pragma unroll
        for (int o = 0; o < 8; o++) vd[o] = kp4[96 + o];
    }
    __syncthreads();

    uint32_t ksb = s2u(ks), vsb = s2u(vs);
    int koff = (lane & 7) * KSH + (lane >> 3) * 8;
    // V trans-load: lanes 0-15 -> key rows 0..15, lanes 16-31 -> same rows, d+8
    int voff = (lane & 15) * KSH + ((lane >> 4) << 3);

    uint32_t qa[2][4][4];
    long tok0[2], tok1[2];
#pragma unroll
    for (int mt2 = 0; mt2 < 2; mt2++) {
        int r0 = warp * 32 + mt2 * 16 + g;
        tok0[mt2] = attn_row(widx, r0);
        tok1[mt2] = attn_row(widx, r0 + 8);
        const __half* q0 = qkv + tok0[mt2] * QKVN + head * HD;
        const __half* q1 = qkv + tok1[mt2] * QKVN + head * HD;
#pragma unroll
        for (int kk = 0; kk < 4; kk++) {
            qa[mt2][kk][0] = *(const uint32_t*)(q0 + kk * 16 + 2 * t);
            qa[mt2][kk][1] = *(const uint32_t*)(q1 + kk * 16 + 2 * t);
            qa[mt2][kk][2] = *(const uint32_t*)(q0 + kk * 16 + 2 * t + 8);
            qa[mt2][kk][3] = *(const uint32_t*)(q1 + kk * 16 + 2 * t + 8);
        }
    }

    float oacc[2][8][4];
#pragma unroll
    for (int i = 0; i < 2; i++)
#pragma unroll
        for (int j = 0; j < 8; j++)
#pragma unroll
            for (int r = 0; r < 4; r++) oacc[i][j][r] = 0.f;
    float lsum[2][2] = {{0.f, 0.f}, {0.f, 0.f}};
    uint32_t pfrag[2][2][2];

    for (int j = 0; j < 32; j++) {
        uint32_t kb[2][4];
        ldsm4(kb[0], ksb + (j * 8 * KSH + koff) * 2);
        ldsm4(kb[1], ksb + (j * 8 * KSH + koff + 32) * 2);
#pragma unroll
        for (int mt2 = 0; mt2 < 2; mt2++) {
            float s[4] = {0.f, 0.f, 0.f, 0.f};
#pragma unroll
            for (int kk = 0; kk < 4; kk++)
                mma16(s, qa[mt2][kk], &kb[kk >> 1][(kk & 1) * 2]);
            float e0 = fast_exp2(LOG2E * s[0]);
            float e1 = fast_exp2(LOG2E * s[1]);
            float e2 = fast_exp2(LOG2E * s[2]);
            float e3 = fast_exp2(LOG2E * s[3]);
            lsum[mt2][0] += e0 + e1;
            lsum[mt2][1] += e2 + e3;
            pfrag[mt2][j & 1][0] = h2u(e0, e1);
            pfrag[mt2][j & 1][1] = h2u(e2, e3);
        }
        if (j & 1) {
            int krow = (j >> 1) * 16;
            uint32_t vb[4][4];
#pragma unroll
            for (int dp = 0; dp < 4; dp++)
                ldsm4t(vb[dp], vsb + (krow * KSH + voff + dp * 16) * 2);
#pragma unroll
            for (int mt2 = 0; mt2 < 2; mt2++) {
                uint32_t pa[4] = {pfrag[mt2][0][0], pfrag[mt2][0][1],
                                  pfrag[mt2][1][0], pfrag[mt2][1][1]};
#pragma unroll
                for (int dt = 0; dt < 8; dt++)
                    mma16(oacc[mt2][dt], pa, &vb[dt >> 1][(dt & 1) * 2]);
            }
        }
    }

#pragma unroll
    for (int mt2 = 0; mt2 < 2; mt2++)
#pragma unroll
        for (int rr = 0; rr < 2; rr++) {
            float l = lsum[mt2][rr];
            l += __shfl_xor_sync(0xffffffffu, l, 1);
            l += __shfl_xor_sync(0xffffffffu, l, 2);
            lsum[mt2][rr] = l;
        }

#pragma unroll
    for (int mt2 = 0; mt2 < 2; mt2++) {
        float i0 = fast_rcp(lsum[mt2][0]);
        float i1 = fast_rcp(lsum[mt2][1]);
        __half* o0 = ao + tok0[mt2] * DIM + head * HD;
        __half* o1 = ao + tok1[mt2] * DIM + head * HD;
#pragma unroll
        for (int dt = 0; dt < 8; dt++) {
            int c = dt * 8 + 2 * t;
            *(uint32_t*)(o0 + c) = h2u(oacc[mt2][dt][0] * i0, oacc[mt2][dt][1] * i0);
            *(uint32_t*)(o1 + c) = h2u(oacc[mt2][dt][2] * i1, oacc[mt2][dt][3] * i1);
        }
    }
}

// ---------------- host --------------------------------------------------------
extern "C" void kernel_launch(void* const* d_in, const int* in_sizes, int n_in,
                              void* d_out, int out_size) {
    const float* x    = (const float*)d_in[0];
    const float* ln1s = (const float*)d_in[1];
    const float* ln1b = (const float*)d_in[2];
    const float* Wq   = (const float*)d_in[3];
    const float* bq   = (const float*)d_in[4];
    const float* Wk   = (const float*)d_in[5];
    const float* bk   = (const float*)d_in[6];
    const float* Wv   = (const float*)d_in[7];
    const float* bv   = (const float*)d_in[8];
    const float* Wo   = (const float*)d_in[9];
    const float* bo   = (const float*)d_in[10];
    const float* ln2s = (const float*)d_in[11];
    const float* ln2b = (const float*)d_in[12];
    const float* W1   = (const float*)d_in[13];
    const float* b1   = (const float*)d_in[14];
    const float* W2   = (const float*)d_in[15];
    const float* b2   = (const float*)d_in[16];
    float* out = (float*)d_out;

    __half *xn, *qkvb, *aob, *hb, *qkvT, *woT, *w1T, *w2T;
    float* qb3;
    cudaGetSymbolAddress((void**)&xn,   g_xn);
    cudaGetSymbolAddress((void**)&qkvb, g_qkv);
    cudaGetSymbolAddress((void**)&aob,  g_ao);
    cudaGetSymbolAddress((void**)&hb,   g_h);
    cudaGetSymbolAddress((void**)&qkvT, g_qkvT);
    cudaGetSymbolAddress((void**)&woT,  g_woT);
    cudaGetSymbolAddress((void**)&w1T,  g_w1T);
    cudaGetSymbolAddress((void**)&w2T,  g_w2T);
    cudaGetSymbolAddress((void**)&qb3,  g_qkvBias);

    cudaFuncSetAttribute(attn_kernel, cudaFuncAttributeMaxDynamicSharedMemorySize, ATT_SMEM);
    cudaFuncSetAttribute((const void*)tc_gemm<2, float>,  cudaFuncAttributeMaxDynamicSharedMemorySize, GEMM_SMEM);
    cudaFuncSetAttribute((const void*)tc_gemm<3, __half>, cudaFuncAttributeMaxDynamicSharedMemorySize, GEMM_SMEM);
    cudaFuncSetAttribute((const void*)tc_gemm<4, __half>, cudaFuncAttributeMaxDynamicSharedMemorySize, GEMM_SMEM);

    cudaMemcpyAsync(out, x, (size_t)NTOK * DIM * sizeof(float), cudaMemcpyDeviceToDevice, 0);

    for (int l = 0; l < LAYERS; l++) {
        cudaMemcpyAsync(qb3 + l * QKVN,        bq + l * DIM, DIM * sizeof(float), cudaMemcpyDeviceToDevice, 0);
        cudaMemcpyAsync(qb3 + l * QKVN + 768,  bk + l * DIM, DIM * sizeof(float), cudaMemcpyDeviceToDevice, 0);
        cudaMemcpyAsync(qb3 + l * QKVN + 1536, bv + l * DIM, DIM * sizeof(float), cudaMemcpyDeviceToDevice, 0);
    }

    transpose_a<<<dim3(24, 24, 8), dim3(32, 8)>>>(Wq, Wk, Wv, Wo, qkvT, woT);
    transpose_b<<<dim3(96, 96, 4), dim3(32, 8)>>>(W1, W2, w1T, w2T);

    dim3 lnGrid(NTOK / 8), lnBlk(32, 8);
    dim3 gQKV(QKVN / TBN, NTOK / TBM);
    dim3 gD(DIM / TBN,    NTOK / TBM);
    dim3 gH(HDIM / TBN,   NTOK / TBM);

    for (int l = 0; l < LAYERS; l++) {
        long oDD = (long)l * DIM * DIM;
        long oDH = (long)l * DIM * HDIM;

        ln_kernel<<<lnGrid, lnBlk>>>(out, xn, ln1s + l*DIM, ln1b + l*DIM);

        tc_gemm<4, __half><<<gQKV, 256, GEMM_SMEM>>>(xn, qkvT + 3*oDD, qb3 + l*QKVN,
                                                     out, qkvb, DIM, QKVN, 0.125f);

        attn_kernel<<<dim3(NWIN, NHEAD), 256, ATT_SMEM>>>(qkvb, aob);

        tc_gemm<2, float><<<gD, 256, GEMM_SMEM>>>(aob, woT + oDD, bo + l*DIM,
                                                  out, out, DIM, DIM, 1.f);

        ln_kernel<<<lnGrid, lnBlk>>>(out, xn, ln2s + l*DIM, ln2b + l*DIM);

        tc_gemm<3, __half><<<gH, 256, GEMM_SMEM>>>(xn, w1T + oDH, b1 + l*HDIM,
                                                   out, hb, DIM, HDIM, 1.f);
        tc_gemm<2, float><<<gD, 256, GEMM_SMEM>>>(hb, w2T + oDH, b2 + l*DIM,
                                                  out, out, HDIM, DIM, 1.f);
    }
}

// round 13
// speedup vs baseline: 7.3899x; 1.0035x over previous
#include <cuda_runtime.h>
#include <cuda_fp16.h>
#include <math.h>
#include <stdint.h>

#define NTOK 32768
#define DIM 768
#define QKVN 2304
#define HDIM 3072
#define NHEAD 12
#define HD 64
#define NWIN 128
#define WTOK 256
#define LAYERS 2
#define EPS 1e-6f
#define LOG2E 1.4426950409f

__device__ __half g_xn  [NTOK * DIM];
__device__ __half g_qkv [(size_t)NTOK * QKVN];
__device__ __half g_ao  [NTOK * DIM];
__device__ __half g_h   [(size_t)NTOK * HDIM];
__device__ __half g_qkvT[LAYERS * 3 * DIM * DIM];
__device__ __half g_woT [LAYERS * DIM * DIM];
__device__ __half g_w1T [LAYERS * DIM * HDIM];
__device__ __half g_w2T [LAYERS * DIM * HDIM];
__device__ float  g_qkvBias[LAYERS * QKVN];

// ---------------- helpers ---------------------------------------------------
__device__ __forceinline__ uint32_t s2u(const void* p) {
    uint32_t a;
    asm("{ .reg .u64 t; cvta.to.shared.u64 t, %1; cvt.u32.u64 %0, t; }" : "=r"(a) : "l"(p));
    return a;
}
// degree-3 exp2, no clamp: valid for |x| < ~100 (args here bounded ~|x|<12)
__device__ __forceinline__ float fast_exp2(float x) {
    float t = x + 12582912.0f;
    float r = t - 12582912.0f;
    float f = x - r;
    int   e = (int)r;
    float p = 1.0f + f * (0.69314927f + f * (0.24022357f + f * 0.05550327f));
    return __int_as_float((e + 127) << 23) * p;
}
__device__ __forceinline__ float fast_rcp(float d) {
    float r = __int_as_float(0x7EF127EA - __float_as_int(d));
    r = r * (2.0f - d * r);
    r = r * (2.0f - d * r);
    return r;
}
__device__ __forceinline__ void cp16(uint32_t s, const void* g) {
    asm volatile("cp.async.cg.shared.global [%0], [%1], 16;" :: "r"(s), "l"(g));
}
__device__ __forceinline__ void mma16(float* c, const uint32_t* a, const uint32_t* b) {
    asm volatile(
        "mma.sync.aligned.m16n8k16.row.col.f32.f16.f16.f32 "
        "{%0,%1,%2,%3}, {%4,%5,%6,%7}, {%8,%9}, {%0,%1,%2,%3};"
        : "+f"(c[0]), "+f"(c[1]), "+f"(c[2]), "+f"(c[3])
        : "r"(a[0]), "r"(a[1]), "r"(a[2]), "r"(a[3]), "r"(b[0]), "r"(b[1]));
}
__device__ __forceinline__ void ldsm4(uint32_t* r, uint32_t addr) {
    asm volatile("ldmatrix.sync.aligned.m8n8.x4.shared.b16 {%0,%1,%2,%3}, [%4];"
                 : "=r"(r[0]), "=r"(r[1]), "=r"(r[2]), "=r"(r[3]) : "r"(addr));
}
__device__ __forceinline__ void ldsm4t(uint32_t* r, uint32_t addr) {
    asm volatile("ldmatrix.sync.aligned.m8n8.x4.trans.shared.b16 {%0,%1,%2,%3}, [%4];"
                 : "=r"(r[0]), "=r"(r[1]), "=r"(r[2]), "=r"(r[3]) : "r"(addr));
}
__device__ __forceinline__ uint32_t h2u(float x, float y) {
    __half2 h = __floats2half2_rn(x, y);
    return *(uint32_t*)&h;
}

// ---------------- bias packing: [bq|bk|bv] per layer --------------------------
__global__ void pack_bias(const float* __restrict__ bq, const float* __restrict__ bk,
                          const float* __restrict__ bv, float* __restrict__ qb3) {
    int i = threadIdx.x + blockIdx.x * 256;
    if (i >= LAYERS * QKVN) return;
    int l = i / QKVN, c = i % QKVN;
    float v;
    if (c < 768)       v = bq[l * DIM + c];
    else if (c < 1536) v = bk[l * DIM + c - 768];
    else               v = bv[l * DIM + c - 1536];
    qb3[i] = v;
}

// ---------------- weight transposes [K,N] -> [N,K] half ----------------------
__global__ void transpose_a(const float* __restrict__ Wq, const float* __restrict__ Wk,
                            const float* __restrict__ Wv, const float* __restrict__ Wo,
                            __half* __restrict__ qkvT, __half* __restrict__ woT) {
    __shared__ float tb[32][33];
    int w = blockIdx.z >> 1, l = blockIdx.z & 1;
    const float* src = (w == 0 ? Wq : w == 1 ? Wk : w == 2 ? Wv : Wo) + (long)l * DIM * DIM;
    __half* dst = (w < 3) ? qkvT + (long)l * 3 * DIM * DIM + (long)w * DIM * DIM
                          : woT + (long)l * DIM * DIM;
    int nb = blockIdx.x * 32, kb = blockIdx.y * 32;
    int x = threadIdx.x, y = threadIdx.y;
#pragma unroll
    for (int r = 0; r < 32; r += 8)
        tb[y + r][x] = src[(long)(kb + y + r) * DIM + nb + x];
    __syncthreads();
#pragma unroll
    for (int r = 0; r < 32; r += 8)
        dst[(long)(nb + y + r) * DIM + kb + x] = __float2half_rn(tb[x][y + r]);
}
__global__ void transpose_b(const float* __restrict__ W1, const float* __restrict__ W2,
                            __half* __restrict__ d1, __half* __restrict__ d2) {
    __shared__ float tb[32][33];
    int w = blockIdx.z >> 1, l = blockIdx.z & 1;
    const float* src; __half* dst; int K, N;
    if (w == 0) { src = W1 + (long)l * DIM * HDIM; dst = d1 + (long)l * DIM * HDIM; K = DIM;  N = HDIM; }
    else        { src = W2 + (long)l * DIM * HDIM; dst = d2 + (long)l * DIM * HDIM; K = HDIM; N = DIM; }
    if (blockIdx.x * 32 >= (unsigned)N || blockIdx.y * 32 >= (unsigned)K) return;
    int nb = blockIdx.x * 32, kb = blockIdx.y * 32;
    int x = threadIdx.x, y = threadIdx.y;
#pragma unroll
    for (int r = 0; r < 32; r += 8)
        tb[y + r][x] = src[(long)(kb + y + r) * N + nb + x];
    __syncthreads();
#pragma unroll
    for (int r = 0; r < 32; r += 8)
        dst[(long)(nb + y + r) * K + kb + x] = __float2half_rn(tb[x][y + r]);
}

// ---------------- LayerNorm: fp32 in, half out --------------------------------
__global__ void ln_kernel(const float* __restrict__ x, __half* __restrict__ y,
                          const float* __restrict__ gamma, const float* __restrict__ beta) {
    int lane = threadIdx.x;
    long row = (long)blockIdx.x * 8 + threadIdx.y;
    const float4* xr = (const float4*)(x + row * DIM);
    float4 vals[6];
    float s = 0.f, s2 = 0.f;
#pragma unroll
    for (int i = 0; i < 6; i++) {
        float4 f = xr[i * 32 + lane];
        vals[i] = f;
        s  += f.x + f.y + f.z + f.w;
        s2 += f.x*f.x + f.y*f.y + f.z*f.z + f.w*f.w;
    }
#pragma unroll
    for (int off = 16; off; off >>= 1) {
        s  += __shfl_xor_sync(0xffffffffu, s,  off);
        s2 += __shfl_xor_sync(0xffffffffu, s2, off);
    }
    float mean = s * (1.f / DIM);
    float var  = s2 * (1.f / DIM) - mean * mean;
    float inv  = rsqrtf(var + EPS);
    uint2* yr = (uint2*)(y + row * DIM);
    const float4* gg = (const float4*)gamma;
    const float4* bb = (const float4*)beta;
#pragma unroll
    for (int i = 0; i < 6; i++) {
        int c = i * 32 + lane;
        float4 g = gg[c], b = bb[c], v = vals[i];
        uint2 u;
        u.x = h2u((v.x - mean) * inv * g.x + b.x, (v.y - mean) * inv * g.y + b.y);
        u.y = h2u((v.z - mean) * inv * g.z + b.z, (v.w - mean) * inv * g.w + b.w);
        yr[c] = u;
    }
}

// ---------------- fp16 mma GEMM: 256 thr, 64x32 warp tile (proven) ------------
#define TBM 128
#define TBN 128
#define TBK 64
#define SH 72
#define TSTG (128 * SH)
#define STGH (2 * TSTG)
#define NSTG 3
#define GEMM_SMEM (NSTG * STGH * 2)

template <int EPI, typename CT>
__global__ void __launch_bounds__(256, 2)
tc_gemm(const __half* __restrict__ A, const __half* __restrict__ Wt,
        const float* __restrict__ bias, const float* __restrict__ res,
        CT* __restrict__ C, int K, int N, float alpha) {
    extern __shared__ __half smh[];
    int tid = threadIdx.x;
    int lane = tid & 31, wid = tid >> 5;
    int g = lane >> 2, t = lane & 3;
    int m0 = (wid & 1) * 64, n0 = (wid >> 1) * 32;
    long row0 = (long)blockIdx.y * TBM;
    int  col0 = blockIdx.x * TBN;

    float acc[4][4][4];
#pragma unroll
    for (int i = 0; i < 4; i++)
#pragma unroll
        for (int j = 0; j < 4; j++)
#pragma unroll
            for (int r = 0; r < 4; r++) acc[i][j][r] = 0.f;

    uint32_t sbase = s2u(smh);
    int iters = K / TBK;

    int aoff = (m0 + (lane & 15)) * SH + ((lane >> 4) << 3);
    int boff = (n0 + (lane & 7) + ((lane >> 4) << 3)) * SH + (((lane >> 3) & 1) << 3);

    auto produce = [&](int stage, int k0) {
        uint32_t ab = sbase + stage * STGH * 2;
        uint32_t bb = ab + TSTG * 2;
#pragma unroll
        for (int j = 0; j < 4; j++) {
            int id = tid + j * 256;
            int r = id >> 3, o = id & 7;
            cp16(ab + r * 144 + o * 16, A  + (row0 + r) * (long)K + k0 + o * 8);
            cp16(bb + r * 144 + o * 16, Wt + (col0 + r) * (long)K + k0 + o * 8);
        }
        asm volatile("cp.async.commit_group;" ::: "memory");
    };

    produce(0, 0);
    produce(1, TBK);
    int cs = 0, ps = 2;
    for (int i = 0; i < iters; i++) {
        if (i < iters - 1) {
            asm volatile("cp.async.wait_group 1;" ::: "memory");
        } else {
            asm volatile("cp.async.wait_group 0;" ::: "memory");
        }
        __syncthreads();
        if (i + 2 < iters) {
            produce(ps, (i + 2) * TBK);
            if (++ps == NSTG) ps = 0;
        }
        uint32_t ab = sbase + cs * STGH * 2;
        uint32_t bb = ab + TSTG * 2;
        if (++cs == NSTG) cs = 0;
#pragma unroll
        for (int kk = 0; kk < 4; kk++) {
            int k2 = kk * 16;
            uint32_t a[4][4], b[2][4];
#pragma unroll
            for (int mt = 0; mt < 4; mt++)
                ldsm4(a[mt], ab + (aoff + mt * 16 * SH + k2) * 2);
#pragma unroll
            for (int np = 0; np < 2; np++)
                ldsm4(b[np], bb + (boff + np * 16 * SH + k2) * 2);
#pragma unroll
            for (int mt = 0; mt < 4; mt++)
#pragma unroll
                for (int nt = 0; nt < 4; nt++)
                    mma16(acc[mt][nt], a[mt], &b[nt >> 1][(nt & 1) * 2]);
        }
    }

    float sc = (EPI == 4) ? ((col0 < 768) ? alpha : 1.f) : alpha;
#pragma unroll
    for (int mt = 0; mt < 4; mt++)
#pragma unroll
    for (int rh = 0; rh < 2; rh++) {
        long r = row0 + m0 + mt * 16 + rh * 8 + g;
        CT* cp = C + r * (long)N + col0;
        const float* rp = res + r * (long)N + col0;
#pragma unroll
        for (int nt = 0; nt < 4; nt++) {
            int c = n0 + nt * 8 + 2 * t;
            float vx = acc[mt][nt][rh * 2 + 0] + bias[col0 + c];
            float vy = acc[mt][nt][rh * 2 + 1] + bias[col0 + c + 1];
            if (EPI == 4) { vx *= sc; vy *= sc; }
            if (EPI == 2) { vx += rp[c]; vy += rp[c + 1]; }
            if (EPI == 3) {
                vx = vx * fast_rcp(1.f + fast_exp2(-2.45547238f * vx));
                vy = vy * fast_rcp(1.f + fast_exp2(-2.45547238f * vy));
            }
            if (sizeof(CT) == 2) {
                *(uint32_t*)(cp + c) = h2u(vx, vy);
            } else {
                float2 v; v.x = vx; v.y = vy;
                *(float2*)((float*)cp + c) = v;
            }
        }
    }
}

// ---------------- tensor-core window attention --------------------------------
// split S-chains (2-deep) + double-buffered K fragments + trans-V
#define KSH 72
#define ATT_SMEM (2 * WTOK * KSH * 2)

__device__ __forceinline__ long attn_row(int widx, int t) {
    int b = widx & 7;
    int ij = widx >> 3;
    int wi = ij >> 2, wj = ij & 3;
    int hh = t >> 4, ww = t & 15;
    return (long)b * 4096 + (wi * 16 + hh) * 64 + (wj * 16 + ww);
}

__global__ void __launch_bounds__(256, 1)
attn_kernel(const __half* __restrict__ qkv, __half* __restrict__ ao) {
    extern __shared__ __half smh[];
    __half* ks = smh;                 // [256][KSH] keys (d-contiguous)
    __half* vs = smh + WTOK * KSH;    // [256][KSH] values (d-contiguous)
    int widx = blockIdx.x, head = blockIdx.y, tid = threadIdx.x;
    int lane = tid & 31, warp = tid >> 5;
    int g = lane >> 2, t = lane & 3;

    {
        int key = tid;
        long tok = attn_row(widx, key);
        const uint4* kp4 = (const uint4*)(qkv + tok * QKVN + 768 + head * HD);
        uint4* kd = (uint4*)(ks + key * KSH);
        uint4* vd = (uint4*)(vs + key * KSH);
#pragma unroll
        for (int o = 0; o < 8; o++) kd[o] = kp4[o];
#pragma unroll
        for (int o = 0; o < 8; o++) vd[o] = kp4[96 + o];
    }
    __syncthreads();

    uint32_t ksb = s2u(ks), vsb = s2u(vs);
    int koff = (lane & 7) * KSH + (lane >> 3) * 8;
    int voff = (lane & 15) * KSH + ((lane >> 4) << 3);

    uint32_t qa[2][4][4];
    long tok0[2], tok1[2];
#pragma unroll
    for (int mt2 = 0; mt2 < 2; mt2++) {
        int r0 = warp * 32 + mt2 * 16 + g;
        tok0[mt2] = attn_row(widx, r0);
        tok1[mt2] = attn_row(widx, r0 + 8);
        const __half* q0 = qkv + tok0[mt2] * QKVN + head * HD;
        const __half* q1 = qkv + tok1[mt2] * QKVN + head * HD;
#pragma unroll
        for (int kk = 0; kk < 4; kk++) {
            qa[mt2][kk][0] = *(const uint32_t*)(q0 + kk * 16 + 2 * t);
            qa[mt2][kk][1] = *(const uint32_t*)(q1 + kk * 16 + 2 * t);
            qa[mt2][kk][2] = *(const uint32_t*)(q0 + kk * 16 + 2 * t + 8);
            qa[mt2][kk][3] = *(const uint32_t*)(q1 + kk * 16 + 2 * t + 8);
        }
    }

    float oacc[2][8][4];
#pragma unroll
    for (int i = 0; i < 2; i++)
#pragma unroll
        for (int j = 0; j < 8; j++)
#pragma unroll
            for (int r = 0; r < 4; r++) oacc[i][j][r] = 0.f;
    float lsum[2][2] = {{0.f, 0.f}, {0.f, 0.f}};
    uint32_t pfrag[2][2][2];

    uint32_t kb[2][2][4];   // [buf][khalf][4]
    ldsm4(kb[0][0], ksb + koff * 2);
    ldsm4(kb[0][1], ksb + (koff + 32) * 2);

    for (int j = 0; j < 32; j++) {
        int cur = j & 1, nxt = cur ^ 1;
        if (j < 31) {
            ldsm4(kb[nxt][0], ksb + ((j + 1) * 8 * KSH + koff) * 2);
            ldsm4(kb[nxt][1], ksb + ((j + 1) * 8 * KSH + koff + 32) * 2);
        }
#pragma unroll
        for (int mt2 = 0; mt2 < 2; mt2++) {
            float s0[4] = {0.f, 0.f, 0.f, 0.f};
            float s1[4] = {0.f, 0.f, 0.f, 0.f};
            mma16(s0, qa[mt2][0], &kb[cur][0][0]);   // kk=0
            mma16(s1, qa[mt2][1], &kb[cur][0][2]);   // kk=1
            mma16(s0, qa[mt2][2], &kb[cur][1][0]);   // kk=2
            mma16(s1, qa[mt2][3], &kb[cur][1][2]);   // kk=3
            float e0 = fast_exp2(LOG2E * (s0[0] + s1[0]));
            float e1 = fast_exp2(LOG2E * (s0[1] + s1[1]));
            float e2 = fast_exp2(LOG2E * (s0[2] + s1[2]));
            float e3 = fast_exp2(LOG2E * (s0[3] + s1[3]));
            lsum[mt2][0] += e0 + e1;
            lsum[mt2][1] += e2 + e3;
            pfrag[mt2][cur][0] = h2u(e0, e1);
            pfrag[mt2][cur][1] = h2u(e2, e3);
        }
        if (cur) {
            int krow = (j >> 1) * 16;
            uint32_t vb[4][4];
#pragma unroll
            for (int dp = 0; dp < 4; dp++)
                ldsm4t(vb[dp], vsb + (krow * KSH + voff + dp * 16) * 2);
#pragma unroll
            for (int mt2 = 0; mt2 < 2; mt2++) {
                uint32_t pa[4] = {pfrag[mt2][0][0], pfrag[mt2][0][1],
                                  pfrag[mt2][1][0], pfrag[mt2][1][1]};
#pragma unroll
                for (int dt = 0; dt < 8; dt++)
                    mma16(oacc[mt2][dt], pa, &vb[dt >> 1][(dt & 1) * 2]);
            }
        }
    }

#pragma unroll
    for (int mt2 = 0; mt2 < 2; mt2++)
#pragma unroll
        for (int rr = 0; rr < 2; rr++) {
            float l = lsum[mt2][rr];
            l += __shfl_xor_sync(0xffffffffu, l, 1);
            l += __shfl_xor_sync(0xffffffffu, l, 2);
            lsum[mt2][rr] = l;
        }

#pragma unroll
    for (int mt2 = 0; mt2 < 2; mt2++) {
        float i0 = fast_rcp(lsum[mt2][0]);
        float i1 = fast_rcp(lsum[mt2][1]);
        __half* o0 = ao + tok0[mt2] * DIM + head * HD;
        __half* o1 = ao + tok1[mt2] * DIM + head * HD;
#pragma unroll
        for (int dt = 0; dt < 8; dt++) {
            int c = dt * 8 + 2 * t;
            *(uint32_t*)(o0 + c) = h2u(oacc[mt2][dt][0] * i0, oacc[mt2][dt][1] * i0);
            *(uint32_t*)(o1 + c) = h2u(oacc[mt2][dt][2] * i1, oacc[mt2][dt][3] * i1);
        }
    }
}

// ---------------- host --------------------------------------------------------
extern "C" void kernel_launch(void* const* d_in, const int* in_sizes, int n_in,
                              void* d_out, int out_size) {
    const float* x    = (const float*)d_in[0];
    const float* ln1s = (const float*)d_in[1];
    const float* ln1b = (const float*)d_in[2];
    const float* Wq   = (const float*)d_in[3];
    const float* bq   = (const float*)d_in[4];
    const float* Wk   = (const float*)d_in[5];
    const float* bk   = (const float*)d_in[6];
    const float* Wv   = (const float*)d_in[7];
    const float* bv   = (const float*)d_in[8];
    const float* Wo   = (const float*)d_in[9];
    const float* bo   = (const float*)d_in[10];
    const float* ln2s = (const float*)d_in[11];
    const float* ln2b = (const float*)d_in[12];
    const float* W1   = (const float*)d_in[13];
    const float* b1   = (const float*)d_in[14];
    const float* W2   = (const float*)d_in[15];
    const float* b2   = (const float*)d_in[16];
    float* out = (float*)d_out;

    __half *xn, *qkvb, *aob, *hb, *qkvT, *woT, *w1T, *w2T;
    float* qb3;
    cudaGetSymbolAddress((void**)&xn,   g_xn);
    cudaGetSymbolAddress((void**)&qkvb, g_qkv);
    cudaGetSymbolAddress((void**)&aob,  g_ao);
    cudaGetSymbolAddress((void**)&hb,   g_h);
    cudaGetSymbolAddress((void**)&qkvT, g_qkvT);
    cudaGetSymbolAddress((void**)&woT,  g_woT);
    cudaGetSymbolAddress((void**)&w1T,  g_w1T);
    cudaGetSymbolAddress((void**)&w2T,  g_w2T);
    cudaGetSymbolAddress((void**)&qb3,  g_qkvBias);

    cudaFuncSetAttribute(attn_kernel, cudaFuncAttributeMaxDynamicSharedMemorySize, ATT_SMEM);
    cudaFuncSetAttribute((const void*)tc_gemm<2, float>,  cudaFuncAttributeMaxDynamicSharedMemorySize, GEMM_SMEM);
    cudaFuncSetAttribute((const void*)tc_gemm<3, __half>, cudaFuncAttributeMaxDynamicSharedMemorySize, GEMM_SMEM);
    cudaFuncSetAttribute((const void*)tc_gemm<4, __half>, cudaFuncAttributeMaxDynamicSharedMemorySize, GEMM_SMEM);

    cudaMemcpyAsync(out, x, (size_t)NTOK * DIM * sizeof(float), cudaMemcpyDeviceToDevice, 0);

    pack_bias<<<(LAYERS * QKVN + 255) / 256, 256>>>(bq, bk, bv, qb3);
    transpose_a<<<dim3(24, 24, 8), dim3(32, 8)>>>(Wq, Wk, Wv, Wo, qkvT, woT);
    transpose_b<<<dim3(96, 96, 4), dim3(32, 8)>>>(W1, W2, w1T, w2T);

    dim3 lnGrid(NTOK / 8), lnBlk(32, 8);
    dim3 gQKV(QKVN / TBN, NTOK / TBM);
    dim3 gD(DIM / TBN,    NTOK / TBM);
    dim3 gH(HDIM / TBN,   NTOK / TBM);

    for (int l = 0; l < LAYERS; l++) {
        long oDD = (long)l * DIM * DIM;
        long oDH = (long)l * DIM * HDIM;

        ln_kernel<<<lnGrid, lnBlk>>>(out, xn, ln1s + l*DIM, ln1b + l*DIM);

        tc_gemm<4, __half><<<gQKV, 256, GEMM_SMEM>>>(xn, qkvT + 3*oDD, qb3 + l*QKVN,
                                                     out, qkvb, DIM, QKVN, 0.125f);

        attn_kernel<<<dim3(NWIN, NHEAD), 256, ATT_SMEM>>>(qkvb, aob);

        tc_gemm<2, float><<<gD, 256, GEMM_SMEM>>>(aob, woT + oDD, bo + l*DIM,
                                                  out, out, DIM, DIM, 1.f);

        ln_kernel<<<lnGrid, lnBlk>>>(out, xn, ln2s + l*DIM, ln2b + l*DIM);

        tc_gemm<3, __half><<<gH, 256, GEMM_SMEM>>>(xn, w1T + oDH, b1 + l*HDIM,
                                                   out, hb, DIM, HDIM, 1.f);
        tc_gemm<2, float><<<gD, 256, GEMM_SMEM>>>(hb, w2T + oDH, b2 + l*DIM,
                                                  out, out, HDIM, DIM, 1.f);
    }
}

// round 14
// speedup vs baseline: 7.4734x; 1.0113x over previous
#include <cuda_runtime.h>
#include <cuda_fp16.h>
#include <math.h>
#include <stdint.h>

#define NTOK 32768
#define DIM 768
#define QKVN 2304
#define HDIM 3072
#define NHEAD 12
#define HD 64
#define NWIN 128
#define WTOK 256
#define LAYERS 2
#define EPS 1e-6f
#define LOG2E 1.4426950409f

__device__ __half g_xn  [NTOK * DIM];
__device__ __half g_qkv [(size_t)NTOK * QKVN];
__device__ __half g_ao  [NTOK * DIM];
__device__ __half g_h   [(size_t)NTOK * HDIM];
__device__ __half g_qkvT[LAYERS * 3 * DIM * DIM];
__device__ __half g_woT [LAYERS * DIM * DIM];
__device__ __half g_w1T [LAYERS * DIM * HDIM];
__device__ __half g_w2T [LAYERS * DIM * HDIM];
__device__ float  g_qkvBias[LAYERS * QKVN];

// ---------------- helpers ---------------------------------------------------
__device__ __forceinline__ uint32_t s2u(const void* p) {
    uint32_t a;
    asm("{ .reg .u64 t; cvta.to.shared.u64 t, %1; cvt.u32.u64 %0, t; }" : "=r"(a) : "l"(p));
    return a;
}
// degree-3 exp2, no clamp: valid for |x| < ~100 (args here bounded ~|x|<12)
__device__ __forceinline__ float fast_exp2(float x) {
    float t = x + 12582912.0f;
    float r = t - 12582912.0f;
    float f = x - r;
    int   e = (int)r;
    float p = 1.0f + f * (0.69314927f + f * (0.24022357f + f * 0.05550327f));
    return __int_as_float((e + 127) << 23) * p;
}
__device__ __forceinline__ float fast_rcp(float d) {      // 2-Newton, err ~1e-7
    float r = __int_as_float(0x7EF127EA - __float_as_int(d));
    r = r * (2.0f - d * r);
    r = r * (2.0f - d * r);
    return r;
}
__device__ __forceinline__ float fast_rcp1(float d) {     // 1-Newton, err ~4e-4
    float r = __int_as_float(0x7EF127EA - __float_as_int(d));
    r = r * (2.0f - d * r);
    return r;
}
__device__ __forceinline__ void cp16(uint32_t s, const void* g) {
    asm volatile("cp.async.cg.shared.global [%0], [%1], 16;" :: "r"(s), "l"(g));
}
__device__ __forceinline__ void mma16(float* c, const uint32_t* a, const uint32_t* b) {
    asm volatile(
        "mma.sync.aligned.m16n8k16.row.col.f32.f16.f16.f32 "
        "{%0,%1,%2,%3}, {%4,%5,%6,%7}, {%8,%9}, {%0,%1,%2,%3};"
        : "+f"(c[0]), "+f"(c[1]), "+f"(c[2]), "+f"(c[3])
        : "r"(a[0]), "r"(a[1]), "r"(a[2]), "r"(a[3]), "r"(b[0]), "r"(b[1]));
}
__device__ __forceinline__ void ldsm4(uint32_t* r, uint32_t addr) {
    asm volatile("ldmatrix.sync.aligned.m8n8.x4.shared.b16 {%0,%1,%2,%3}, [%4];"
                 : "=r"(r[0]), "=r"(r[1]), "=r"(r[2]), "=r"(r[3]) : "r"(addr));
}
__device__ __forceinline__ void ldsm4t(uint32_t* r, uint32_t addr) {
    asm volatile("ldmatrix.sync.aligned.m8n8.x4.trans.shared.b16 {%0,%1,%2,%3}, [%4];"
                 : "=r"(r[0]), "=r"(r[1]), "=r"(r[2]), "=r"(r[3]) : "r"(addr));
}
__device__ __forceinline__ uint32_t h2u(float x, float y) {
    __half2 h = __floats2half2_rn(x, y);
    return *(uint32_t*)&h;
}

// ---------------- bias packing: [bq|bk|bv] per layer --------------------------
__global__ void pack_bias(const float* __restrict__ bq, const float* __restrict__ bk,
                          const float* __restrict__ bv, float* __restrict__ qb3) {
    int i = threadIdx.x + blockIdx.x * 256;
    if (i >= LAYERS * QKVN) return;
    int l = i / QKVN, c = i % QKVN;
    float v;
    if (c < 768)       v = bq[l * DIM + c];
    else if (c < 1536) v = bk[l * DIM + c - 768];
    else               v = bv[l * DIM + c - 1536];
    qb3[i] = v;
}

// ---------------- weight transposes [K,N] -> [N,K] half ----------------------
__global__ void transpose_a(const float* __restrict__ Wq, const float* __restrict__ Wk,
                            const float* __restrict__ Wv, const float* __restrict__ Wo,
                            __half* __restrict__ qkvT, __half* __restrict__ woT) {
    __shared__ float tb[32][33];
    int w = blockIdx.z >> 1, l = blockIdx.z & 1;
    const float* src = (w == 0 ? Wq : w == 1 ? Wk : w == 2 ? Wv : Wo) + (long)l * DIM * DIM;
    __half* dst = (w < 3) ? qkvT + (long)l * 3 * DIM * DIM + (long)w * DIM * DIM
                          : woT + (long)l * DIM * DIM;
    int nb = blockIdx.x * 32, kb = blockIdx.y * 32;
    int x = threadIdx.x, y = threadIdx.y;
#pragma unroll
    for (int r = 0; r < 32; r += 8)
        tb[y + r][x] = src[(long)(kb + y + r) * DIM + nb + x];
    __syncthreads();
#pragma unroll
    for (int r = 0; r < 32; r += 8)
        dst[(long)(nb + y + r) * DIM + kb + x] = __float2half_rn(tb[x][y + r]);
}
__global__ void transpose_b(const float* __restrict__ W1, const float* __restrict__ W2,
                            __half* __restrict__ d1, __half* __restrict__ d2) {
    __shared__ float tb[32][33];
    int w = blockIdx.z >> 1, l = blockIdx.z & 1;
    const float* src; __half* dst; int K, N;
    if (w == 0) { src = W1 + (long)l * DIM * HDIM; dst = d1 + (long)l * DIM * HDIM; K = DIM;  N = HDIM; }
    else        { src = W2 + (long)l * DIM * HDIM; dst = d2 + (long)l * DIM * HDIM; K = HDIM; N = DIM; }
    if (blockIdx.x * 32 >= (unsigned)N || blockIdx.y * 32 >= (unsigned)K) return;
    int nb = blockIdx.x * 32, kb = blockIdx.y * 32;
    int x = threadIdx.x, y = threadIdx.y;
#pragma unroll
    for (int r = 0; r < 32; r += 8)
        tb[y + r][x] = src[(long)(kb + y + r) * N + nb + x];
    __syncthreads();
#pragma unroll
    for (int r = 0; r < 32; r += 8)
        dst[(long)(nb + y + r) * K + kb + x] = __float2half_rn(tb[x][y + r]);
}

// ---------------- LayerNorm: fp32 in, half out --------------------------------
__global__ void ln_kernel(const float* __restrict__ x, __half* __restrict__ y,
                          const float* __restrict__ gamma, const float* __restrict__ beta) {
    int lane = threadIdx.x;
    long row = (long)blockIdx.x * 8 + threadIdx.y;
    const float4* xr = (const float4*)(x + row * DIM);
    float4 vals[6];
    float s = 0.f, s2 = 0.f;
#pragma unroll
    for (int i = 0; i < 6; i++) {
        float4 f = xr[i * 32 + lane];
        vals[i] = f;
        s  += f.x + f.y + f.z + f.w;
        s2 += f.x*f.x + f.y*f.y + f.z*f.z + f.w*f.w;
    }
#pragma unroll
    for (int off = 16; off; off >>= 1) {
        s  += __shfl_xor_sync(0xffffffffu, s,  off);
        s2 += __shfl_xor_sync(0xffffffffu, s2, off);
    }
    float mean = s * (1.f / DIM);
    float var  = s2 * (1.f / DIM) - mean * mean;
    float inv  = rsqrtf(var + EPS);
    uint2* yr = (uint2*)(y + row * DIM);
    const float4* gg = (const float4*)gamma;
    const float4* bb = (const float4*)beta;
#pragma unroll
    for (int i = 0; i < 6; i++) {
        int c = i * 32 + lane;
        float4 g = gg[c], b = bb[c], v = vals[i];
        uint2 u;
        u.x = h2u((v.x - mean) * inv * g.x + b.x, (v.y - mean) * inv * g.y + b.y);
        u.y = h2u((v.z - mean) * inv * g.z + b.z, (v.w - mean) * inv * g.w + b.w);
        yr[c] = u;
    }
}

// ---------------- fp16 mma GEMM: 256 thr, 64x32 warp tile (proven) ------------
#define TBM 128
#define TBN 128
#define TBK 64
#define SH 72
#define TSTG (128 * SH)
#define STGH (2 * TSTG)
#define NSTG 3
#define GEMM_SMEM (NSTG * STGH * 2)

template <int EPI, typename CT>
__global__ void __launch_bounds__(256, 2)
tc_gemm(const __half* __restrict__ A, const __half* __restrict__ Wt,
        const float* __restrict__ bias, const float* __restrict__ res,
        CT* __restrict__ C, int K, int N, float alpha) {
    extern __shared__ __half smh[];
    int tid = threadIdx.x;
    int lane = tid & 31, wid = tid >> 5;
    int g = lane >> 2, t = lane & 3;
    int m0 = (wid & 1) * 64, n0 = (wid >> 1) * 32;
    long row0 = (long)blockIdx.y * TBM;
    int  col0 = blockIdx.x * TBN;

    float acc[4][4][4];
#pragma unroll
    for (int i = 0; i < 4; i++)
#pragma unroll
        for (int j = 0; j < 4; j++)
#pragma unroll
            for (int r = 0; r < 4; r++) acc[i][j][r] = 0.f;

    uint32_t sbase = s2u(smh);
    int iters = K / TBK;

    int aoff = (m0 + (lane & 15)) * SH + ((lane >> 4) << 3);
    int boff = (n0 + (lane & 7) + ((lane >> 4) << 3)) * SH + (((lane >> 3) & 1) << 3);

    auto produce = [&](int stage, int k0) {
        uint32_t ab = sbase + stage * STGH * 2;
        uint32_t bb = ab + TSTG * 2;
#pragma unroll
        for (int j = 0; j < 4; j++) {
            int id = tid + j * 256;
            int r = id >> 3, o = id & 7;
            cp16(ab + r * 144 + o * 16, A  + (row0 + r) * (long)K + k0 + o * 8);
            cp16(bb + r * 144 + o * 16, Wt + (col0 + r) * (long)K + k0 + o * 8);
        }
        asm volatile("cp.async.commit_group;" ::: "memory");
    };

    produce(0, 0);
    produce(1, TBK);
    int cs = 0, ps = 2;
    for (int i = 0; i < iters; i++) {
        if (i < iters - 1) {
            asm volatile("cp.async.wait_group 1;" ::: "memory");
        } else {
            asm volatile("cp.async.wait_group 0;" ::: "memory");
        }
        __syncthreads();
        if (i + 2 < iters) {
            produce(ps, (i + 2) * TBK);
            if (++ps == NSTG) ps = 0;
        }
        uint32_t ab = sbase + cs * STGH * 2;
        uint32_t bb = ab + TSTG * 2;
        if (++cs == NSTG) cs = 0;
#pragma unroll
        for (int kk = 0; kk < 4; kk++) {
            int k2 = kk * 16;
            uint32_t a[4][4], b[2][4];
#pragma unroll
            for (int mt = 0; mt < 4; mt++)
                ldsm4(a[mt], ab + (aoff + mt * 16 * SH + k2) * 2);
#pragma unroll
            for (int np = 0; np < 2; np++)
                ldsm4(b[np], bb + (boff + np * 16 * SH + k2) * 2);
#pragma unroll
            for (int mt = 0; mt < 4; mt++)
#pragma unroll
                for (int nt = 0; nt < 4; nt++)
                    mma16(acc[mt][nt], a[mt], &b[nt >> 1][(nt & 1) * 2]);
        }
    }

    float sc = (EPI == 4) ? ((col0 < 768) ? alpha : 1.f) : alpha;
#pragma unroll
    for (int mt = 0; mt < 4; mt++)
#pragma unroll
    for (int rh = 0; rh < 2; rh++) {
        long r = row0 + m0 + mt * 16 + rh * 8 + g;
        CT* cp = C + r * (long)N + col0;
        const float* rp = res + r * (long)N + col0;
#pragma unroll
        for (int nt = 0; nt < 4; nt++) {
            int c = n0 + nt * 8 + 2 * t;
            float vx = acc[mt][nt][rh * 2 + 0] + bias[col0 + c];
            float vy = acc[mt][nt][rh * 2 + 1] + bias[col0 + c + 1];
            if (EPI == 4) { vx *= sc; vy *= sc; }
            if (EPI == 2) { vx += rp[c]; vy += rp[c + 1]; }
            if (EPI == 3) {
                vx = vx * fast_rcp1(1.f + fast_exp2(-2.45547238f * vx));
                vy = vy * fast_rcp1(1.f + fast_exp2(-2.45547238f * vy));
            }
            if (sizeof(CT) == 2) {
                *(uint32_t*)(cp + c) = h2u(vx, vy);
            } else {
                float2 v; v.x = vx; v.y = vy;
                *(float2*)((float*)cp + c) = v;
            }
        }
    }
}

// ---------------- tensor-core window attention --------------------------------
#define KSH 72
#define ATT_SMEM (2 * WTOK * KSH * 2)

__device__ __forceinline__ long attn_row(int widx, int t) {
    int b = widx & 7;
    int ij = widx >> 3;
    int wi = ij >> 2, wj = ij & 3;
    int hh = t >> 4, ww = t & 15;
    return (long)b * 4096 + (wi * 16 + hh) * 64 + (wj * 16 + ww);
}

__global__ void __launch_bounds__(256, 2)
attn_kernel(const __half* __restrict__ qkv, __half* __restrict__ ao) {
    extern __shared__ __half smh[];
    __half* ks = smh;
    __half* vs = smh + WTOK * KSH;
    int widx = blockIdx.x, head = blockIdx.y, tid = threadIdx.x;
    int lane = tid & 31, warp = tid >> 5;
    int g = lane >> 2, t = lane & 3;

    {
        int key = tid;
        long tok = attn_row(widx, key);
        const uint4* kp4 = (const uint4*)(qkv + tok * QKVN + 768 + head * HD);
        uint4* kd = (uint4*)(ks + key * KSH);
        uint4* vd = (uint4*)(vs + key * KSH);
#pragma unroll
        for (int o = 0; o < 8; o++) kd[o] = kp4[o];
#pragma unroll
        for (int o = 0; o < 8; o++) vd[o] = kp4[96 + o];
    }
    __syncthreads();

    uint32_t ksb = s2u(ks), vsb = s2u(vs);
    int koff = (lane & 7) * KSH + (lane >> 3) * 8;
    int voff = (lane & 15) * KSH + ((lane >> 4) << 3);

    uint32_t qa[2][4][4];
    long tok0[2], tok1[2];
#pragma unroll
    for (int mt2 = 0; mt2 < 2; mt2++) {
        int r0 = warp * 32 + mt2 * 16 + g;
        tok0[mt2] = attn_row(widx, r0);
        tok1[mt2] = attn_row(widx, r0 + 8);
        const __half* q0 = qkv + tok0[mt2] * QKVN + head * HD;
        const __half* q1 = qkv + tok1[mt2] * QKVN + head * HD;
#pragma unroll
        for (int kk = 0; kk < 4; kk++) {
            qa[mt2][kk][0] = *(const uint32_t*)(q0 + kk * 16 + 2 * t);
            qa[mt2][kk][1] = *(const uint32_t*)(q1 + kk * 16 + 2 * t);
            qa[mt2][kk][2] = *(const uint32_t*)(q0 + kk * 16 + 2 * t + 8);
            qa[mt2][kk][3] = *(const uint32_t*)(q1 + kk * 16 + 2 * t + 8);
        }
    }

    float oacc[2][8][4];
#pragma unroll
    for (int i = 0; i < 2; i++)
#pragma unroll
        for (int j = 0; j < 8; j++)
#pragma unroll
            for (int r = 0; r < 4; r++) oacc[i][j][r] = 0.f;
    float lsum[2][2] = {{0.f, 0.f}, {0.f, 0.f}};
    uint32_t pfrag[2][2][2];

    uint32_t kb[2][2][4];
    ldsm4(kb[0][0], ksb + koff * 2);
    ldsm4(kb[0][1], ksb + (koff + 32) * 2);

    for (int j = 0; j < 32; j++) {
        int cur = j & 1, nxt = cur ^ 1;
        if (j < 31) {
            ldsm4(kb[nxt][0], ksb + ((j + 1) * 8 * KSH + koff) * 2);
            ldsm4(kb[nxt][1], ksb + ((j + 1) * 8 * KSH + koff + 32) * 2);
        }
#pragma unroll
        for (int mt2 = 0; mt2 < 2; mt2++) {
            float s0[4] = {0.f, 0.f, 0.f, 0.f};
            float s1[4] = {0.f, 0.f, 0.f, 0.f};
            mma16(s0, qa[mt2][0], &kb[cur][0][0]);
            mma16(s1, qa[mt2][1], &kb[cur][0][2]);
            mma16(s0, qa[mt2][2], &kb[cur][1][0]);
            mma16(s1, qa[mt2][3], &kb[cur][1][2]);
            float e0 = fast_exp2(LOG2E * (s0[0] + s1[0]));
            float e1 = fast_exp2(LOG2E * (s0[1] + s1[1]));
            float e2 = fast_exp2(LOG2E * (s0[2] + s1[2]));
            float e3 = fast_exp2(LOG2E * (s0[3] + s1[3]));
            lsum[mt2][0] += e0 + e1;
            lsum[mt2][1] += e2 + e3;
            pfrag[mt2][cur][0] = h2u(e0, e1);
            pfrag[mt2][cur][1] = h2u(e2, e3);
        }
        if (cur) {
            int krow = (j >> 1) * 16;
            uint32_t vb[4][4];
#pragma unroll
            for (int dp = 0; dp < 4; dp++)
                ldsm4t(vb[dp], vsb + (krow * KSH + voff + dp * 16) * 2);
#pragma unroll
            for (int mt2 = 0; mt2 < 2; mt2++) {
                uint32_t pa[4] = {pfrag[mt2][0][0], pfrag[mt2][0][1],
                                  pfrag[mt2][1][0], pfrag[mt2][1][1]};
#pragma unroll
                for (int dt = 0; dt < 8; dt++)
                    mma16(oacc[mt2][dt], pa, &vb[dt >> 1][(dt & 1) * 2]);
            }
        }
    }

#pragma unroll
    for (int mt2 = 0; mt2 < 2; mt2++)
#pragma unroll
        for (int rr = 0; rr < 2; rr++) {
            float l = lsum[mt2][rr];
            l += __shfl_xor_sync(0xffffffffu, l, 1);
            l += __shfl_xor_sync(0xffffffffu, l, 2);
            lsum[mt2][rr] = l;
        }

#pragma unroll
    for (int mt2 = 0; mt2 < 2; mt2++) {
        float i0 = fast_rcp(lsum[mt2][0]);
        float i1 = fast_rcp(lsum[mt2][1]);
        __half* o0 = ao + tok0[mt2] * DIM + head * HD;
        __half* o1 = ao + tok1[mt2] * DIM + head * HD;
#pragma unroll
        for (int dt = 0; dt < 8; dt++) {
            int c = dt * 8 + 2 * t;
            *(uint32_t*)(o0 + c) = h2u(oacc[mt2][dt][0] * i0, oacc[mt2][dt][1] * i0);
            *(uint32_t*)(o1 + c) = h2u(oacc[mt2][dt][2] * i1, oacc[mt2][dt][3] * i1);
        }
    }
}

// ---------------- host --------------------------------------------------------
extern "C" void kernel_launch(void* const* d_in, const int* in_sizes, int n_in,
                              void* d_out, int out_size) {
    const float* x    = (const float*)d_in[0];
    const float* ln1s = (const float*)d_in[1];
    const float* ln1b = (const float*)d_in[2];
    const float* Wq   = (const float*)d_in[3];
    const float* bq   = (const float*)d_in[4];
    const float* Wk   = (const float*)d_in[5];
    const float* bk   = (const float*)d_in[6];
    const float* Wv   = (const float*)d_in[7];
    const float* bv   = (const float*)d_in[8];
    const float* Wo   = (const float*)d_in[9];
    const float* bo   = (const float*)d_in[10];
    const float* ln2s = (const float*)d_in[11];
    const float* ln2b = (const float*)d_in[12];
    const float* W1   = (const float*)d_in[13];
    const float* b1   = (const float*)d_in[14];
    const float* W2   = (const float*)d_in[15];
    const float* b2   = (const float*)d_in[16];
    float* out = (float*)d_out;

    __half *xn, *qkvb, *aob, *hb, *qkvT, *woT, *w1T, *w2T;
    float* qb3;
    cudaGetSymbolAddress((void**)&xn,   g_xn);
    cudaGetSymbolAddress((void**)&qkvb, g_qkv);
    cudaGetSymbolAddress((void**)&aob,  g_ao);
    cudaGetSymbolAddress((void**)&hb,   g_h);
    cudaGetSymbolAddress((void**)&qkvT, g_qkvT);
    cudaGetSymbolAddress((void**)&woT,  g_woT);
    cudaGetSymbolAddress((void**)&w1T,  g_w1T);
    cudaGetSymbolAddress((void**)&w2T,  g_w2T);
    cudaGetSymbolAddress((void**)&qb3,  g_qkvBias);

    cudaFuncSetAttribute(attn_kernel, cudaFuncAttributeMaxDynamicSharedMemorySize, ATT_SMEM);
    cudaFuncSetAttribute((const void*)tc_gemm<2, float>,  cudaFuncAttributeMaxDynamicSharedMemorySize, GEMM_SMEM);
    cudaFuncSetAttribute((const void*)tc_gemm<3, __half>, cudaFuncAttributeMaxDynamicSharedMemorySize, GEMM_SMEM);
    cudaFuncSetAttribute((const void*)tc_gemm<4, __half>, cudaFuncAttributeMaxDynamicSharedMemorySize, GEMM_SMEM);

    pack_bias<<<(LAYERS * QKVN + 255) / 256, 256>>>(bq, bk, bv, qb3);
    transpose_a<<<dim3(24, 24, 8), dim3(32, 8)>>>(Wq, Wk, Wv, Wo, qkvT, woT);
    transpose_b<<<dim3(96, 96, 4), dim3(32, 8)>>>(W1, W2, w1T, w2T);

    dim3 lnGrid(NTOK / 8), lnBlk(32, 8);
    dim3 gQKV(QKVN / TBN, NTOK / TBM);
    dim3 gD(DIM / TBN,    NTOK / TBM);
    dim3 gH(HDIM / TBN,   NTOK / TBM);

    for (int l = 0; l < LAYERS; l++) {
        long oDD = (long)l * DIM * DIM;
        long oDH = (long)l * DIM * HDIM;
        // layer 0: residual stream is the input x; out is first written by Wo-GEMM
        const float* resid = (l == 0) ? x : out;

        ln_kernel<<<lnGrid, lnBlk>>>(resid, xn, ln1s + l*DIM, ln1b + l*DIM);

        tc_gemm<4, __half><<<gQKV, 256, GEMM_SMEM>>>(xn, qkvT + 3*oDD, qb3 + l*QKVN,
                                                     resid, qkvb, DIM, QKVN, 0.125f);

        attn_kernel<<<dim3(NWIN, NHEAD), 256, ATT_SMEM>>>(qkvb, aob);

        tc_gemm<2, float><<<gD, 256, GEMM_SMEM>>>(aob, woT + oDD, bo + l*DIM,
                                                  resid, out, DIM, DIM, 1.f);

        ln_kernel<<<lnGrid, lnBlk>>>(out, xn, ln2s + l*DIM, ln2b + l*DIM);

        tc_gemm<3, __half><<<gH, 256, GEMM_SMEM>>>(xn, w1T + oDH, b1 + l*HDIM,
                                                   out, hb, DIM, HDIM, 1.f);
        tc_gemm<2, float><<<gD, 256, GEMM_SMEM>>>(hb, w2T + oDH, b2 + l*DIM,
                                                  out, out, HDIM, DIM, 1.f);
    }
}

// round 15
// speedup vs baseline: 7.4875x; 1.0019x over previous
#include <cuda_runtime.h>
#include <cuda_fp16.h>
#include <math.h>
#include <stdint.h>

#define NTOK 32768
#define DIM 768
#define QKVN 2304
#define HDIM 3072
#define NHEAD 12
#define HD 64
#define NWIN 128
#define WTOK 256
#define LAYERS 2
#define EPS 1e-6f
#define LOG2E 1.4426950409f

__device__ __half g_xn  [NTOK * DIM];
__device__ __half g_qkv [(size_t)NTOK * QKVN];
__device__ __half g_ao  [NTOK * DIM];
__device__ __half g_h   [(size_t)NTOK * HDIM];
__device__ __half g_qkvT[LAYERS * 3 * DIM * DIM];
__device__ __half g_woT [LAYERS * DIM * DIM];
__device__ __half g_w1T [LAYERS * DIM * HDIM];
__device__ __half g_w2T [LAYERS * DIM * HDIM];
__device__ float  g_qkvBias[LAYERS * QKVN];

// ---------------- helpers ---------------------------------------------------
__device__ __forceinline__ uint32_t s2u(const void* p) {
    uint32_t a;
    asm("{ .reg .u64 t; cvta.to.shared.u64 t, %1; cvt.u32.u64 %0, t; }" : "=r"(a) : "l"(p));
    return a;
}
__device__ __forceinline__ float fast_exp2(float x) {
    float t = x + 12582912.0f;
    float r = t - 12582912.0f;
    float f = x - r;
    int   e = (int)r;
    float p = 1.0f + f * (0.69314927f + f * (0.24022357f + f * 0.05550327f));
    return __int_as_float((e + 127) << 23) * p;
}
__device__ __forceinline__ float fast_rcp(float d) {      // 2-Newton
    float r = __int_as_float(0x7EF127EA - __float_as_int(d));
    r = r * (2.0f - d * r);
    r = r * (2.0f - d * r);
    return r;
}
__device__ __forceinline__ float fast_rcp1(float d) {     // 1-Newton
    float r = __int_as_float(0x7EF127EA - __float_as_int(d));
    r = r * (2.0f - d * r);
    return r;
}
__device__ __forceinline__ void cp16(uint32_t s, const void* g) {
    asm volatile("cp.async.cg.shared.global [%0], [%1], 16;" :: "r"(s), "l"(g));
}
__device__ __forceinline__ void mma16(float* c, const uint32_t* a, const uint32_t* b) {
    asm volatile(
        "mma.sync.aligned.m16n8k16.row.col.f32.f16.f16.f32 "
        "{%0,%1,%2,%3}, {%4,%5,%6,%7}, {%8,%9}, {%0,%1,%2,%3};"
        : "+f"(c[0]), "+f"(c[1]), "+f"(c[2]), "+f"(c[3])
        : "r"(a[0]), "r"(a[1]), "r"(a[2]), "r"(a[3]), "r"(b[0]), "r"(b[1]));
}
__device__ __forceinline__ void ldsm4(uint32_t* r, uint32_t addr) {
    asm volatile("ldmatrix.sync.aligned.m8n8.x4.shared.b16 {%0,%1,%2,%3}, [%4];"
                 : "=r"(r[0]), "=r"(r[1]), "=r"(r[2]), "=r"(r[3]) : "r"(addr));
}
__device__ __forceinline__ void ldsm4t(uint32_t* r, uint32_t addr) {
    asm volatile("ldmatrix.sync.aligned.m8n8.x4.trans.shared.b16 {%0,%1,%2,%3}, [%4];"
                 : "=r"(r[0]), "=r"(r[1]), "=r"(r[2]), "=r"(r[3]) : "r"(addr));
}
__device__ __forceinline__ uint32_t h2u(float x, float y) {
    __half2 h = __floats2half2_rn(x, y);
    return *(uint32_t*)&h;
}

// ---------------- bias packing: [bq|bk|bv] per layer --------------------------
__global__ void pack_bias(const float* __restrict__ bq, const float* __restrict__ bk,
                          const float* __restrict__ bv, float* __restrict__ qb3) {
    int i = threadIdx.x + blockIdx.x * 256;
    if (i >= LAYERS * QKVN) return;
    int l = i / QKVN, c = i % QKVN;
    float v;
    if (c < 768)       v = bq[l * DIM + c];
    else if (c < 1536) v = bk[l * DIM + c - 768];
    else               v = bv[l * DIM + c - 1536];
    qb3[i] = v;
}

// ---------------- weight transposes [K,N] -> [N,K] half ----------------------
__global__ void transpose_a(const float* __restrict__ Wq, const float* __restrict__ Wk,
                            const float* __restrict__ Wv, const float* __restrict__ Wo,
                            __half* __restrict__ qkvT, __half* __restrict__ woT) {
    __shared__ float tb[32][33];
    int w = blockIdx.z >> 1, l = blockIdx.z & 1;
    const float* src = (w == 0 ? Wq : w == 1 ? Wk : w == 2 ? Wv : Wo) + (long)l * DIM * DIM;
    __half* dst = (w < 3) ? qkvT + (long)l * 3 * DIM * DIM + (long)w * DIM * DIM
                          : woT + (long)l * DIM * DIM;
    int nb = blockIdx.x * 32, kb = blockIdx.y * 32;
    int x = threadIdx.x, y = threadIdx.y;
#pragma unroll
    for (int r = 0; r < 32; r += 8)
        tb[y + r][x] = src[(long)(kb + y + r) * DIM + nb + x];
    __syncthreads();
#pragma unroll
    for (int r = 0; r < 32; r += 8)
        dst[(long)(nb + y + r) * DIM + kb + x] = __float2half_rn(tb[x][y + r]);
}
__global__ void transpose_b(const float* __restrict__ W1, const float* __restrict__ W2,
                            __half* __restrict__ d1, __half* __restrict__ d2) {
    __shared__ float tb[32][33];
    int w = blockIdx.z >> 1, l = blockIdx.z & 1;
    const float* src; __half* dst; int K, N;
    if (w == 0) { src = W1 + (long)l * DIM * HDIM; dst = d1 + (long)l * DIM * HDIM; K = DIM;  N = HDIM; }
    else        { src = W2 + (long)l * DIM * HDIM; dst = d2 + (long)l * DIM * HDIM; K = HDIM; N = DIM; }
    if (blockIdx.x * 32 >= (unsigned)N || blockIdx.y * 32 >= (unsigned)K) return;
    int nb = blockIdx.x * 32, kb = blockIdx.y * 32;
    int x = threadIdx.x, y = threadIdx.y;
#pragma unroll
    for (int r = 0; r < 32; r += 8)
        tb[y + r][x] = src[(long)(kb + y + r) * N + nb + x];
    __syncthreads();
#pragma unroll
    for (int r = 0; r < 32; r += 8)
        dst[(long)(nb + y + r) * K + kb + x] = __float2half_rn(tb[x][y + r]);
}

// ---------------- LayerNorm: fp32 in, half out --------------------------------
__global__ void ln_kernel(const float* __restrict__ x, __half* __restrict__ y,
                          const float* __restrict__ gamma, const float* __restrict__ beta) {
    int lane = threadIdx.x;
    long row = (long)blockIdx.x * 8 + threadIdx.y;
    const float4* xr = (const float4*)(x + row * DIM);
    float4 vals[6];
    float s = 0.f, s2 = 0.f;
#pragma unroll
    for (int i = 0; i < 6; i++) {
        float4 f = xr[i * 32 + lane];
        vals[i] = f;
        s  += f.x + f.y + f.z + f.w;
        s2 += f.x*f.x + f.y*f.y + f.z*f.z + f.w*f.w;
    }
#pragma unroll
    for (int off = 16; off; off >>= 1) {
        s  += __shfl_xor_sync(0xffffffffu, s,  off);
        s2 += __shfl_xor_sync(0xffffffffu, s2, off);
    }
    float mean = s * (1.f / DIM);
    float var  = s2 * (1.f / DIM) - mean * mean;
    float inv  = rsqrtf(var + EPS);
    uint2* yr = (uint2*)(y + row * DIM);
    const float4* gg = (const float4*)gamma;
    const float4* bb = (const float4*)beta;
#pragma unroll
    for (int i = 0; i < 6; i++) {
        int c = i * 32 + lane;
        float4 g = gg[c], b = bb[c], v = vals[i];
        uint2 u;
        u.x = h2u((v.x - mean) * inv * g.x + b.x, (v.y - mean) * inv * g.y + b.y);
        u.y = h2u((v.z - mean) * inv * g.z + b.z, (v.w - mean) * inv * g.w + b.w);
        yr[c] = u;
    }
}

// ---------------- fp16 mma GEMM: 256 thr, 64x32 warp tile (proven) ------------
#define TBM 128
#define TBN 128
#define TBK 64
#define SH 72
#define TSTG (128 * SH)
#define STGH (2 * TSTG)
#define NSTG 3
#define GEMM_SMEM (NSTG * STGH * 2)

template <int EPI, typename CT>
__global__ void __launch_bounds__(256, 2)
tc_gemm(const __half* __restrict__ A, const __half* __restrict__ Wt,
        const float* __restrict__ bias, const float* __restrict__ res,
        CT* __restrict__ C, int K, int N, float alpha) {
    extern __shared__ __half smh[];
    int tid = threadIdx.x;
    int lane = tid & 31, wid = tid >> 5;
    int g = lane >> 2, t = lane & 3;
    int m0 = (wid & 1) * 64, n0 = (wid >> 1) * 32;
    long row0 = (long)blockIdx.y * TBM;
    int  col0 = blockIdx.x * TBN;

    float acc[4][4][4];
#pragma unroll
    for (int i = 0; i < 4; i++)
#pragma unroll
        for (int j = 0; j < 4; j++)
#pragma unroll
            for (int r = 0; r < 4; r++) acc[i][j][r] = 0.f;

    uint32_t sbase = s2u(smh);
    int iters = K / TBK;

    int aoff = (m0 + (lane & 15)) * SH + ((lane >> 4) << 3);
    int boff = (n0 + (lane & 7) + ((lane >> 4) << 3)) * SH + (((lane >> 3) & 1) << 3);

    auto produce = [&](int stage, int k0) {
        uint32_t ab = sbase + stage * STGH * 2;
        uint32_t bb = ab + TSTG * 2;
#pragma unroll
        for (int j = 0; j < 4; j++) {
            int id = tid + j * 256;
            int r = id >> 3, o = id & 7;
            cp16(ab + r * 144 + o * 16, A  + (row0 + r) * (long)K + k0 + o * 8);
            cp16(bb + r * 144 + o * 16, Wt + (col0 + r) * (long)K + k0 + o * 8);
        }
        asm volatile("cp.async.commit_group;" ::: "memory");
    };

    produce(0, 0);
    produce(1, TBK);
    int cs = 0, ps = 2;
    for (int i = 0; i < iters; i++) {
        if (i < iters - 1) {
            asm volatile("cp.async.wait_group 1;" ::: "memory");
        } else {
            asm volatile("cp.async.wait_group 0;" ::: "memory");
        }
        __syncthreads();
        if (i + 2 < iters) {
            produce(ps, (i + 2) * TBK);
            if (++ps == NSTG) ps = 0;
        }
        uint32_t ab = sbase + cs * STGH * 2;
        uint32_t bb = ab + TSTG * 2;
        if (++cs == NSTG) cs = 0;
#pragma unroll
        for (int kk = 0; kk < 4; kk++) {
            int k2 = kk * 16;
            uint32_t a[4][4], b[2][4];
#pragma unroll
            for (int mt = 0; mt < 4; mt++)
                ldsm4(a[mt], ab + (aoff + mt * 16 * SH + k2) * 2);
#pragma unroll
            for (int np = 0; np < 2; np++)
                ldsm4(b[np], bb + (boff + np * 16 * SH + k2) * 2);
#pragma unroll
            for (int mt = 0; mt < 4; mt++)
#pragma unroll
                for (int nt = 0; nt < 4; nt++)
                    mma16(acc[mt][nt], a[mt], &b[nt >> 1][(nt & 1) * 2]);
        }
    }

    float sc = (EPI == 4) ? ((col0 < 768) ? alpha : 1.f) : alpha;
#pragma unroll
    for (int mt = 0; mt < 4; mt++)
#pragma unroll
    for (int rh = 0; rh < 2; rh++) {
        long r = row0 + m0 + mt * 16 + rh * 8 + g;
        CT* cp = C + r * (long)N + col0;
        const float* rp = res + r * (long)N + col0;
#pragma unroll
        for (int nt = 0; nt < 4; nt++) {
            int c = n0 + nt * 8 + 2 * t;
            float vx = acc[mt][nt][rh * 2 + 0] + bias[col0 + c];
            float vy = acc[mt][nt][rh * 2 + 1] + bias[col0 + c + 1];
            if (EPI == 4) { vx *= sc; vy *= sc; }
            if (EPI == 2) { vx += rp[c]; vy += rp[c + 1]; }
            if (EPI == 3) {
                vx = vx * fast_rcp1(1.f + fast_exp2(-2.45547238f * vx));
                vy = vy * fast_rcp1(1.f + fast_exp2(-2.45547238f * vy));
            }
            if (sizeof(CT) == 2) {
                *(uint32_t*)(cp + c) = h2u(vx, vy);
            } else {
                float2 v; v.x = vx; v.y = vy;
                *(float2*)((float*)cp + c) = v;
            }
        }
    }
}

// ---------------- tensor-core window attention --------------------------------
#define KSH 72
#define ATT_SMEM (2 * WTOK * KSH * 2)

__device__ __forceinline__ long attn_row(int widx, int t) {
    int b = widx & 7;
    int ij = widx >> 3;
    int wi = ij >> 2, wj = ij & 3;
    int hh = t >> 4, ww = t & 15;
    return (long)b * 4096 + (wi * 16 + hh) * 64 + (wj * 16 + ww);
}

__global__ void __launch_bounds__(256, 2)
attn_kernel(const __half* __restrict__ qkv, __half* __restrict__ ao) {
    extern __shared__ __half smh[];
    __half* ks = smh;
    __half* vs = smh + WTOK * KSH;
    int widx = blockIdx.x, head = blockIdx.y, tid = threadIdx.x;
    int lane = tid & 31, warp = tid >> 5;
    int g = lane >> 2, t = lane & 3;

    // async-stage K and V rows (LSU streams these while we fetch Q below)
    {
        int key = tid;
        long tok = attn_row(widx, key);
        const char* kp = (const char*)(qkv + tok * QKVN + 768 + head * HD);
        uint32_t kd = s2u(ks + key * KSH);
        uint32_t vd = s2u(vs + key * KSH);
#pragma unroll
        for (int o = 0; o < 8; o++) cp16(kd + o * 16, kp + o * 16);
#pragma unroll
        for (int o = 0; o < 8; o++) cp16(vd + o * 16, kp + 1536 + o * 16);
        asm volatile("cp.async.commit_group;" ::: "memory");
    }

    // Q fragments straight from gmem (overlaps with cp.async staging)
    uint32_t qa[2][4][4];
    long tok0[2], tok1[2];
#pragma unroll
    for (int mt2 = 0; mt2 < 2; mt2++) {
        int r0 = warp * 32 + mt2 * 16 + g;
        tok0[mt2] = attn_row(widx, r0);
        tok1[mt2] = attn_row(widx, r0 + 8);
        const __half* q0 = qkv + tok0[mt2] * QKVN + head * HD;
        const __half* q1 = qkv + tok1[mt2] * QKVN + head * HD;
#pragma unroll
        for (int kk = 0; kk < 4; kk++) {
            qa[mt2][kk][0] = *(const uint32_t*)(q0 + kk * 16 + 2 * t);
            qa[mt2][kk][1] = *(const uint32_t*)(q1 + kk * 16 + 2 * t);
            qa[mt2][kk][2] = *(const uint32_t*)(q0 + kk * 16 + 2 * t + 8);
            qa[mt2][kk][3] = *(const uint32_t*)(q1 + kk * 16 + 2 * t + 8);
        }
    }

    asm volatile("cp.async.wait_group 0;" ::: "memory");
    __syncthreads();

    uint32_t ksb = s2u(ks) + ((lane & 7) * KSH + (lane >> 3) * 8) * 2;
    uint32_t vsb = s2u(vs) + ((lane & 15) * KSH + ((lane >> 4) << 3)) * 2;

    float oacc[2][8][4];
#pragma unroll
    for (int i = 0; i < 2; i++)
#pragma unroll
        for (int j = 0; j < 8; j++)
#pragma unroll
            for (int r = 0; r < 4; r++) oacc[i][j][r] = 0.f;
    float lsum[2][2] = {{0.f, 0.f}, {0.f, 0.f}};
    uint32_t pfrag[2][2][2];

    uint32_t kb[2][2][4];
    ldsm4(kb[0][0], ksb);
    ldsm4(kb[0][1], ksb + 64);

    for (int j = 0; j < 32; j++) {
        int cur = j & 1, nxt = cur ^ 1;
        if (j < 31) {
            uint32_t nb = ksb + (j + 1) * 8 * KSH * 2;
            ldsm4(kb[nxt][0], nb);
            ldsm4(kb[nxt][1], nb + 64);
        }
#pragma unroll
        for (int mt2 = 0; mt2 < 2; mt2++) {
            float s0[4] = {0.f, 0.f, 0.f, 0.f};
            float s1[4] = {0.f, 0.f, 0.f, 0.f};
            mma16(s0, qa[mt2][0], &kb[cur][0][0]);
            mma16(s1, qa[mt2][1], &kb[cur][0][2]);
            mma16(s0, qa[mt2][2], &kb[cur][1][0]);
            mma16(s1, qa[mt2][3], &kb[cur][1][2]);
            float e0 = fast_exp2(LOG2E * (s0[0] + s1[0]));
            float e1 = fast_exp2(LOG2E * (s0[1] + s1[1]));
            float e2 = fast_exp2(LOG2E * (s0[2] + s1[2]));
            float e3 = fast_exp2(LOG2E * (s0[3] + s1[3]));
            lsum[mt2][0] += e0 + e1;
            lsum[mt2][1] += e2 + e3;
            pfrag[mt2][cur][0] = h2u(e0, e1);
            pfrag[mt2][cur][1] = h2u(e2, e3);
        }
        if (cur) {
            uint32_t vrow = vsb + (j >> 1) * 16 * KSH * 2;
            uint32_t vb[4][4];
#pragma unroll
            for (int dp = 0; dp < 4; dp++)
                ldsm4t(vb[dp], vrow + dp * 32);
#pragma unroll
            for (int mt2 = 0; mt2 < 2; mt2++) {
                uint32_t pa[4] = {pfrag[mt2][0][0], pfrag[mt2][0][1],
                                  pfrag[mt2][1][0], pfrag[mt2][1][1]};
#pragma unroll
                for (int dt = 0; dt < 8; dt++)
                    mma16(oacc[mt2][dt], pa, &vb[dt >> 1][(dt & 1) * 2]);
            }
        }
    }

#pragma unroll
    for (int mt2 = 0; mt2 < 2; mt2++)
#pragma unroll
        for (int rr = 0; rr < 2; rr++) {
            float l = lsum[mt2][rr];
            l += __shfl_xor_sync(0xffffffffu, l, 1);
            l += __shfl_xor_sync(0xffffffffu, l, 2);
            lsum[mt2][rr] = l;
        }

#pragma unroll
    for (int mt2 = 0; mt2 < 2; mt2++) {
        float i0 = fast_rcp(lsum[mt2][0]);
        float i1 = fast_rcp(lsum[mt2][1]);
        __half* o0 = ao + tok0[mt2] * DIM + head * HD;
        __half* o1 = ao + tok1[mt2] * DIM + head * HD;
#pragma unroll
        for (int dt = 0; dt < 8; dt++) {
            int c = dt * 8 + 2 * t;
            *(uint32_t*)(o0 + c) = h2u(oacc[mt2][dt][0] * i0, oacc[mt2][dt][1] * i0);
            *(uint32_t*)(o1 + c) = h2u(oacc[mt2][dt][2] * i1, oacc[mt2][dt][3] * i1);
        }
    }
}

// ---------------- host --------------------------------------------------------
extern "C" void kernel_launch(void* const* d_in, const int* in_sizes, int n_in,
                              void* d_out, int out_size) {
    const float* x    = (const float*)d_in[0];
    const float* ln1s = (const float*)d_in[1];
    const float* ln1b = (const float*)d_in[2];
    const float* Wq   = (const float*)d_in[3];
    const float* bq   = (const float*)d_in[4];
    const float* Wk   = (const float*)d_in[5];
    const float* bk   = (const float*)d_in[6];
    const float* Wv   = (const float*)d_in[7];
    const float* bv   = (const float*)d_in[8];
    const float* Wo   = (const float*)d_in[9];
    const float* bo   = (const float*)d_in[10];
    const float* ln2s = (const float*)d_in[11];
    const float* ln2b = (const float*)d_in[12];
    const float* W1   = (const float*)d_in[13];
    const float* b1   = (const float*)d_in[14];
    const float* W2   = (const float*)d_in[15];
    const float* b2   = (const float*)d_in[16];
    float* out = (float*)d_out;

    __half *xn, *qkvb, *aob, *hb, *qkvT, *woT, *w1T, *w2T;
    float* qb3;
    cudaGetSymbolAddress((void**)&xn,   g_xn);
    cudaGetSymbolAddress((void**)&qkvb, g_qkv);
    cudaGetSymbolAddress((void**)&aob,  g_ao);
    cudaGetSymbolAddress((void**)&hb,   g_h);
    cudaGetSymbolAddress((void**)&qkvT, g_qkvT);
    cudaGetSymbolAddress((void**)&woT,  g_woT);
    cudaGetSymbolAddress((void**)&w1T,  g_w1T);
    cudaGetSymbolAddress((void**)&w2T,  g_w2T);
    cudaGetSymbolAddress((void**)&qb3,  g_qkvBias);

    cudaFuncSetAttribute(attn_kernel, cudaFuncAttributeMaxDynamicSharedMemorySize, ATT_SMEM);
    cudaFuncSetAttribute((const void*)tc_gemm<2, float>,  cudaFuncAttributeMaxDynamicSharedMemorySize, GEMM_SMEM);
    cudaFuncSetAttribute((const void*)tc_gemm<3, __half>, cudaFuncAttributeMaxDynamicSharedMemorySize, GEMM_SMEM);
    cudaFuncSetAttribute((const void*)tc_gemm<4, __half>, cudaFuncAttributeMaxDynamicSharedMemorySize, GEMM_SMEM);

    pack_bias<<<(LAYERS * QKVN + 255) / 256, 256>>>(bq, bk, bv, qb3);
    transpose_a<<<dim3(24, 24, 8), dim3(32, 8)>>>(Wq, Wk, Wv, Wo, qkvT, woT);
    transpose_b<<<dim3(96, 96, 4), dim3(32, 8)>>>(W1, W2, w1T, w2T);

    dim3 lnGrid(NTOK / 8), lnBlk(32, 8);
    dim3 gQKV(QKVN / TBN, NTOK / TBM);
    dim3 gD(DIM / TBN,    NTOK / TBM);
    dim3 gH(HDIM / TBN,   NTOK / TBM);

    for (int l = 0; l < LAYERS; l++) {
        long oDD = (long)l * DIM * DIM;
        long oDH = (long)l * DIM * HDIM;
        const float* resid = (l == 0) ? x : out;

        ln_kernel<<<lnGrid, lnBlk>>>(resid, xn, ln1s + l*DIM, ln1b + l*DIM);

        tc_gemm<4, __half><<<gQKV, 256, GEMM_SMEM>>>(xn, qkvT + 3*oDD, qb3 + l*QKVN,
                                                     resid, qkvb, DIM, QKVN, 0.125f);

        attn_kernel<<<dim3(NWIN, NHEAD), 256, ATT_SMEM>>>(qkvb, aob);

        tc_gemm<2, float><<<gD, 256, GEMM_SMEM>>>(aob, woT + oDD, bo + l*DIM,
                                                  resid, out, DIM, DIM, 1.f);

        ln_kernel<<<lnGrid, lnBlk>>>(out, xn, ln2s + l*DIM, ln2b + l*DIM);

        tc_gemm<3, __half><<<gH, 256, GEMM_SMEM>>>(xn, w1T + oDH, b1 + l*HDIM,
                                                   out, hb, DIM, HDIM, 1.f);
        tc_gemm<2, float><<<gD, 256, GEMM_SMEM>>>(hb, w2T + oDH, b2 + l*DIM,
                                                  out, out, HDIM, DIM, 1.f);
    }
}

// round 16
// speedup vs baseline: 7.5791x; 1.0122x over previous
#include <cuda_runtime.h>
#include <cuda_fp16.h>
#include <math.h>
#include <stdint.h>

#define NTOK 32768
#define DIM 768
#define QKVN 2304
#define HDIM 3072
#define NHEAD 12
#define HD 64
#define NWIN 128
#define WTOK 256
#define LAYERS 2
#define EPS 1e-6f
#define LOG2E 1.4426950409f

__device__ __half g_xn  [NTOK * DIM];
__device__ __half g_qkv [(size_t)NTOK * QKVN];
__device__ __half g_ao  [NTOK * DIM];
__device__ __half g_h   [(size_t)NTOK * HDIM];
__device__ __half g_qkvT[LAYERS * 3 * DIM * DIM];
__device__ __half g_woT [LAYERS * DIM * DIM];
__device__ __half g_w1T [LAYERS * DIM * HDIM];
__device__ __half g_w2T [LAYERS * DIM * HDIM];
__device__ float  g_qkvBias[LAYERS * QKVN];

// ---------------- helpers ---------------------------------------------------
__device__ __forceinline__ uint32_t s2u(const void* p) {
    uint32_t a;
    asm("{ .reg .u64 t; cvta.to.shared.u64 t, %1; cvt.u32.u64 %0, t; }" : "=r"(a) : "l"(p));
    return a;
}
__device__ __forceinline__ float fast_exp2(float x) {
    float t = x + 12582912.0f;
    float r = t - 12582912.0f;
    float f = x - r;
    int   e = (int)r;
    float p = 1.0f + f * (0.69314927f + f * (0.24022357f + f * 0.05550327f));
    return __int_as_float((e + 127) << 23) * p;
}
__device__ __forceinline__ float fast_rcp(float d) {      // 2-Newton
    float r = __int_as_float(0x7EF127EA - __float_as_int(d));
    r = r * (2.0f - d * r);
    r = r * (2.0f - d * r);
    return r;
}
__device__ __forceinline__ float fast_rcp1(float d) {     // 1-Newton
    float r = __int_as_float(0x7EF127EA - __float_as_int(d));
    r = r * (2.0f - d * r);
    return r;
}
__device__ __forceinline__ void cp16(uint32_t s, const void* g) {
    asm volatile("cp.async.cg.shared.global [%0], [%1], 16;" :: "r"(s), "l"(g));
}
__device__ __forceinline__ void mma16(float* c, const uint32_t* a, const uint32_t* b) {
    asm volatile(
        "mma.sync.aligned.m16n8k16.row.col.f32.f16.f16.f32 "
        "{%0,%1,%2,%3}, {%4,%5,%6,%7}, {%8,%9}, {%0,%1,%2,%3};"
        : "+f"(c[0]), "+f"(c[1]), "+f"(c[2]), "+f"(c[3])
        : "r"(a[0]), "r"(a[1]), "r"(a[2]), "r"(a[3]), "r"(b[0]), "r"(b[1]));
}
__device__ __forceinline__ void ldsm4(uint32_t* r, uint32_t addr) {
    asm volatile("ldmatrix.sync.aligned.m8n8.x4.shared.b16 {%0,%1,%2,%3}, [%4];"
                 : "=r"(r[0]), "=r"(r[1]), "=r"(r[2]), "=r"(r[3]) : "r"(addr));
}
__device__ __forceinline__ void ldsm4t(uint32_t* r, uint32_t addr) {
    asm volatile("ldmatrix.sync.aligned.m8n8.x4.trans.shared.b16 {%0,%1,%2,%3}, [%4];"
                 : "=r"(r[0]), "=r"(r[1]), "=r"(r[2]), "=r"(r[3]) : "r"(addr));
}
__device__ __forceinline__ uint32_t h2u(float x, float y) {
    __half2 h = __floats2half2_rn(x, y);
    return *(uint32_t*)&h;
}

// ---------------- bias packing: [bq|bk|bv] per layer --------------------------
__global__ void pack_bias(const float* __restrict__ bq, const float* __restrict__ bk,
                          const float* __restrict__ bv, float* __restrict__ qb3) {
    int i = threadIdx.x + blockIdx.x * 256;
    if (i >= LAYERS * QKVN) return;
    int l = i / QKVN, c = i % QKVN;
    float v;
    if (c < 768)       v = bq[l * DIM + c];
    else if (c < 1536) v = bk[l * DIM + c - 768];
    else               v = bv[l * DIM + c - 1536];
    qb3[i] = v;
}

// ---------------- weight transposes [K,N] -> [N,K] half ----------------------
__global__ void transpose_a(const float* __restrict__ Wq, const float* __restrict__ Wk,
                            const float* __restrict__ Wv, const float* __restrict__ Wo,
                            __half* __restrict__ qkvT, __half* __restrict__ woT) {
    __shared__ float tb[32][33];
    int w = blockIdx.z >> 1, l = blockIdx.z & 1;
    const float* src = (w == 0 ? Wq : w == 1 ? Wk : w == 2 ? Wv : Wo) + (long)l * DIM * DIM;
    __half* dst = (w < 3) ? qkvT + (long)l * 3 * DIM * DIM + (long)w * DIM * DIM
                          : woT + (long)l * DIM * DIM;
    int nb = blockIdx.x * 32, kb = blockIdx.y * 32;
    int x = threadIdx.x, y = threadIdx.y;
#pragma unroll
    for (int r = 0; r < 32; r += 8)
        tb[y + r][x] = src[(long)(kb + y + r) * DIM + nb + x];
    __syncthreads();
#pragma unroll
    for (int r = 0; r < 32; r += 8)
        dst[(long)(nb + y + r) * DIM + kb + x] = __float2half_rn(tb[x][y + r]);
}
__global__ void transpose_b(const float* __restrict__ W1, const float* __restrict__ W2,
                            __half* __restrict__ d1, __half* __restrict__ d2) {
    __shared__ float tb[32][33];
    int w = blockIdx.z >> 1, l = blockIdx.z & 1;
    const float* src; __half* dst; int K, N;
    if (w == 0) { src = W1 + (long)l * DIM * HDIM; dst = d1 + (long)l * DIM * HDIM; K = DIM;  N = HDIM; }
    else        { src = W2 + (long)l * DIM * HDIM; dst = d2 + (long)l * DIM * HDIM; K = HDIM; N = DIM; }
    if (blockIdx.x * 32 >= (unsigned)N || blockIdx.y * 32 >= (unsigned)K) return;
    int nb = blockIdx.x * 32, kb = blockIdx.y * 32;
    int x = threadIdx.x, y = threadIdx.y;
#pragma unroll
    for (int r = 0; r < 32; r += 8)
        tb[y + r][x] = src[(long)(kb + y + r) * N + nb + x];
    __syncthreads();
#pragma unroll
    for (int r = 0; r < 32; r += 8)
        dst[(long)(nb + y + r) * K + kb + x] = __float2half_rn(tb[x][y + r]);
}

// ---------------- LayerNorm: fp32 in, half out --------------------------------
__global__ void ln_kernel(const float* __restrict__ x, __half* __restrict__ y,
                          const float* __restrict__ gamma, const float* __restrict__ beta) {
    int lane = threadIdx.x;
    long row = (long)blockIdx.x * 8 + threadIdx.y;
    const float4* xr = (const float4*)(x + row * DIM);
    float4 vals[6];
    float s = 0.f, s2 = 0.f;
#pragma unroll
    for (int i = 0; i < 6; i++) {
        float4 f = xr[i * 32 + lane];
        vals[i] = f;
        s  += f.x + f.y + f.z + f.w;
        s2 += f.x*f.x + f.y*f.y + f.z*f.z + f.w*f.w;
    }
#pragma unroll
    for (int off = 16; off; off >>= 1) {
        s  += __shfl_xor_sync(0xffffffffu, s,  off);
        s2 += __shfl_xor_sync(0xffffffffu, s2, off);
    }
    float mean = s * (1.f / DIM);
    float var  = s2 * (1.f / DIM) - mean * mean;
    float inv  = rsqrtf(var + EPS);
    uint2* yr = (uint2*)(y + row * DIM);
    const float4* gg = (const float4*)gamma;
    const float4* bb = (const float4*)beta;
#pragma unroll
    for (int i = 0; i < 6; i++) {
        int c = i * 32 + lane;
        float4 g = gg[c], b = bb[c], v = vals[i];
        uint2 u;
        u.x = h2u((v.x - mean) * inv * g.x + b.x, (v.y - mean) * inv * g.y + b.y);
        u.y = h2u((v.z - mean) * inv * g.z + b.z, (v.w - mean) * inv * g.w + b.w);
        yr[c] = u;
    }
}

// ---------------- fp16 mma GEMM: 256 thr, 64x32 warp tile (proven) ------------
#define TBM 128
#define TBN 128
#define TBK 64
#define SH 72
#define TSTG (128 * SH)
#define STGH (2 * TSTG)
#define NSTG 3
#define GEMM_SMEM (NSTG * STGH * 2)

template <int EPI, typename CT>
__global__ void __launch_bounds__(256, 2)
tc_gemm(const __half* __restrict__ A, const __half* __restrict__ Wt,
        const float* __restrict__ bias, const float* __restrict__ res,
        CT* __restrict__ C, int K, int N, float alpha) {
    extern __shared__ __half smh[];
    int tid = threadIdx.x;
    int lane = tid & 31, wid = tid >> 5;
    int g = lane >> 2, t = lane & 3;
    int m0 = (wid & 1) * 64, n0 = (wid >> 1) * 32;
    long row0 = (long)blockIdx.y * TBM;
    int  col0 = blockIdx.x * TBN;

    float acc[4][4][4];
#pragma unroll
    for (int i = 0; i < 4; i++)
#pragma unroll
        for (int j = 0; j < 4; j++)
#pragma unroll
            for (int r = 0; r < 4; r++) acc[i][j][r] = 0.f;

    uint32_t sbase = s2u(smh);
    int iters = K / TBK;

    int aoff = (m0 + (lane & 15)) * SH + ((lane >> 4) << 3);
    int boff = (n0 + (lane & 7) + ((lane >> 4) << 3)) * SH + (((lane >> 3) & 1) << 3);

    auto produce = [&](int stage, int k0) {
        uint32_t ab = sbase + stage * STGH * 2;
        uint32_t bb = ab + TSTG * 2;
#pragma unroll
        for (int j = 0; j < 4; j++) {
            int id = tid + j * 256;
            int r = id >> 3, o = id & 7;
            cp16(ab + r * 144 + o * 16, A  + (row0 + r) * (long)K + k0 + o * 8);
            cp16(bb + r * 144 + o * 16, Wt + (col0 + r) * (long)K + k0 + o * 8);
        }
        asm volatile("cp.async.commit_group;" ::: "memory");
    };

    produce(0, 0);
    produce(1, TBK);
    int cs = 0, ps = 2;
    for (int i = 0; i < iters; i++) {
        if (i < iters - 1) {
            asm volatile("cp.async.wait_group 1;" ::: "memory");
        } else {
            asm volatile("cp.async.wait_group 0;" ::: "memory");
        }
        __syncthreads();
        if (i + 2 < iters) {
            produce(ps, (i + 2) * TBK);
            if (++ps == NSTG) ps = 0;
        }
        uint32_t ab = sbase + cs * STGH * 2;
        uint32_t bb = ab + TSTG * 2;
        if (++cs == NSTG) cs = 0;
#pragma unroll
        for (int kk = 0; kk < 4; kk++) {
            int k2 = kk * 16;
            uint32_t a[4][4], b[2][4];
#pragma unroll
            for (int mt = 0; mt < 4; mt++)
                ldsm4(a[mt], ab + (aoff + mt * 16 * SH + k2) * 2);
#pragma unroll
            for (int np = 0; np < 2; np++)
                ldsm4(b[np], bb + (boff + np * 16 * SH + k2) * 2);
#pragma unroll
            for (int mt = 0; mt < 4; mt++)
#pragma unroll
                for (int nt = 0; nt < 4; nt++)
                    mma16(acc[mt][nt], a[mt], &b[nt >> 1][(nt & 1) * 2]);
        }
    }

    float sc = (EPI == 4) ? ((col0 < 768) ? alpha : 1.f) : alpha;
#pragma unroll
    for (int mt = 0; mt < 4; mt++)
#pragma unroll
    for (int rh = 0; rh < 2; rh++) {
        long r = row0 + m0 + mt * 16 + rh * 8 + g;
        CT* cp = C + r * (long)N + col0;
        const float* rp = res + r * (long)N + col0;
#pragma unroll
        for (int nt = 0; nt < 4; nt++) {
            int c = n0 + nt * 8 + 2 * t;
            float vx = acc[mt][nt][rh * 2 + 0] + bias[col0 + c];
            float vy = acc[mt][nt][rh * 2 + 1] + bias[col0 + c + 1];
            if (EPI == 4) { vx *= sc; vy *= sc; }
            if (EPI == 2) { vx += rp[c]; vy += rp[c + 1]; }
            if (EPI == 3) {
                vx = vx * fast_rcp1(1.f + fast_exp2(-2.45547238f * vx));
                vy = vy * fast_rcp1(1.f + fast_exp2(-2.45547238f * vy));
            }
            if (sizeof(CT) == 2) {
                *(uint32_t*)(cp + c) = h2u(vx, vy);
            } else {
                float2 v; v.x = vx; v.y = vy;
                *(float2*)((float*)cp + c) = v;
            }
        }
    }
}

// ---------------- tensor-core window attention --------------------------------
#define KSH 72
#define ATT_SMEM (2 * WTOK * KSH * 2)

__device__ __forceinline__ long attn_row(int widx, int t) {
    int b = widx & 7;
    int ij = widx >> 3;
    int wi = ij >> 2, wj = ij & 3;
    int hh = t >> 4, ww = t & 15;
    return (long)b * 4096 + (wi * 16 + hh) * 64 + (wj * 16 + ww);
}

__global__ void __launch_bounds__(256, 2)
attn_kernel(const __half* __restrict__ qkv, __half* __restrict__ ao) {
    extern __shared__ __half smh[];
    __half* ks = smh;
    __half* vs = smh + WTOK * KSH;
    int widx = blockIdx.x, head = blockIdx.y, tid = threadIdx.x;
    int lane = tid & 31, warp = tid >> 5;
    int g = lane >> 2, t = lane & 3;

    // async-stage K and V rows
    {
        int key = tid;
        long tok = attn_row(widx, key);
        const char* kp = (const char*)(qkv + tok * QKVN + 768 + head * HD);
        uint32_t kd = s2u(ks + key * KSH);
        uint32_t vd = s2u(vs + key * KSH);
#pragma unroll
        for (int o = 0; o < 8; o++) cp16(kd + o * 16, kp + o * 16);
#pragma unroll
        for (int o = 0; o < 8; o++) cp16(vd + o * 16, kp + 1536 + o * 16);
        asm volatile("cp.async.commit_group;" ::: "memory");
    }

    // Q fragments straight from gmem (overlaps with cp.async staging)
    uint32_t qa[2][4][4];
    long tok0[2], tok1[2];
#pragma unroll
    for (int mt2 = 0; mt2 < 2; mt2++) {
        int r0 = warp * 32 + mt2 * 16 + g;
        tok0[mt2] = attn_row(widx, r0);
        tok1[mt2] = attn_row(widx, r0 + 8);
        const __half* q0 = qkv + tok0[mt2] * QKVN + head * HD;
        const __half* q1 = qkv + tok1[mt2] * QKVN + head * HD;
#pragma unroll
        for (int kk = 0; kk < 4; kk++) {
            qa[mt2][kk][0] = *(const uint32_t*)(q0 + kk * 16 + 2 * t);
            qa[mt2][kk][1] = *(const uint32_t*)(q1 + kk * 16 + 2 * t);
            qa[mt2][kk][2] = *(const uint32_t*)(q0 + kk * 16 + 2 * t + 8);
            qa[mt2][kk][3] = *(const uint32_t*)(q1 + kk * 16 + 2 * t + 8);
        }
    }

    asm volatile("cp.async.wait_group 0;" ::: "memory");
    __syncthreads();

    uint32_t ksb = s2u(ks) + ((lane & 7) * KSH + (lane >> 3) * 8) * 2;
    uint32_t vsb = s2u(vs) + ((lane & 15) * KSH + ((lane >> 4) << 3)) * 2;

    float oacc[2][8][4];
#pragma unroll
    for (int i = 0; i < 2; i++)
#pragma unroll
        for (int j = 0; j < 8; j++)
#pragma unroll
            for (int r = 0; r < 4; r++) oacc[i][j][r] = 0.f;
    float lsum[2][2] = {{0.f, 0.f}, {0.f, 0.f}};
    uint32_t pfrag[2][2][2];

    uint32_t kb[2][2][4];
    ldsm4(kb[0][0], ksb);
    ldsm4(kb[0][1], ksb + 64);

    // QK^T + exp for one 16-key half-step; buffer indices are compile-time
#define QK_STEP(CUR)                                                          \
    do {                                                                      \
        _Pragma("unroll")                                                     \
        for (int mt2 = 0; mt2 < 2; mt2++) {                                   \
            float s0[4] = {0.f, 0.f, 0.f, 0.f};                               \
            float s1[4] = {0.f, 0.f, 0.f, 0.f};                               \
            mma16(s0, qa[mt2][0], &kb[CUR][0][0]);                            \
            mma16(s1, qa[mt2][1], &kb[CUR][0][2]);                            \
            mma16(s0, qa[mt2][2], &kb[CUR][1][0]);                            \
            mma16(s1, qa[mt2][3], &kb[CUR][1][2]);                            \
            float e0 = fast_exp2(LOG2E * (s0[0] + s1[0]));                    \
            float e1 = fast_exp2(LOG2E * (s0[1] + s1[1]));                    \
            float e2 = fast_exp2(LOG2E * (s0[2] + s1[2]));                    \
            float e3 = fast_exp2(LOG2E * (s0[3] + s1[3]));                    \
            lsum[mt2][0] += e0 + e1;                                          \
            lsum[mt2][1] += e2 + e3;                                          \
            pfrag[mt2][CUR][0] = h2u(e0, e1);                                 \
            pfrag[mt2][CUR][1] = h2u(e2, e3);                                 \
        }                                                                     \
    } while (0)

    for (int jj = 0; jj < 16; jj++) {
        int j = jj * 2;
        // even half-step: prefetch j+1 into buf 1, compute buf 0
        {
            uint32_t nb = ksb + (j + 1) * 8 * KSH * 2;
            ldsm4(kb[1][0], nb);
            ldsm4(kb[1][1], nb + 64);
        }
        QK_STEP(0);
        // odd half-step: prefetch j+2 into buf 0 (unless last), compute buf 1
        if (jj < 15) {
            uint32_t nb = ksb + (j + 2) * 8 * KSH * 2;
            ldsm4(kb[0][0], nb);
            ldsm4(kb[0][1], nb + 64);
        }
        QK_STEP(1);
        // PV step for these 16 keys
        uint32_t vrow = vsb + jj * 16 * KSH * 2;
        uint32_t vb[4][4];
#pragma unroll
        for (int dp = 0; dp < 4; dp++)
            ldsm4t(vb[dp], vrow + dp * 32);
#pragma unroll
        for (int mt2 = 0; mt2 < 2; mt2++) {
            uint32_t pa[4] = {pfrag[mt2][0][0], pfrag[mt2][0][1],
                              pfrag[mt2][1][0], pfrag[mt2][1][1]};
#pragma unroll
            for (int dt = 0; dt < 8; dt++)
                mma16(oacc[mt2][dt], pa, &vb[dt >> 1][(dt & 1) * 2]);
        }
    }
#undef QK_STEP

#pragma unroll
    for (int mt2 = 0; mt2 < 2; mt2++)
#pragma unroll
        for (int rr = 0; rr < 2; rr++) {
            float l = lsum[mt2][rr];
            l += __shfl_xor_sync(0xffffffffu, l, 1);
            l += __shfl_xor_sync(0xffffffffu, l, 2);
            lsum[mt2][rr] = l;
        }

#pragma unroll
    for (int mt2 = 0; mt2 < 2; mt2++) {
        float i0 = fast_rcp(lsum[mt2][0]);
        float i1 = fast_rcp(lsum[mt2][1]);
        __half* o0 = ao + tok0[mt2] * DIM + head * HD;
        __half* o1 = ao + tok1[mt2] * DIM + head * HD;
#pragma unroll
        for (int dt = 0; dt < 8; dt++) {
            int c = dt * 8 + 2 * t;
            *(uint32_t*)(o0 + c) = h2u(oacc[mt2][dt][0] * i0, oacc[mt2][dt][1] * i0);
            *(uint32_t*)(o1 + c) = h2u(oacc[mt2][dt][2] * i1, oacc[mt2][dt][3] * i1);
        }
    }
}

// ---------------- host --------------------------------------------------------
extern "C" void kernel_launch(void* const* d_in, const int* in_sizes, int n_in,
                              void* d_out, int out_size) {
    const float* x    = (const float*)d_in[0];
    const float* ln1s = (const float*)d_in[1];
    const float* ln1b = (const float*)d_in[2];
    const float* Wq   = (const float*)d_in[3];
    const float* bq   = (const float*)d_in[4];
    const float* Wk   = (const float*)d_in[5];
    const float* bk   = (const float*)d_in[6];
    const float* Wv   = (const float*)d_in[7];
    const float* bv   = (const float*)d_in[8];
    const float* Wo   = (const float*)d_in[9];
    const float* bo   = (const float*)d_in[10];
    const float* ln2s = (const float*)d_in[11];
    const float* ln2b = (const float*)d_in[12];
    const float* W1   = (const float*)d_in[13];
    const float* b1   = (const float*)d_in[14];
    const float* W2   = (const float*)d_in[15];
    const float* b2   = (const float*)d_in[16];
    float* out = (float*)d_out;

    __half *xn, *qkvb, *aob, *hb, *qkvT, *woT, *w1T, *w2T;
    float* qb3;
    cudaGetSymbolAddress((void**)&xn,   g_xn);
    cudaGetSymbolAddress((void**)&qkvb, g_qkv);
    cudaGetSymbolAddress((void**)&aob,  g_ao);
    cudaGetSymbolAddress((void**)&hb,   g_h);
    cudaGetSymbolAddress((void**)&qkvT, g_qkvT);
    cudaGetSymbolAddress((void**)&woT,  g_woT);
    cudaGetSymbolAddress((void**)&w1T,  g_w1T);
    cudaGetSymbolAddress((void**)&w2T,  g_w2T);
    cudaGetSymbolAddress((void**)&qb3,  g_qkvBias);

    cudaFuncSetAttribute(attn_kernel, cudaFuncAttributeMaxDynamicSharedMemorySize, ATT_SMEM);
    cudaFuncSetAttribute((const void*)tc_gemm<2, float>,  cudaFuncAttributeMaxDynamicSharedMemorySize, GEMM_SMEM);
    cudaFuncSetAttribute((const void*)tc_gemm<3, __half>, cudaFuncAttributeMaxDynamicSharedMemorySize, GEMM_SMEM);
    cudaFuncSetAttribute((const void*)tc_gemm<4, __half>, cudaFuncAttributeMaxDynamicSharedMemorySize, GEMM_SMEM);

    pack_bias<<<(LAYERS * QKVN + 255) / 256, 256>>>(bq, bk, bv, qb3);
    transpose_a<<<dim3(24, 24, 8), dim3(32, 8)>>>(Wq, Wk, Wv, Wo, qkvT, woT);
    transpose_b<<<dim3(96, 96, 4), dim3(32, 8)>>>(W1, W2, w1T, w2T);

    dim3 lnGrid(NTOK / 8), lnBlk(32, 8);
    dim3 gQKV(QKVN / TBN, NTOK / TBM);
    dim3 gD(DIM / TBN,    NTOK / TBM);
    dim3 gH(HDIM / TBN,   NTOK / TBM);

    for (int l = 0; l < LAYERS; l++) {
        long oDD = (long)l * DIM * DIM;
        long oDH = (long)l * DIM * HDIM;
        const float* resid = (l == 0) ? x : out;

        ln_kernel<<<lnGrid, lnBlk>>>(resid, xn, ln1s + l*DIM, ln1b + l*DIM);

        tc_gemm<4, __half><<<gQKV, 256, GEMM_SMEM>>>(xn, qkvT + 3*oDD, qb3 + l*QKVN,
                                                     resid, qkvb, DIM, QKVN, 0.125f);

        attn_kernel<<<dim3(NWIN, NHEAD), 256, ATT_SMEM>>>(qkvb, aob);

        tc_gemm<2, float><<<gD, 256, GEMM_SMEM>>>(aob, woT + oDD, bo + l*DIM,
                                                  resid, out, DIM, DIM, 1.f);

        ln_kernel<<<lnGrid, lnBlk>>>(out, xn, ln2s + l*DIM, ln2b + l*DIM);

        tc_gemm<3, __half><<<gH, 256, GEMM_SMEM>>>(xn, w1T + oDH, b1 + l*HDIM,
                                                   out, hb, DIM, HDIM, 1.f);
        tc_gemm<2, float><<<gD, 256, GEMM_SMEM>>>(hb, w2T + oDH, b2 + l*DIM,
                                                  out, out, HDIM, DIM, 1.f);
    }
}

// round 17
// speedup vs baseline: 7.6092x; 1.0040x over previous
#include <cuda_runtime.h>
#include <cuda_fp16.h>
#include <math.h>
#include <stdint.h>

#define NTOK 32768
#define DIM 768
#define QKVN 2304
#define HDIM 3072
#define NHEAD 12
#define HD 64
#define NWIN 128
#define WTOK 256
#define LAYERS 2
#define EPS 1e-6f
#define LOG2E 1.4426950409f

__device__ __half g_xn  [NTOK * DIM];
__device__ __half g_qkv [(size_t)NTOK * QKVN];
__device__ __half g_ao  [NTOK * DIM];
__device__ __half g_h   [(size_t)NTOK * HDIM];
__device__ __half g_qkvT[LAYERS * 3 * DIM * DIM];
__device__ __half g_woT [LAYERS * DIM * DIM];
__device__ __half g_w1T [LAYERS * DIM * HDIM];
__device__ __half g_w2T [LAYERS * DIM * HDIM];
__device__ float  g_qkvBias[LAYERS * QKVN];

// ---------------- helpers ---------------------------------------------------
__device__ __forceinline__ uint32_t s2u(const void* p) {
    uint32_t a;
    asm("{ .reg .u64 t; cvta.to.shared.u64 t, %1; cvt.u32.u64 %0, t; }" : "=r"(a) : "l"(p));
    return a;
}
__device__ __forceinline__ float fast_exp2(float x) {
    float t = x + 12582912.0f;
    float r = t - 12582912.0f;
    float f = x - r;
    int   e = (int)r;
    float p = 1.0f + f * (0.69314927f + f * (0.24022357f + f * 0.05550327f));
    return __int_as_float((e + 127) << 23) * p;
}
__device__ __forceinline__ float fast_rcp(float d) {      // 2-Newton
    float r = __int_as_float(0x7EF127EA - __float_as_int(d));
    r = r * (2.0f - d * r);
    r = r * (2.0f - d * r);
    return r;
}
__device__ __forceinline__ float fast_rcp1(float d) {     // 1-Newton
    float r = __int_as_float(0x7EF127EA - __float_as_int(d));
    r = r * (2.0f - d * r);
    return r;
}
__device__ __forceinline__ void cp16(uint32_t s, const void* g) {
    asm volatile("cp.async.cg.shared.global [%0], [%1], 16;" :: "r"(s), "l"(g));
}
__device__ __forceinline__ void mma16(float* c, const uint32_t* a, const uint32_t* b) {
    asm volatile(
        "mma.sync.aligned.m16n8k16.row.col.f32.f16.f16.f32 "
        "{%0,%1,%2,%3}, {%4,%5,%6,%7}, {%8,%9}, {%0,%1,%2,%3};"
        : "+f"(c[0]), "+f"(c[1]), "+f"(c[2]), "+f"(c[3])
        : "r"(a[0]), "r"(a[1]), "r"(a[2]), "r"(a[3]), "r"(b[0]), "r"(b[1]));
}
__device__ __forceinline__ void ldsm4(uint32_t* r, uint32_t addr) {
    asm volatile("ldmatrix.sync.aligned.m8n8.x4.shared.b16 {%0,%1,%2,%3}, [%4];"
                 : "=r"(r[0]), "=r"(r[1]), "=r"(r[2]), "=r"(r[3]) : "r"(addr));
}
__device__ __forceinline__ void ldsm4t(uint32_t* r, uint32_t addr) {
    asm volatile("ldmatrix.sync.aligned.m8n8.x4.trans.shared.b16 {%0,%1,%2,%3}, [%4];"
                 : "=r"(r[0]), "=r"(r[1]), "=r"(r[2]), "=r"(r[3]) : "r"(addr));
}
__device__ __forceinline__ uint32_t h2u(float x, float y) {
    __half2 h = __floats2half2_rn(x, y);
    return *(uint32_t*)&h;
}

// ---------------- bias packing: [bq|bk|bv] per layer --------------------------
__global__ void pack_bias(const float* __restrict__ bq, const float* __restrict__ bk,
                          const float* __restrict__ bv, float* __restrict__ qb3) {
    int i = threadIdx.x + blockIdx.x * 256;
    if (i >= LAYERS * QKVN) return;
    int l = i / QKVN, c = i % QKVN;
    float v;
    if (c < 768)       v = bq[l * DIM + c];
    else if (c < 1536) v = bk[l * DIM + c - 768];
    else               v = bv[l * DIM + c - 1536];
    qb3[i] = v;
}

// ---------------- weight transposes [K,N] -> [N,K] half ----------------------
__global__ void transpose_a(const float* __restrict__ Wq, const float* __restrict__ Wk,
                            const float* __restrict__ Wv, const float* __restrict__ Wo,
                            __half* __restrict__ qkvT, __half* __restrict__ woT) {
    __shared__ float tb[32][33];
    int w = blockIdx.z >> 1, l = blockIdx.z & 1;
    const float* src = (w == 0 ? Wq : w == 1 ? Wk : w == 2 ? Wv : Wo) + (long)l * DIM * DIM;
    __half* dst = (w < 3) ? qkvT + (long)l * 3 * DIM * DIM + (long)w * DIM * DIM
                          : woT + (long)l * DIM * DIM;
    int nb = blockIdx.x * 32, kb = blockIdx.y * 32;
    int x = threadIdx.x, y = threadIdx.y;
#pragma unroll
    for (int r = 0; r < 32; r += 8)
        tb[y + r][x] = src[(long)(kb + y + r) * DIM + nb + x];
    __syncthreads();
#pragma unroll
    for (int r = 0; r < 32; r += 8)
        dst[(long)(nb + y + r) * DIM + kb + x] = __float2half_rn(tb[x][y + r]);
}
__global__ void transpose_b(const float* __restrict__ W1, const float* __restrict__ W2,
                            __half* __restrict__ d1, __half* __restrict__ d2) {
    __shared__ float tb[32][33];
    int w = blockIdx.z >> 1, l = blockIdx.z & 1;
    const float* src; __half* dst; int K, N;
    if (w == 0) { src = W1 + (long)l * DIM * HDIM; dst = d1 + (long)l * DIM * HDIM; K = DIM;  N = HDIM; }
    else        { src = W2 + (long)l * DIM * HDIM; dst = d2 + (long)l * DIM * HDIM; K = HDIM; N = DIM; }
    if (blockIdx.x * 32 >= (unsigned)N || blockIdx.y * 32 >= (unsigned)K) return;
    int nb = blockIdx.x * 32, kb = blockIdx.y * 32;
    int x = threadIdx.x, y = threadIdx.y;
#pragma unroll
    for (int r = 0; r < 32; r += 8)
        tb[y + r][x] = src[(long)(kb + y + r) * N + nb + x];
    __syncthreads();
#pragma unroll
    for (int r = 0; r < 32; r += 8)
        dst[(long)(nb + y + r) * K + kb + x] = __float2half_rn(tb[x][y + r]);
}

// ---------------- LayerNorm: fp32 in, half out --------------------------------
__global__ void ln_kernel(const float* __restrict__ x, __half* __restrict__ y,
                          const float* __restrict__ gamma, const float* __restrict__ beta) {
    int lane = threadIdx.x;
    long row = (long)blockIdx.x * 8 + threadIdx.y;
    const float4* xr = (const float4*)(x + row * DIM);
    float4 vals[6];
    float s = 0.f, s2 = 0.f;
#pragma unroll
    for (int i = 0; i < 6; i++) {
        float4 f = xr[i * 32 + lane];
        vals[i] = f;
        s  += f.x + f.y + f.z + f.w;
        s2 += f.x*f.x + f.y*f.y + f.z*f.z + f.w*f.w;
    }
#pragma unroll
    for (int off = 16; off; off >>= 1) {
        s  += __shfl_xor_sync(0xffffffffu, s,  off);
        s2 += __shfl_xor_sync(0xffffffffu, s2, off);
    }
    float mean = s * (1.f / DIM);
    float var  = s2 * (1.f / DIM) - mean * mean;
    float inv  = rsqrtf(var + EPS);
    uint2* yr = (uint2*)(y + row * DIM);
    const float4* gg = (const float4*)gamma;
    const float4* bb = (const float4*)beta;
#pragma unroll
    for (int i = 0; i < 6; i++) {
        int c = i * 32 + lane;
        float4 g = gg[c], b = bb[c], v = vals[i];
        uint2 u;
        u.x = h2u((v.x - mean) * inv * g.x + b.x, (v.y - mean) * inv * g.y + b.y);
        u.y = h2u((v.z - mean) * inv * g.z + b.z, (v.w - mean) * inv * g.w + b.w);
        yr[c] = u;
    }
}

// ---------------- fp16 mma GEMM: rolling fragment prefetch --------------------
#define TBM 128
#define TBN 128
#define TBK 64
#define SH 72
#define TSTG (128 * SH)
#define STGH (2 * TSTG)
#define NSTG 3
#define GEMM_SMEM (NSTG * STGH * 2)

template <int EPI, typename CT>
__global__ void __launch_bounds__(256, 2)
tc_gemm(const __half* __restrict__ A, const __half* __restrict__ Wt,
        const float* __restrict__ bias, const float* __restrict__ res,
        CT* __restrict__ C, int K, int N, float alpha) {
    extern __shared__ __half smh[];
    int tid = threadIdx.x;
    int lane = tid & 31, wid = tid >> 5;
    int g = lane >> 2, t = lane & 3;
    int m0 = (wid & 1) * 64, n0 = (wid >> 1) * 32;
    long row0 = (long)blockIdx.y * TBM;
    int  col0 = blockIdx.x * TBN;

    float acc[4][4][4];
#pragma unroll
    for (int i = 0; i < 4; i++)
#pragma unroll
        for (int j = 0; j < 4; j++)
#pragma unroll
            for (int r = 0; r < 4; r++) acc[i][j][r] = 0.f;

    uint32_t sbase = s2u(smh);
    int iters = K / TBK;

    int aoff = (m0 + (lane & 15)) * SH + ((lane >> 4) << 3);
    int boff = (n0 + (lane & 7) + ((lane >> 4) << 3)) * SH + (((lane >> 3) & 1) << 3);

    auto produce = [&](int stage, int k0) {
        uint32_t ab = sbase + stage * STGH * 2;
        uint32_t bb = ab + TSTG * 2;
#pragma unroll
        for (int j = 0; j < 4; j++) {
            int id = tid + j * 256;
            int r = id >> 3, o = id & 7;
            cp16(ab + r * 144 + o * 16, A  + (row0 + r) * (long)K + k0 + o * 8);
            cp16(bb + r * 144 + o * 16, Wt + (col0 + r) * (long)K + k0 + o * 8);
        }
        asm volatile("cp.async.commit_group;" ::: "memory");
    };

    produce(0, 0);
    produce(1, TBK);
    int cs = 0, ps = 2;
    for (int i = 0; i < iters; i++) {
        if (i < iters - 1) {
            asm volatile("cp.async.wait_group 1;" ::: "memory");
        } else {
            asm volatile("cp.async.wait_group 0;" ::: "memory");
        }
        __syncthreads();
        uint32_t ab = sbase + cs * STGH * 2;
        uint32_t bb = ab + TSTG * 2;
        if (++cs == NSTG) cs = 0;

        // prefetch kk=0 fragments BEFORE the produce burst (hide LDSM latency)
        uint32_t a[4][4], b[2][4];
#pragma unroll
        for (int mt = 0; mt < 4; mt++)
            ldsm4(a[mt], ab + (aoff + mt * 16 * SH) * 2);
#pragma unroll
        for (int np = 0; np < 2; np++)
            ldsm4(b[np], bb + (boff + np * 16 * SH) * 2);

        if (i + 2 < iters) {
            produce(ps, (i + 2) * TBK);
            if (++ps == NSTG) ps = 0;
        }

#pragma unroll
        for (int kk = 0; kk < 4; kk++) {
#pragma unroll
            for (int mt = 0; mt < 4; mt++)
#pragma unroll
                for (int nt = 0; nt < 4; nt++)
                    mma16(acc[mt][nt], a[mt], &b[nt >> 1][(nt & 1) * 2]);
            if (kk < 3) {
                int k2 = (kk + 1) * 16;
#pragma unroll
                for (int mt = 0; mt < 4; mt++)
                    ldsm4(a[mt], ab + (aoff + mt * 16 * SH + k2) * 2);
#pragma unroll
                for (int np = 0; np < 2; np++)
                    ldsm4(b[np], bb + (boff + np * 16 * SH + k2) * 2);
            }
        }
    }

    float sc = (EPI == 4) ? ((col0 < 768) ? alpha : 1.f) : alpha;
#pragma unroll
    for (int mt = 0; mt < 4; mt++)
#pragma unroll
    for (int rh = 0; rh < 2; rh++) {
        long r = row0 + m0 + mt * 16 + rh * 8 + g;
        CT* cp = C + r * (long)N + col0;
        const float* rp = res + r * (long)N + col0;
#pragma unroll
        for (int nt = 0; nt < 4; nt++) {
            int c = n0 + nt * 8 + 2 * t;
            float vx = acc[mt][nt][rh * 2 + 0] + bias[col0 + c];
            float vy = acc[mt][nt][rh * 2 + 1] + bias[col0 + c + 1];
            if (EPI == 4) { vx *= sc; vy *= sc; }
            if (EPI == 2) { vx += rp[c]; vy += rp[c + 1]; }
            if (EPI == 3) {
                vx = vx * fast_rcp1(1.f + fast_exp2(-2.45547238f * vx));
                vy = vy * fast_rcp1(1.f + fast_exp2(-2.45547238f * vy));
            }
            if (sizeof(CT) == 2) {
                *(uint32_t*)(cp + c) = h2u(vx, vy);
            } else {
                float2 v; v.x = vx; v.y = vy;
                *(float2*)((float*)cp + c) = v;
            }
        }
    }
}

// ---------------- tensor-core window attention --------------------------------
#define KSH 72
#define ATT_SMEM (2 * WTOK * KSH * 2)

__device__ __forceinline__ long attn_row(int widx, int t) {
    int b = widx & 7;
    int ij = widx >> 3;
    int wi = ij >> 2, wj = ij & 3;
    int hh = t >> 4, ww = t & 15;
    return (long)b * 4096 + (wi * 16 + hh) * 64 + (wj * 16 + ww);
}

__global__ void __launch_bounds__(256, 2)
attn_kernel(const __half* __restrict__ qkv, __half* __restrict__ ao) {
    extern __shared__ __half smh[];
    __half* ks = smh;
    __half* vs = smh + WTOK * KSH;
    int widx = blockIdx.x, head = blockIdx.y, tid = threadIdx.x;
    int lane = tid & 31, warp = tid >> 5;
    int g = lane >> 2, t = lane & 3;

    // async-stage K and V rows
    {
        int key = tid;
        long tok = attn_row(widx, key);
        const char* kp = (const char*)(qkv + tok * QKVN + 768 + head * HD);
        uint32_t kd = s2u(ks + key * KSH);
        uint32_t vd = s2u(vs + key * KSH);
#pragma unroll
        for (int o = 0; o < 8; o++) cp16(kd + o * 16, kp + o * 16);
#pragma unroll
        for (int o = 0; o < 8; o++) cp16(vd + o * 16, kp + 1536 + o * 16);
        asm volatile("cp.async.commit_group;" ::: "memory");
    }

    // Q fragments straight from gmem (overlaps with cp.async staging)
    uint32_t qa[2][4][4];
    long tok0[2], tok1[2];
#pragma unroll
    for (int mt2 = 0; mt2 < 2; mt2++) {
        int r0 = warp * 32 + mt2 * 16 + g;
        tok0[mt2] = attn_row(widx, r0);
        tok1[mt2] = attn_row(widx, r0 + 8);
        const __half* q0 = qkv + tok0[mt2] * QKVN + head * HD;
        const __half* q1 = qkv + tok1[mt2] * QKVN + head * HD;
#pragma unroll
        for (int kk = 0; kk < 4; kk++) {
            qa[mt2][kk][0] = *(const uint32_t*)(q0 + kk * 16 + 2 * t);
            qa[mt2][kk][1] = *(const uint32_t*)(q1 + kk * 16 + 2 * t);
            qa[mt2][kk][2] = *(const uint32_t*)(q0 + kk * 16 + 2 * t + 8);
            qa[mt2][kk][3] = *(const uint32_t*)(q1 + kk * 16 + 2 * t + 8);
        }
    }

    asm volatile("cp.async.wait_group 0;" ::: "memory");
    __syncthreads();

    uint32_t ksb = s2u(ks) + ((lane & 7) * KSH + (lane >> 3) * 8) * 2;
    uint32_t vsb = s2u(vs) + ((lane & 15) * KSH + ((lane >> 4) << 3)) * 2;

    float oacc[2][8][4];
#pragma unroll
    for (int i = 0; i < 2; i++)
#pragma unroll
        for (int j = 0; j < 8; j++)
#pragma unroll
            for (int r = 0; r < 4; r++) oacc[i][j][r] = 0.f;
    float lsum[2][2] = {{0.f, 0.f}, {0.f, 0.f}};
    uint32_t pfrag[2][2][2];

    uint32_t kb[2][2][4];
    ldsm4(kb[0][0], ksb);
    ldsm4(kb[0][1], ksb + 64);

#define QK_STEP(CUR)                                                          \
    do {                                                                      \
        _Pragma("unroll")                                                     \
        for (int mt2 = 0; mt2 < 2; mt2++) {                                   \
            float s0[4] = {0.f, 0.f, 0.f, 0.f};                               \
            float s1[4] = {0.f, 0.f, 0.f, 0.f};                               \
            mma16(s0, qa[mt2][0], &kb[CUR][0][0]);                            \
            mma16(s1, qa[mt2][1], &kb[CUR][0][2]);                            \
            mma16(s0, qa[mt2][2], &kb[CUR][1][0]);                            \
            mma16(s1, qa[mt2][3], &kb[CUR][1][2]);                            \
            float e0 = fast_exp2(LOG2E * (s0[0] + s1[0]));                    \
            float e1 = fast_exp2(LOG2E * (s0[1] + s1[1]));                    \
            float e2 = fast_exp2(LOG2E * (s0[2] + s1[2]));                    \
            float e3 = fast_exp2(LOG2E * (s0[3] + s1[3]));                    \
            lsum[mt2][0] += e0 + e1;                                          \
            lsum[mt2][1] += e2 + e3;                                          \
            pfrag[mt2][CUR][0] = h2u(e0, e1);                                 \
            pfrag[mt2][CUR][1] = h2u(e2, e3);                                 \
        }                                                                     \
    } while (0)

    for (int jj = 0; jj < 16; jj++) {
        int j = jj * 2;
        // V fragments for this jj: independent of QK, issue EARLY so the
        // ldsm4t latency hides under the QK mma/exp work.
        uint32_t vb[4][4];
        {
            uint32_t vrow = vsb + jj * 16 * KSH * 2;
#pragma unroll
            for (int dp = 0; dp < 4; dp++)
                ldsm4t(vb[dp], vrow + dp * 32);
        }
        // even half-step: prefetch j+1 into buf 1, compute buf 0
        {
            uint32_t nb = ksb + (j + 1) * 8 * KSH * 2;
            ldsm4(kb[1][0], nb);
            ldsm4(kb[1][1], nb + 64);
        }
        QK_STEP(0);
        // odd half-step: prefetch j+2 into buf 0 (unless last), compute buf 1
        if (jj < 15) {
            uint32_t nb = ksb + (j + 2) * 8 * KSH * 2;
            ldsm4(kb[0][0], nb);
            ldsm4(kb[0][1], nb + 64);
        }
        QK_STEP(1);
        // PV step for these 16 keys (vb already resident)
#pragma unroll
        for (int mt2 = 0; mt2 < 2; mt2++) {
            uint32_t pa[4] = {pfrag[mt2][0][0], pfrag[mt2][0][1],
                              pfrag[mt2][1][0], pfrag[mt2][1][1]};
#pragma unroll
            for (int dt = 0; dt < 8; dt++)
                mma16(oacc[mt2][dt], pa, &vb[dt >> 1][(dt & 1) * 2]);
        }
    }
#undef QK_STEP

#pragma unroll
    for (int mt2 = 0; mt2 < 2; mt2++)
#pragma unroll
        for (int rr = 0; rr < 2; rr++) {
            float l = lsum[mt2][rr];
            l += __shfl_xor_sync(0xffffffffu, l, 1);
            l += __shfl_xor_sync(0xffffffffu, l, 2);
            lsum[mt2][rr] = l;
        }

#pragma unroll
    for (int mt2 = 0; mt2 < 2; mt2++) {
        float i0 = fast_rcp(lsum[mt2][0]);
        float i1 = fast_rcp(lsum[mt2][1]);
        __half* o0 = ao + tok0[mt2] * DIM + head * HD;
        __half* o1 = ao + tok1[mt2] * DIM + head * HD;
#pragma unroll
        for (int dt = 0; dt < 8; dt++) {
            int c = dt * 8 + 2 * t;
            *(uint32_t*)(o0 + c) = h2u(oacc[mt2][dt][0] * i0, oacc[mt2][dt][1] * i0);
            *(uint32_t*)(o1 + c) = h2u(oacc[mt2][dt][2] * i1, oacc[mt2][dt][3] * i1);
        }
    }
}

// ---------------- host --------------------------------------------------------
extern "C" void kernel_launch(void* const* d_in, const int* in_sizes, int n_in,
                              void* d_out, int out_size) {
    const float* x    = (const float*)d_in[0];
    const float* ln1s = (const float*)d_in[1];
    const float* ln1b = (const float*)d_in[2];
    const float* Wq   = (const float*)d_in[3];
    const float* bq   = (const float*)d_in[4];
    const float* Wk   = (const float*)d_in[5];
    const float* bk   = (const float*)d_in[6];
    const float* Wv   = (const float*)d_in[7];
    const float* bv   = (const float*)d_in[8];
    const float* Wo   = (const float*)d_in[9];
    const float* bo   = (const float*)d_in[10];
    const float* ln2s = (const float*)d_in[11];
    const float* ln2b = (const float*)d_in[12];
    const float* W1   = (const float*)d_in[13];
    const float* b1   = (const float*)d_in[14];
    const float* W2   = (const float*)d_in[15];
    const float* b2   = (const float*)d_in[16];
    float* out = (float*)d_out;

    __half *xn, *qkvb, *aob, *hb, *qkvT, *woT, *w1T, *w2T;
    float* qb3;
    cudaGetSymbolAddress((void**)&xn,   g_xn);
    cudaGetSymbolAddress((void**)&qkvb, g_qkv);
    cudaGetSymbolAddress((void**)&aob,  g_ao);
    cudaGetSymbolAddress((void**)&hb,   g_h);
    cudaGetSymbolAddress((void**)&qkvT, g_qkvT);
    cudaGetSymbolAddress((void**)&woT,  g_woT);
    cudaGetSymbolAddress((void**)&w1T,  g_w1T);
    cudaGetSymbolAddress((void**)&w2T,  g_w2T);
    cudaGetSymbolAddress((void**)&qb3,  g_qkvBias);

    cudaFuncSetAttribute(attn_kernel, cudaFuncAttributeMaxDynamicSharedMemorySize, ATT_SMEM);
    cudaFuncSetAttribute((const void*)tc_gemm<2, float>,  cudaFuncAttributeMaxDynamicSharedMemorySize, GEMM_SMEM);
    cudaFuncSetAttribute((const void*)tc_gemm<3, __half>, cudaFuncAttributeMaxDynamicSharedMemorySize, GEMM_SMEM);
    cudaFuncSetAttribute((const void*)tc_gemm<4, __half>, cudaFuncAttributeMaxDynamicSharedMemorySize, GEMM_SMEM);

    pack_bias<<<(LAYERS * QKVN + 255) / 256, 256>>>(bq, bk, bv, qb3);
    transpose_a<<<dim3(24, 24, 8), dim3(32, 8)>>>(Wq, Wk, Wv, Wo, qkvT, woT);
    transpose_b<<<dim3(96, 96, 4), dim3(32, 8)>>>(W1, W2, w1T, w2T);

    dim3 lnGrid(NTOK / 8), lnBlk(32, 8);
    dim3 gQKV(QKVN / TBN, NTOK / TBM);
    dim3 gD(DIM / TBN,    NTOK / TBM);
    dim3 gH(HDIM / TBN,   NTOK / TBM);

    for (int l = 0; l < LAYERS; l++) {
        long oDD = (long)l * DIM * DIM;
        long oDH = (long)l * DIM * HDIM;
        const float* resid = (l == 0) ? x : out;

        ln_kernel<<<lnGrid, lnBlk>>>(resid, xn, ln1s + l*DIM, ln1b + l*DIM);

        tc_gemm<4, __half><<<gQKV, 256, GEMM_SMEM>>>(xn, qkvT + 3*oDD, qb3 + l*QKVN,
                                                     resid, qkvb, DIM, QKVN, 0.125f);

        attn_kernel<<<dim3(NWIN, NHEAD), 256, ATT_SMEM>>>(qkvb, aob);

        tc_gemm<2, float><<<gD, 256, GEMM_SMEM>>>(aob, woT + oDD, bo + l*DIM,
                                                  resid, out, DIM, DIM, 1.f);

        ln_kernel<<<lnGrid, lnBlk>>>(out, xn, ln2s + l*DIM, ln2b + l*DIM);

        tc_gemm<3, __half><<<gH, 256, GEMM_SMEM>>>(xn, w1T + oDH, b1 + l*HDIM,
                                                   out, hb, DIM, HDIM, 1.f);
        tc_gemm<2, float><<<gD, 256, GEMM_SMEM>>>(hb, w2T + oDH, b2 + l*DIM,
                                                  out, out, HDIM, DIM, 1.f);
    }
}